// round 11
// baseline (speedup 1.0000x reference)
#include <cuda_runtime.h>
#include <cuda_bf16.h>
#include <cstdint>

// Problem constants (fixed by the dataset)
#define NN 100000
#define EE 3200000
#define NG 64
#define F_IN 128
#define H1 128
#define H2 64
#define DENSE 128
#define LABELS 2

#define SCAN_BLK 512
#define NB_SCAN ((NN + SCAN_BLK - 1) / SCAN_BLK)   // 196

// ---------------- scratch (__device__ globals; no runtime allocation) -------
__device__ float g_dis[NN];
__device__ int   g_deg[NN];
__device__ int   g_rowptr[NN];
__device__ int   g_nextptr[NN];
__device__ int   g_partials[256];
__device__ int   g_csr[EE];                       // src per CSR slot
__device__ __nv_bfloat16 g_hb[(size_t)NN * 128];  // gemm outputs, pre-scaled by dis
__device__ float g_h1[(size_t)NN * 128];          // relu(layer1)
__device__ float g_gsum[NG * 64];
__device__ float g_gcnt[NG];

// ---------------- CSR build --------------------------------------------------
__global__ void k_deg_count(const int* __restrict__ dst, int* __restrict__ deg) {
    int i = blockIdx.x * blockDim.x + threadIdx.x;
    int stride = gridDim.x * blockDim.x;
    const int4* d4 = (const int4*)dst;
    for (; i < EE / 4; i += stride) {
        int4 v = __ldg(&d4[i]);
        atomicAdd(&deg[v.x], 1);
        atomicAdd(&deg[v.y], 1);
        atomicAdd(&deg[v.z], 1);
        atomicAdd(&deg[v.w], 1);
    }
}

__global__ void k_scan_block(const int* __restrict__ deg, int* __restrict__ rowptr,
                             int* __restrict__ partials) {
    __shared__ int s[SCAN_BLK];
    int tid = threadIdx.x;
    int i = blockIdx.x * SCAN_BLK + tid;
    int v = (i < NN) ? deg[i] : 0;
    s[tid] = v;
    __syncthreads();
#pragma unroll
    for (int off = 1; off < SCAN_BLK; off <<= 1) {
        int t = (tid >= off) ? s[tid - off] : 0;
        __syncthreads();
        s[tid] += t;
        __syncthreads();
    }
    if (i < NN) rowptr[i] = s[tid] - v;           // block-local exclusive
    if (tid == SCAN_BLK - 1) partials[blockIdx.x] = s[tid];
}

// fused: scan partials (redundantly per block) + finalize rowptr/nextptr/dis
__global__ void k_scan_finish(int* __restrict__ rowptr, const int* __restrict__ partials,
                              int* __restrict__ nextptr, const int* __restrict__ deg,
                              float* __restrict__ dis) {
    __shared__ int s[256];
    int tid = threadIdx.x;
    int v = (tid < NB_SCAN) ? partials[tid] : 0;
    s[tid] = v;
    __syncthreads();
#pragma unroll
    for (int off = 1; off < 256; off <<= 1) {
        int t = (tid >= off) ? s[tid - off] : 0;
        __syncthreads();
        s[tid] += t;
        __syncthreads();
    }
    int ex = s[tid] - v;                           // exclusive
    __syncthreads();
    s[tid] = ex;
    __syncthreads();
    int i = blockIdx.x * 256 + tid;
    if (i < NN) {
        int r = rowptr[i] + s[i / SCAN_BLK];
        rowptr[i] = r;
        nextptr[i] = r;
        dis[i] = rsqrtf(1.0f + (float)deg[i]);
    }
}

__global__ void k_fill(const int* __restrict__ src, const int* __restrict__ dst,
                       int* __restrict__ nextptr, int* __restrict__ csr) {
    int i = blockIdx.x * blockDim.x + threadIdx.x;
    int stride = gridDim.x * blockDim.x;
    for (; i < EE; i += stride) {
        int d = dst[i];
        int s = src[i];
        int pos = atomicAdd(&nextptr[d], 1);
        csr[pos] = s;
    }
}

// ---------------- tf32 helpers ----------------------------------------------
__device__ __forceinline__ uint32_t f2tf32(float f) {
    uint32_t r;
    asm("cvt.rna.tf32.f32 %0, %1;" : "=r"(r) : "f"(f));
    return r;
}

__device__ __forceinline__ void tf32_store4(float* p, float4 v) {
    uint32_t hx = f2tf32(v.x), hy = f2tf32(v.y), hz = f2tf32(v.z), hw = f2tf32(v.w);
    *(float4*)p = make_float4(__uint_as_float(hx), __uint_as_float(hy),
                              __uint_as_float(hz), __uint_as_float(hw));
}

__device__ __forceinline__ void mma_tf32(float d[4], const uint32_t a[4],
                                         uint32_t b0, uint32_t b1) {
    asm volatile(
        "mma.sync.aligned.m16n8k8.row.col.f32.tf32.tf32.f32 "
        "{%0,%1,%2,%3},{%4,%5,%6,%7},{%8,%9},{%0,%1,%2,%3};"
        : "+f"(d[0]), "+f"(d[1]), "+f"(d[2]), "+f"(d[3])
        : "r"(a[0]), "r"(a[1]), "r"(a[2]), "r"(a[3]), "r"(b0), "r"(b1));
}

// ---------------- tf32 GEMM: Cb[M,BN] = bf16((A[M,128] @ B[128,BN]) * dis[m])
template<int BN>
__global__ void __launch_bounds__(256)
k_gemm_tc(const float* __restrict__ A, const float* __restrict__ B,
          const float* __restrict__ dis, __nv_bfloat16* __restrict__ Cb, int M) {
    constexpr int BM = 128, BK = 16, KTOT = 128;
    constexpr int AP = 20;
    constexpr int BP = BN + 8;
    constexpr int NT = (BN / 2) / 8;
    __shared__ float sA[BM * AP];
    __shared__ float sB[BK * BP];

    int tid = threadIdx.x;
    int row0 = blockIdx.x * BM;
    int lane = tid & 31, warp = tid >> 5;
    int wr = warp >> 1, wc = warp & 1;
    int g = lane >> 2, tig = lane & 3;

    float acc[2][NT][4];
#pragma unroll
    for (int m = 0; m < 2; m++)
#pragma unroll
        for (int n = 0; n < NT; n++)
#pragma unroll
            for (int i = 0; i < 4; i++) acc[m][n][i] = 0.f;

    for (int kk = 0; kk < KTOT; kk += BK) {
#pragma unroll
        for (int i = 0; i < 2; i++) {
            int j = tid + 256 * i;
            int r = j >> 2;
            int c4 = (j & 3) * 4;
            float4 v = make_float4(0.f, 0.f, 0.f, 0.f);
            if (row0 + r < M)
                v = *(const float4*)(A + (size_t)(row0 + r) * KTOT + kk + c4);
            tf32_store4(sA + r * AP + c4, v);
        }
#pragma unroll
        for (int i = 0; i < BN / 64; i++) {
            int j = tid + 256 * i;
            int r = j / (BN / 4);
            int c4 = (j % (BN / 4)) * 4;
            float4 v = *(const float4*)(B + (size_t)(kk + r) * BN + c4);
            tf32_store4(sB + r * BP + c4, v);
        }
        __syncthreads();

#pragma unroll
        for (int ks = 0; ks < 2; ks++) {
            int k0 = ks * 8;
            uint32_t a[2][4];
#pragma unroll
            for (int mt = 0; mt < 2; mt++) {
                int rb = wr * 32 + mt * 16;
                a[mt][0] = __float_as_uint(sA[(rb + g) * AP + k0 + tig]);
                a[mt][1] = __float_as_uint(sA[(rb + g + 8) * AP + k0 + tig]);
                a[mt][2] = __float_as_uint(sA[(rb + g) * AP + k0 + tig + 4]);
                a[mt][3] = __float_as_uint(sA[(rb + g + 8) * AP + k0 + tig + 4]);
            }
#pragma unroll
            for (int nt = 0; nt < NT; nt++) {
                int nc = wc * (BN / 2) + nt * 8 + g;
                uint32_t b0 = __float_as_uint(sB[(k0 + tig) * BP + nc]);
                uint32_t b1 = __float_as_uint(sB[(k0 + tig + 4) * BP + nc]);
#pragma unroll
                for (int mt = 0; mt < 2; mt++)
                    mma_tf32(acc[mt][nt], a[mt], b0, b1);
            }
        }
        __syncthreads();
    }

#pragma unroll
    for (int mt = 0; mt < 2; mt++) {
        int r1 = row0 + wr * 32 + mt * 16 + g;
        int r2 = r1 + 8;
        float d1 = (r1 < M) ? __ldg(&dis[r1]) : 0.f;
        float d2 = (r2 < M) ? __ldg(&dis[r2]) : 0.f;
#pragma unroll
        for (int nt = 0; nt < NT; nt++) {
            int cc = wc * (BN / 2) + nt * 8 + 2 * tig;
            if (r1 < M)
                *(__nv_bfloat162*)(Cb + (size_t)r1 * BN + cc) =
                    __float22bfloat162_rn(make_float2(acc[mt][nt][0] * d1,
                                                      acc[mt][nt][1] * d1));
            if (r2 < M)
                *(__nv_bfloat162*)(Cb + (size_t)r2 * BN + cc) =
                    __float22bfloat162_rn(make_float2(acc[mt][nt][2] * d2,
                                                      acc[mt][nt][3] * d2));
        }
    }
}

// ---------------- fused gather (layer1) --------------------------------------
__device__ __forceinline__ void accum8(float* a, uint4 v) {
    float2 f;
    f = __bfloat1622float2(*reinterpret_cast<__nv_bfloat162*>(&v.x));
    a[0] += f.x; a[1] += f.y;
    f = __bfloat1622float2(*reinterpret_cast<__nv_bfloat162*>(&v.y));
    a[2] += f.x; a[3] += f.y;
    f = __bfloat1622float2(*reinterpret_cast<__nv_bfloat162*>(&v.z));
    a[4] += f.x; a[5] += f.y;
    f = __bfloat1622float2(*reinterpret_cast<__nv_bfloat162*>(&v.w));
    a[6] += f.x; a[7] += f.y;
}

__device__ __forceinline__ void accum4(float* a, uint2 v) {
    float2 f;
    f = __bfloat1622float2(*reinterpret_cast<__nv_bfloat162*>(&v.x));
    a[0] += f.x; a[1] += f.y;
    f = __bfloat1622float2(*reinterpret_cast<__nv_bfloat162*>(&v.y));
    a[2] += f.x; a[3] += f.y;
}

// K=128: half-warp per edge row (16 lanes x uint4 = 256 B), 8 edges/iter.
__global__ void __launch_bounds__(256)
k_gather128s(const __nv_bfloat16* __restrict__ hb, const float* __restrict__ dis,
             const int* __restrict__ deg, const int* __restrict__ rowptr,
             const int* __restrict__ csr, const float* __restrict__ bias,
             float* __restrict__ out) {
    int warp = (blockIdx.x * blockDim.x + threadIdx.x) >> 5;
    int lane = threadIdx.x & 31;
    int h = lane >> 4;
    int l = lane & 15;
    int nwarps = (gridDim.x * blockDim.x) >> 5;
    for (int node = warp; node < NN; node += nwarps) {
        int beg = rowptr[node];
        int cnt = deg[node];
        float acc[8] = {0.f, 0.f, 0.f, 0.f, 0.f, 0.f, 0.f, 0.f};
        int off = beg + h;
        int e = 0;
        for (; e + 7 < cnt; e += 8) {
            int s0 = __ldg(csr + off + e);
            int s1 = __ldg(csr + off + e + 2);
            int s2 = __ldg(csr + off + e + 4);
            int s3 = __ldg(csr + off + e + 6);
            uint4 v0 = *(const uint4*)(hb + (size_t)s0 * 128 + l * 8);
            uint4 v1 = *(const uint4*)(hb + (size_t)s1 * 128 + l * 8);
            uint4 v2 = *(const uint4*)(hb + (size_t)s2 * 128 + l * 8);
            uint4 v3 = *(const uint4*)(hb + (size_t)s3 * 128 + l * 8);
            accum8(acc, v0); accum8(acc, v1); accum8(acc, v2); accum8(acc, v3);
        }
        for (; e < cnt; e += 2) {
            int idx = e + h;
            if (idx < cnt) {
                int s = __ldg(csr + beg + idx);
                uint4 v = *(const uint4*)(hb + (size_t)s * 128 + l * 8);
                accum8(acc, v);
            }
        }
        if (h == 0) {
            uint4 v = *(const uint4*)(hb + (size_t)node * 128 + l * 8);
            accum8(acc, v);
        }
#pragma unroll
        for (int i = 0; i < 8; i++)
            acc[i] += __shfl_xor_sync(0xffffffffu, acc[i], 16);
        if (h == 0) {
            float dn = dis[node];
            float4 b0 = *(const float4*)(bias + l * 8);
            float4 b1 = *(const float4*)(bias + l * 8 + 4);
            float4 r0, r1;
            r0.x = fmaxf(acc[0] * dn + b0.x, 0.f);
            r0.y = fmaxf(acc[1] * dn + b0.y, 0.f);
            r0.z = fmaxf(acc[2] * dn + b0.z, 0.f);
            r0.w = fmaxf(acc[3] * dn + b0.w, 0.f);
            r1.x = fmaxf(acc[4] * dn + b1.x, 0.f);
            r1.y = fmaxf(acc[5] * dn + b1.y, 0.f);
            r1.z = fmaxf(acc[6] * dn + b1.z, 0.f);
            r1.w = fmaxf(acc[7] * dn + b1.w, 0.f);
            *(float4*)(out + (size_t)node * 128 + l * 8) = r0;
            *(float4*)(out + (size_t)node * 128 + l * 8 + 4) = r1;
        }
    }
}

// ---------------- fused gather(layer2) + mean-pool accumulate ----------------
// Block = 64 contiguous nodes (8 warps x 8 nodes). Per-warp run-length
// accumulation into smem bins (batch sorted, so <=2 graphs/block typical);
// global-atomic fallback if a block spans >4 graphs.
__global__ void __launch_bounds__(256)
k_gather64pool(const __nv_bfloat16* __restrict__ hb, const float* __restrict__ dis,
               const int* __restrict__ deg, const int* __restrict__ rowptr,
               const int* __restrict__ csr, const float* __restrict__ bias,
               const int* __restrict__ batch, float* __restrict__ gsum) {
    __shared__ float sm[4][64];
    __shared__ int s_gmin, s_ngr;
    int tid = threadIdx.x;
    int wid = tid >> 5;
    int lane = tid & 31;
    int h = lane >> 4;
    int l = lane & 15;
    int base = blockIdx.x * 64;
    int nmax = NN - base; if (nmax > 64) nmax = 64;

    if (tid == 0) {
        int gmin = batch[base];
        int gmax = batch[base + nmax - 1];
        s_gmin = gmin; s_ngr = gmax - gmin + 1;
    }
    for (int i = tid; i < 4 * 64; i += 256) ((float*)sm)[i] = 0.f;
    __syncthreads();
    int gmin = s_gmin;
    bool use_sm = (s_ngr <= 4);

    float4 bv = *(const float4*)(bias + l * 4);   // cols l*4..l*4+3 (h==0 lanes)
    float racc[4] = {0.f, 0.f, 0.f, 0.f};
    int curg = -1;

    for (int i = 0; i < 8; i++) {
        int node = base + (wid << 3) + i;
        if (node >= NN || (wid << 3) + i >= nmax) break;
        int beg = rowptr[node];
        int cnt = deg[node];
        float acc[4] = {0.f, 0.f, 0.f, 0.f};
        int off = beg + h;
        int e = 0;
        for (; e + 7 < cnt; e += 8) {
            int s0 = __ldg(csr + off + e);
            int s1 = __ldg(csr + off + e + 2);
            int s2 = __ldg(csr + off + e + 4);
            int s3 = __ldg(csr + off + e + 6);
            uint2 v0 = *(const uint2*)(hb + (size_t)s0 * 64 + l * 4);
            uint2 v1 = *(const uint2*)(hb + (size_t)s1 * 64 + l * 4);
            uint2 v2 = *(const uint2*)(hb + (size_t)s2 * 64 + l * 4);
            uint2 v3 = *(const uint2*)(hb + (size_t)s3 * 64 + l * 4);
            accum4(acc, v0); accum4(acc, v1); accum4(acc, v2); accum4(acc, v3);
        }
        for (; e < cnt; e += 2) {
            int idx = e + h;
            if (idx < cnt) {
                int s = __ldg(csr + beg + idx);
                uint2 v = *(const uint2*)(hb + (size_t)s * 64 + l * 4);
                accum4(acc, v);
            }
        }
        if (h == 0) {
            uint2 v = *(const uint2*)(hb + (size_t)node * 64 + l * 4);
            accum4(acc, v);
        }
#pragma unroll
        for (int k = 0; k < 4; k++)
            acc[k] += __shfl_xor_sync(0xffffffffu, acc[k], 16);

        float dn = dis[node];
        float rv[4];
        rv[0] = fmaxf(acc[0] * dn + bv.x, 0.f);
        rv[1] = fmaxf(acc[1] * dn + bv.y, 0.f);
        rv[2] = fmaxf(acc[2] * dn + bv.z, 0.f);
        rv[3] = fmaxf(acc[3] * dn + bv.w, 0.f);
        int g = batch[node];
        if (use_sm) {
            if (g != curg) {
                if (curg >= 0 && h == 0) {
#pragma unroll
                    for (int k = 0; k < 4; k++)
                        atomicAdd(&sm[curg - gmin][l * 4 + k], racc[k]);
                }
                curg = g;
                racc[0] = rv[0]; racc[1] = rv[1]; racc[2] = rv[2]; racc[3] = rv[3];
            } else {
                racc[0] += rv[0]; racc[1] += rv[1];
                racc[2] += rv[2]; racc[3] += rv[3];
            }
        } else if (h == 0) {
#pragma unroll
            for (int k = 0; k < 4; k++)
                atomicAdd(&gsum[(size_t)g * 64 + l * 4 + k], rv[k]);
        }
    }
    if (use_sm && curg >= 0 && h == 0) {
#pragma unroll
        for (int k = 0; k < 4; k++)
            atomicAdd(&sm[curg - gmin][l * 4 + k], racc[k]);
    }
    __syncthreads();
    if (use_sm && tid < 64) {
        int ngr = s_ngr;
        for (int s = 0; s < ngr; s++) {
            float v = sm[s][tid];
            if (v != 0.f)
                atomicAdd(&gsum[(size_t)(gmin + s) * 64 + tid], v);
        }
    }
}

// ---------------- pooling setup ----------------------------------------------
__global__ void k_zero_pool(float* gsum, float* gcnt) {
    int i = blockIdx.x * blockDim.x + threadIdx.x;
    if (i < NG * 64) gsum[i] = 0.f;
    if (i < NG) gcnt[i] = 0.f;
}

__global__ void k_count(const int* __restrict__ batch, float* __restrict__ gcnt) {
    int i = blockIdx.x * blockDim.x + threadIdx.x;
    unsigned act = __ballot_sync(0xffffffffu, i < NN);
    if (i < NN) {
        int b = batch[i];
        unsigned m = __match_any_sync(act, b);
        int leader = __ffs(m) - 1;
        if ((threadIdx.x & 31) == leader)
            atomicAdd(&gcnt[b], (float)__popc(m));
    }
}

// ---------------- final: ge = (gsum/cnt)@Wf1+bf1 ; ic = ge@Wf2+bf2 ----------
__global__ void k_final2(const float* __restrict__ gsum, const float* __restrict__ gcnt,
                         const float* __restrict__ Wf1, const float* __restrict__ bf1,
                         const float* __restrict__ Wf2, const float* __restrict__ bf2,
                         float* __restrict__ out) {
    __shared__ float ge[NG * DENSE];
    int tid = threadIdx.x;                     // 256
    for (int idx = tid; idx < NG * DENSE; idx += 256) {
        int gg = idx >> 7, j = idx & 127;
        float inv = 1.0f / fmaxf(gcnt[gg], 1.0f);
        const float* pg = gsum + gg * 64;
        float a = 0.f;
#pragma unroll 8
        for (int c = 0; c < 64; c++)
            a += pg[c] * Wf1[c * DENSE + j];
        float v = a * inv + bf1[j];
        ge[idx] = v;
        out[idx] = v;
    }
    __syncthreads();
    if (tid < NG * LABELS) {
        int gg = tid >> 1, l = tid & 1;
        float s = bf2[l];
#pragma unroll 8
        for (int c = 0; c < DENSE; c++)
            s += ge[gg * DENSE + c] * Wf2[c * LABELS + l];
        out[NG * DENSE + 1 + tid] = s;
    }
    if (tid == 0) out[NG * DENSE] = 0.f;
}

// ---------------- launch ----------------------------------------------------
extern "C" void kernel_launch(void* const* d_in, const int* in_sizes, int n_in,
                              void* d_out, int out_size) {
    const float* x   = (const float*)d_in[0];
    const float* W1  = (const float*)d_in[1];
    const float* b1  = (const float*)d_in[2];
    const float* W2  = (const float*)d_in[3];
    const float* b2  = (const float*)d_in[4];
    const float* Wf1 = (const float*)d_in[5];
    const float* bf1 = (const float*)d_in[6];
    const float* Wf2 = (const float*)d_in[7];
    const float* bf2 = (const float*)d_in[8];
    const int* ei    = (const int*)d_in[9];
    const int* batch = (const int*)d_in[10];
    const int* src = ei;
    const int* dst = ei + EE;
    float* out = (float*)d_out;

    float *dis, *h1, *gsum, *gcnt;
    __nv_bfloat16* hb;
    int *deg, *rowptr, *nextptr, *partials, *csr;
    cudaGetSymbolAddress((void**)&dis,  g_dis);
    cudaGetSymbolAddress((void**)&deg,  g_deg);
    cudaGetSymbolAddress((void**)&rowptr, g_rowptr);
    cudaGetSymbolAddress((void**)&nextptr, g_nextptr);
    cudaGetSymbolAddress((void**)&partials, g_partials);
    cudaGetSymbolAddress((void**)&csr,  g_csr);
    cudaGetSymbolAddress((void**)&hb,   g_hb);
    cudaGetSymbolAddress((void**)&h1,   g_h1);
    cudaGetSymbolAddress((void**)&gsum, g_gsum);
    cudaGetSymbolAddress((void**)&gcnt, g_gcnt);

    // side streams + events (created once, on the uncaptured correctness call)
    static cudaStream_t s1 = nullptr, s2 = nullptr;
    static cudaEvent_t e_root = nullptr, e_scan = nullptr,
                       e_fill = nullptr, e_pool = nullptr;
    if (!s1) {
        cudaStreamCreateWithFlags(&s1, cudaStreamNonBlocking);
        cudaStreamCreateWithFlags(&s2, cudaStreamNonBlocking);
        cudaEventCreateWithFlags(&e_root, cudaEventDisableTiming);
        cudaEventCreateWithFlags(&e_scan, cudaEventDisableTiming);
        cudaEventCreateWithFlags(&e_fill, cudaEventDisableTiming);
        cudaEventCreateWithFlags(&e_pool, cudaEventDisableTiming);
    }

    const int TB = 256;
    const int nblkN = (NN + TB - 1) / TB;
    const int ew_grid = 148 * 16;
    const int gemm_blocks = (NN + 127) / 128;
    const int gather_blocks = (NN * 32 + TB - 1) / TB;
    const int g64p_blocks = (NN + 63) / 64;

    // zero deg, then fork s2 for pool setup (depends only on inputs)
    cudaMemsetAsync(deg, 0, NN * sizeof(int), 0);
    cudaEventRecord(e_root, 0);
    cudaStreamWaitEvent(s2, e_root, 0);
    k_zero_pool<<<(NG * 64 + TB - 1) / TB, TB, 0, s2>>>(gsum, gcnt);
    k_count<<<nblkN, TB, 0, s2>>>(batch, gcnt);
    cudaEventRecord(e_pool, s2);

    // ---- CSR build + normalization
    k_deg_count<<<ew_grid, TB>>>(dst, deg);
    k_scan_block<<<NB_SCAN, SCAN_BLK>>>(deg, rowptr, partials);
    k_scan_finish<<<nblkN, TB>>>(rowptr, partials, nextptr, deg, dis);
    cudaEventRecord(e_scan, 0);

    // fork: fill on s1 (atomic/LTS-bound) overlaps gemm1 (tensor-bound)
    cudaStreamWaitEvent(s1, e_scan, 0);
    k_fill<<<ew_grid, TB, 0, s1>>>(src, dst, nextptr, csr);
    cudaEventRecord(e_fill, s1);

    // ---- layer 1: hb = bf16((x@W1)*dis) ; h1 = relu(dn*(sum+self)+b1)
    k_gemm_tc<128><<<gemm_blocks, 256>>>(x, W1, dis, hb, NN);
    cudaStreamWaitEvent(0, e_fill, 0);   // join s1
    k_gather128s<<<gather_blocks, TB>>>(hb, dis, deg, rowptr, csr, b1, h1);

    // ---- layer 2: hb = bf16((h1@W2)*dis) ; gather+pool fused
    k_gemm_tc<64><<<gemm_blocks, 256>>>(h1, W2, dis, hb, NN);
    cudaStreamWaitEvent(0, e_pool, 0);   // join s2 (gsum zeroed, counts ready)
    k_gather64pool<<<g64p_blocks, TB>>>(hb, dis, deg, rowptr, csr, b2, batch, gsum);

    // ---- head
    k_final2<<<1, 256>>>(gsum, gcnt, Wf1, bf1, Wf2, bf2, out);
}

// round 12
// speedup vs baseline: 1.0682x; 1.0682x over previous
#include <cuda_runtime.h>
#include <cuda_bf16.h>
#include <cstdint>

// Problem constants (fixed by the dataset)
#define NN 100000
#define EE 3200000
#define NG 64
#define F_IN 128
#define H1 128
#define H2 64
#define DENSE 128
#define LABELS 2

#define SCAN_BLK 512
#define NB_SCAN ((NN + SCAN_BLK - 1) / SCAN_BLK)   // 196

// ---------------- scratch (__device__ globals; no runtime allocation) -------
__device__ float g_dis[NN];
__device__ int   g_deg[NN];
__device__ int   g_rowptr[NN];
__device__ int   g_nextptr[NN];
__device__ int   g_partials[256];
__device__ int   g_csr[EE];                       // src per CSR slot
__device__ __nv_bfloat16 g_hb[(size_t)NN * 128];  // gemm outputs, pre-scaled by dis
__device__ float g_h1[(size_t)NN * 128];          // relu(layer1)
__device__ float g_h2[(size_t)NN * 64];           // relu(layer2)
__device__ float g_gsum[NG * 64];
__device__ float g_gcnt[NG];

// ---------------- CSR build --------------------------------------------------
__global__ void k_zero_deg(int* deg) {
    int i = blockIdx.x * blockDim.x + threadIdx.x;
    if (i < NN) deg[i] = 0;
}

__global__ void k_deg_count(const int* __restrict__ dst, int* __restrict__ deg) {
    int i = blockIdx.x * blockDim.x + threadIdx.x;
    int stride = gridDim.x * blockDim.x;
    const int4* d4 = (const int4*)dst;
    for (; i < EE / 4; i += stride) {
        int4 v = __ldg(&d4[i]);
        atomicAdd(&deg[v.x], 1);
        atomicAdd(&deg[v.y], 1);
        atomicAdd(&deg[v.z], 1);
        atomicAdd(&deg[v.w], 1);
    }
}

__global__ void k_dis(const int* __restrict__ deg, float* __restrict__ dis) {
    int i = blockIdx.x * blockDim.x + threadIdx.x;
    if (i < NN) dis[i] = rsqrtf(1.0f + (float)deg[i]);
}

__global__ void k_scan_block(const int* __restrict__ deg, int* __restrict__ rowptr,
                             int* __restrict__ partials) {
    __shared__ int s[SCAN_BLK];
    int tid = threadIdx.x;
    int i = blockIdx.x * SCAN_BLK + tid;
    int v = (i < NN) ? deg[i] : 0;
    s[tid] = v;
    __syncthreads();
#pragma unroll
    for (int off = 1; off < SCAN_BLK; off <<= 1) {
        int t = (tid >= off) ? s[tid - off] : 0;
        __syncthreads();
        s[tid] += t;
        __syncthreads();
    }
    if (i < NN) rowptr[i] = s[tid] - v;
    if (tid == SCAN_BLK - 1) partials[blockIdx.x] = s[tid];
}

__global__ void k_scan_partials(int* __restrict__ partials) {
    __shared__ int s[256];
    int tid = threadIdx.x;
    int v = (tid < NB_SCAN) ? partials[tid] : 0;
    s[tid] = v;
    __syncthreads();
#pragma unroll
    for (int off = 1; off < 256; off <<= 1) {
        int t = (tid >= off) ? s[tid - off] : 0;
        __syncthreads();
        s[tid] += t;
        __syncthreads();
    }
    if (tid < NB_SCAN) partials[tid] = s[tid] - v;
}

__global__ void k_scan_add(int* __restrict__ rowptr, const int* __restrict__ partials,
                           int* __restrict__ nextptr) {
    int i = blockIdx.x * blockDim.x + threadIdx.x;
    if (i < NN) {
        int r = rowptr[i] + partials[i / SCAN_BLK];
        rowptr[i] = r;
        nextptr[i] = r;
    }
}

__global__ void k_fill(const int* __restrict__ src, const int* __restrict__ dst,
                       int* __restrict__ nextptr, int* __restrict__ csr) {
    int i = blockIdx.x * blockDim.x + threadIdx.x;
    int stride = gridDim.x * blockDim.x;
    for (; i < EE; i += stride) {
        int d = dst[i];
        int s = src[i];
        int pos = atomicAdd(&nextptr[d], 1);
        csr[pos] = s;
    }
}

// ---------------- tf32 helpers ----------------------------------------------
__device__ __forceinline__ uint32_t f2tf32(float f) {
    uint32_t r;
    asm("cvt.rna.tf32.f32 %0, %1;" : "=r"(r) : "f"(f));
    return r;
}

__device__ __forceinline__ void tf32_store4(float* p, float4 v) {
    uint32_t hx = f2tf32(v.x), hy = f2tf32(v.y), hz = f2tf32(v.z), hw = f2tf32(v.w);
    *(float4*)p = make_float4(__uint_as_float(hx), __uint_as_float(hy),
                              __uint_as_float(hz), __uint_as_float(hw));
}

__device__ __forceinline__ void mma_tf32(float d[4], const uint32_t a[4],
                                         uint32_t b0, uint32_t b1) {
    asm volatile(
        "mma.sync.aligned.m16n8k8.row.col.f32.tf32.tf32.f32 "
        "{%0,%1,%2,%3},{%4,%5,%6,%7},{%8,%9},{%0,%1,%2,%3};"
        : "+f"(d[0]), "+f"(d[1]), "+f"(d[2]), "+f"(d[3])
        : "r"(a[0]), "r"(a[1]), "r"(a[2]), "r"(a[3]), "r"(b0), "r"(b1));
}

// ---------------- tf32 GEMM: Cb[M,BN] = bf16((A[M,128] @ B[128,BN]) * dis[m])
template<int BN>
__global__ void __launch_bounds__(256)
k_gemm_tc(const float* __restrict__ A, const float* __restrict__ B,
          const float* __restrict__ dis, __nv_bfloat16* __restrict__ Cb, int M) {
    constexpr int BM = 128, BK = 16, KTOT = 128;
    constexpr int AP = 20;
    constexpr int BP = BN + 8;
    constexpr int NT = (BN / 2) / 8;
    __shared__ float sA[BM * AP];
    __shared__ float sB[BK * BP];

    int tid = threadIdx.x;
    int row0 = blockIdx.x * BM;
    int lane = tid & 31, warp = tid >> 5;
    int wr = warp >> 1, wc = warp & 1;
    int g = lane >> 2, tig = lane & 3;

    float acc[2][NT][4];
#pragma unroll
    for (int m = 0; m < 2; m++)
#pragma unroll
        for (int n = 0; n < NT; n++)
#pragma unroll
            for (int i = 0; i < 4; i++) acc[m][n][i] = 0.f;

    for (int kk = 0; kk < KTOT; kk += BK) {
#pragma unroll
        for (int i = 0; i < 2; i++) {
            int j = tid + 256 * i;
            int r = j >> 2;
            int c4 = (j & 3) * 4;
            float4 v = make_float4(0.f, 0.f, 0.f, 0.f);
            if (row0 + r < M)
                v = *(const float4*)(A + (size_t)(row0 + r) * KTOT + kk + c4);
            tf32_store4(sA + r * AP + c4, v);
        }
#pragma unroll
        for (int i = 0; i < BN / 64; i++) {
            int j = tid + 256 * i;
            int r = j / (BN / 4);
            int c4 = (j % (BN / 4)) * 4;
            float4 v = *(const float4*)(B + (size_t)(kk + r) * BN + c4);
            tf32_store4(sB + r * BP + c4, v);
        }
        __syncthreads();

#pragma unroll
        for (int ks = 0; ks < 2; ks++) {
            int k0 = ks * 8;
            uint32_t a[2][4];
#pragma unroll
            for (int mt = 0; mt < 2; mt++) {
                int rb = wr * 32 + mt * 16;
                a[mt][0] = __float_as_uint(sA[(rb + g) * AP + k0 + tig]);
                a[mt][1] = __float_as_uint(sA[(rb + g + 8) * AP + k0 + tig]);
                a[mt][2] = __float_as_uint(sA[(rb + g) * AP + k0 + tig + 4]);
                a[mt][3] = __float_as_uint(sA[(rb + g + 8) * AP + k0 + tig + 4]);
            }
#pragma unroll
            for (int nt = 0; nt < NT; nt++) {
                int nc = wc * (BN / 2) + nt * 8 + g;
                uint32_t b0 = __float_as_uint(sB[(k0 + tig) * BP + nc]);
                uint32_t b1 = __float_as_uint(sB[(k0 + tig + 4) * BP + nc]);
#pragma unroll
                for (int mt = 0; mt < 2; mt++)
                    mma_tf32(acc[mt][nt], a[mt], b0, b1);
            }
        }
        __syncthreads();
    }

#pragma unroll
    for (int mt = 0; mt < 2; mt++) {
        int r1 = row0 + wr * 32 + mt * 16 + g;
        int r2 = r1 + 8;
        float d1 = (r1 < M) ? __ldg(&dis[r1]) : 0.f;
        float d2 = (r2 < M) ? __ldg(&dis[r2]) : 0.f;
#pragma unroll
        for (int nt = 0; nt < NT; nt++) {
            int cc = wc * (BN / 2) + nt * 8 + 2 * tig;
            if (r1 < M)
                *(__nv_bfloat162*)(Cb + (size_t)r1 * BN + cc) =
                    __float22bfloat162_rn(make_float2(acc[mt][nt][0] * d1,
                                                      acc[mt][nt][1] * d1));
            if (r2 < M)
                *(__nv_bfloat162*)(Cb + (size_t)r2 * BN + cc) =
                    __float22bfloat162_rn(make_float2(acc[mt][nt][2] * d2,
                                                      acc[mt][nt][3] * d2));
        }
    }
}

// ---------------- fused gather: out = relu(dn*(sum_src hb + hb[node]) + b) --
__device__ __forceinline__ void accum8(float* a, uint4 v) {
    float2 f;
    f = __bfloat1622float2(*reinterpret_cast<__nv_bfloat162*>(&v.x));
    a[0] += f.x; a[1] += f.y;
    f = __bfloat1622float2(*reinterpret_cast<__nv_bfloat162*>(&v.y));
    a[2] += f.x; a[3] += f.y;
    f = __bfloat1622float2(*reinterpret_cast<__nv_bfloat162*>(&v.z));
    a[4] += f.x; a[5] += f.y;
    f = __bfloat1622float2(*reinterpret_cast<__nv_bfloat162*>(&v.w));
    a[6] += f.x; a[7] += f.y;
}

__device__ __forceinline__ void accum4(float* a, uint2 v) {
    float2 f;
    f = __bfloat1622float2(*reinterpret_cast<__nv_bfloat162*>(&v.x));
    a[0] += f.x; a[1] += f.y;
    f = __bfloat1622float2(*reinterpret_cast<__nv_bfloat162*>(&v.y));
    a[2] += f.x; a[3] += f.y;
}

// K=128: half-warp per edge row (16 lanes x uint4 = 256 B), 8 edges/iter.
__global__ void __launch_bounds__(256)
k_gather128s(const __nv_bfloat16* __restrict__ hb, const float* __restrict__ dis,
             const int* __restrict__ deg, const int* __restrict__ rowptr,
             const int* __restrict__ csr, const float* __restrict__ bias,
             float* __restrict__ out) {
    int warp = (blockIdx.x * blockDim.x + threadIdx.x) >> 5;
    int lane = threadIdx.x & 31;
    int h = lane >> 4;
    int l = lane & 15;
    int nwarps = (gridDim.x * blockDim.x) >> 5;
    for (int node = warp; node < NN; node += nwarps) {
        int beg = rowptr[node];
        int cnt = deg[node];
        float acc[8] = {0.f, 0.f, 0.f, 0.f, 0.f, 0.f, 0.f, 0.f};
        int off = beg + h;
        int e = 0;
        for (; e + 7 < cnt; e += 8) {
            int s0 = __ldg(csr + off + e);
            int s1 = __ldg(csr + off + e + 2);
            int s2 = __ldg(csr + off + e + 4);
            int s3 = __ldg(csr + off + e + 6);
            uint4 v0 = *(const uint4*)(hb + (size_t)s0 * 128 + l * 8);
            uint4 v1 = *(const uint4*)(hb + (size_t)s1 * 128 + l * 8);
            uint4 v2 = *(const uint4*)(hb + (size_t)s2 * 128 + l * 8);
            uint4 v3 = *(const uint4*)(hb + (size_t)s3 * 128 + l * 8);
            accum8(acc, v0); accum8(acc, v1); accum8(acc, v2); accum8(acc, v3);
        }
        for (; e < cnt; e += 2) {
            int idx = e + h;
            if (idx < cnt) {
                int s = __ldg(csr + beg + idx);
                uint4 v = *(const uint4*)(hb + (size_t)s * 128 + l * 8);
                accum8(acc, v);
            }
        }
        if (h == 0) {
            uint4 v = *(const uint4*)(hb + (size_t)node * 128 + l * 8);
            accum8(acc, v);
        }
#pragma unroll
        for (int i = 0; i < 8; i++)
            acc[i] += __shfl_xor_sync(0xffffffffu, acc[i], 16);
        if (h == 0) {
            float dn = dis[node];
            float4 b0 = *(const float4*)(bias + l * 8);
            float4 b1 = *(const float4*)(bias + l * 8 + 4);
            float4 r0, r1;
            r0.x = fmaxf(acc[0] * dn + b0.x, 0.f);
            r0.y = fmaxf(acc[1] * dn + b0.y, 0.f);
            r0.z = fmaxf(acc[2] * dn + b0.z, 0.f);
            r0.w = fmaxf(acc[3] * dn + b0.w, 0.f);
            r1.x = fmaxf(acc[4] * dn + b1.x, 0.f);
            r1.y = fmaxf(acc[5] * dn + b1.y, 0.f);
            r1.z = fmaxf(acc[6] * dn + b1.z, 0.f);
            r1.w = fmaxf(acc[7] * dn + b1.w, 0.f);
            *(float4*)(out + (size_t)node * 128 + l * 8) = r0;
            *(float4*)(out + (size_t)node * 128 + l * 8 + 4) = r1;
        }
    }
}

// K=64: half-warp per edge row (16 lanes x uint2 = 128 B), 8 edges/iter.
__global__ void __launch_bounds__(256)
k_gather64s(const __nv_bfloat16* __restrict__ hb, const float* __restrict__ dis,
            const int* __restrict__ deg, const int* __restrict__ rowptr,
            const int* __restrict__ csr, const float* __restrict__ bias,
            float* __restrict__ out) {
    int warp = (blockIdx.x * blockDim.x + threadIdx.x) >> 5;
    int lane = threadIdx.x & 31;
    int h = lane >> 4;
    int l = lane & 15;
    int nwarps = (gridDim.x * blockDim.x) >> 5;
    for (int node = warp; node < NN; node += nwarps) {
        int beg = rowptr[node];
        int cnt = deg[node];
        float acc[4] = {0.f, 0.f, 0.f, 0.f};
        int off = beg + h;
        int e = 0;
        for (; e + 7 < cnt; e += 8) {
            int s0 = __ldg(csr + off + e);
            int s1 = __ldg(csr + off + e + 2);
            int s2 = __ldg(csr + off + e + 4);
            int s3 = __ldg(csr + off + e + 6);
            uint2 v0 = *(const uint2*)(hb + (size_t)s0 * 64 + l * 4);
            uint2 v1 = *(const uint2*)(hb + (size_t)s1 * 64 + l * 4);
            uint2 v2 = *(const uint2*)(hb + (size_t)s2 * 64 + l * 4);
            uint2 v3 = *(const uint2*)(hb + (size_t)s3 * 64 + l * 4);
            accum4(acc, v0); accum4(acc, v1); accum4(acc, v2); accum4(acc, v3);
        }
        for (; e < cnt; e += 2) {
            int idx = e + h;
            if (idx < cnt) {
                int s = __ldg(csr + beg + idx);
                uint2 v = *(const uint2*)(hb + (size_t)s * 64 + l * 4);
                accum4(acc, v);
            }
        }
        if (h == 0) {
            uint2 v = *(const uint2*)(hb + (size_t)node * 64 + l * 4);
            accum4(acc, v);
        }
#pragma unroll
        for (int i = 0; i < 4; i++)
            acc[i] += __shfl_xor_sync(0xffffffffu, acc[i], 16);
        if (h == 0) {
            float dn = dis[node];
            float4 bv = *(const float4*)(bias + l * 4);
            float4 r;
            r.x = fmaxf(acc[0] * dn + bv.x, 0.f);
            r.y = fmaxf(acc[1] * dn + bv.y, 0.f);
            r.z = fmaxf(acc[2] * dn + bv.z, 0.f);
            r.w = fmaxf(acc[3] * dn + bv.w, 0.f);
            *(float4*)(out + (size_t)node * 64 + l * 4) = r;
        }
    }
}

// ---------------- pooling (64-wide, over h2) --------------------------------
__global__ void k_zero_pool(float* gsum, float* gcnt) {
    int i = blockIdx.x * blockDim.x + threadIdx.x;
    if (i < NG * 64) gsum[i] = 0.f;
    if (i < NG) gcnt[i] = 0.f;
}

__global__ void k_count(const int* __restrict__ batch, float* __restrict__ gcnt) {
    int i = blockIdx.x * blockDim.x + threadIdx.x;
    unsigned act = __ballot_sync(0xffffffffu, i < NN);
    if (i < NN) {
        int b = batch[i];
        unsigned m = __match_any_sync(act, b);
        int leader = __ffs(m) - 1;
        if ((threadIdx.x & 31) == leader)
            atomicAdd(&gcnt[b], (float)__popc(m));
    }
}

__global__ void k_pool64(const float* __restrict__ h2, const int* __restrict__ batch,
                         float* __restrict__ gsum) {
    constexpr int RB = 256;
    __shared__ float sm[4][64];
    __shared__ int s_gmin, s_ngr;
    int base = blockIdx.x * RB;
    int nrows = NN - base; if (nrows > RB) nrows = RB;
    int tid = threadIdx.x;
    if (tid == 0) {
        int gmin = batch[base];
        int gmax = batch[base + nrows - 1];
        s_gmin = gmin; s_ngr = gmax - gmin + 1;
    }
    for (int i = tid; i < 4 * 64; i += 256) ((float*)sm)[i] = 0.f;
    __syncthreads();
    int gmin = s_gmin, ngr = s_ngr;
    int col = tid & 63, strip = tid >> 6;
    if (ngr <= 4) {
        int curg = -1; float acc = 0.f;
        for (int r = strip; r < nrows; r += 4) {
            int node = base + r;
            int g = batch[node];
            float v = h2[(size_t)node * 64 + col];
            if (g != curg) {
                if (curg >= 0) atomicAdd(&sm[curg - gmin][col], acc);
                curg = g; acc = v;
            } else acc += v;
        }
        if (curg >= 0) atomicAdd(&sm[curg - gmin][col], acc);
        __syncthreads();
        if (tid < 64)
            for (int s = 0; s < ngr; s++)
                atomicAdd(&gsum[(size_t)(gmin + s) * 64 + col], sm[s][col]);
    } else {
        for (int r = strip; r < nrows; r += 4) {
            int node = base + r;
            atomicAdd(&gsum[(size_t)batch[node] * 64 + col],
                      h2[(size_t)node * 64 + col]);
        }
    }
}

// ---------------- final: ge = (gsum/cnt)@Wf1+bf1 ; ic = ge@Wf2+bf2 ----------
__global__ void k_final2(const float* __restrict__ gsum, const float* __restrict__ gcnt,
                         const float* __restrict__ Wf1, const float* __restrict__ bf1,
                         const float* __restrict__ Wf2, const float* __restrict__ bf2,
                         float* __restrict__ out) {
    __shared__ float ge[NG * DENSE];
    int tid = threadIdx.x;                     // 256
    for (int idx = tid; idx < NG * DENSE; idx += 256) {
        int gg = idx >> 7, j = idx & 127;
        float inv = 1.0f / fmaxf(gcnt[gg], 1.0f);
        const float* pg = gsum + gg * 64;
        float a = 0.f;
#pragma unroll 8
        for (int c = 0; c < 64; c++)
            a += pg[c] * Wf1[c * DENSE + j];
        float v = a * inv + bf1[j];
        ge[idx] = v;
        out[idx] = v;
    }
    __syncthreads();
    if (tid < NG * LABELS) {
        int gg = tid >> 1, l = tid & 1;
        float s = bf2[l];
#pragma unroll 8
        for (int c = 0; c < DENSE; c++)
            s += ge[gg * DENSE + c] * Wf2[c * LABELS + l];
        out[NG * DENSE + 1 + tid] = s;
    }
    if (tid == 0) out[NG * DENSE] = 0.f;
}

// ---------------- launch ----------------------------------------------------
extern "C" void kernel_launch(void* const* d_in, const int* in_sizes, int n_in,
                              void* d_out, int out_size) {
    const float* x   = (const float*)d_in[0];
    const float* W1  = (const float*)d_in[1];
    const float* b1  = (const float*)d_in[2];
    const float* W2  = (const float*)d_in[3];
    const float* b2  = (const float*)d_in[4];
    const float* Wf1 = (const float*)d_in[5];
    const float* bf1 = (const float*)d_in[6];
    const float* Wf2 = (const float*)d_in[7];
    const float* bf2 = (const float*)d_in[8];
    const int* ei    = (const int*)d_in[9];
    const int* batch = (const int*)d_in[10];
    const int* src = ei;
    const int* dst = ei + EE;
    float* out = (float*)d_out;

    float *dis, *h1, *h2, *gsum, *gcnt;
    __nv_bfloat16* hb;
    int *deg, *rowptr, *nextptr, *partials, *csr;
    cudaGetSymbolAddress((void**)&dis,  g_dis);
    cudaGetSymbolAddress((void**)&deg,  g_deg);
    cudaGetSymbolAddress((void**)&rowptr, g_rowptr);
    cudaGetSymbolAddress((void**)&nextptr, g_nextptr);
    cudaGetSymbolAddress((void**)&partials, g_partials);
    cudaGetSymbolAddress((void**)&csr,  g_csr);
    cudaGetSymbolAddress((void**)&hb,   g_hb);
    cudaGetSymbolAddress((void**)&h1,   g_h1);
    cudaGetSymbolAddress((void**)&h2,   g_h2);
    cudaGetSymbolAddress((void**)&gsum, g_gsum);
    cudaGetSymbolAddress((void**)&gcnt, g_gcnt);

    // side streams + events (created once, on the uncaptured correctness call)
    static cudaStream_t s1 = nullptr, s2 = nullptr;
    static cudaEvent_t e_root = nullptr, e_dis = nullptr,
                       e_g1 = nullptr, e_pool = nullptr;
    if (!s1) {
        cudaStreamCreateWithFlags(&s1, cudaStreamNonBlocking);
        cudaStreamCreateWithFlags(&s2, cudaStreamNonBlocking);
        cudaEventCreateWithFlags(&e_root, cudaEventDisableTiming);
        cudaEventCreateWithFlags(&e_dis,  cudaEventDisableTiming);
        cudaEventCreateWithFlags(&e_g1,   cudaEventDisableTiming);
        cudaEventCreateWithFlags(&e_pool, cudaEventDisableTiming);
    }

    const int TB = 256;
    const int nblkN = (NN + TB - 1) / TB;
    const int ew_grid = 148 * 16;
    const int gemm_blocks = (NN + 127) / 128;
    const int gather_blocks = (NN * 32 + TB - 1) / TB;

    // fork point for s2 (pool setup depends only on inputs)
    k_zero_deg<<<nblkN, TB>>>(deg);
    cudaEventRecord(e_root, 0);
    cudaStreamWaitEvent(s2, e_root, 0);
    k_zero_pool<<<(NG * 64 + TB - 1) / TB, TB, 0, s2>>>(gsum, gcnt);
    k_count<<<nblkN, TB, 0, s2>>>(batch, gcnt);
    cudaEventRecord(e_pool, s2);

    // ---- degree + dis, then gemm1 forks onto s1 (dis is its only dependency)
    k_deg_count<<<ew_grid, TB>>>(dst, deg);
    k_dis<<<nblkN, TB>>>(deg, dis);
    cudaEventRecord(e_dis, 0);
    cudaStreamWaitEvent(s1, e_dis, 0);
    k_gemm_tc<128><<<gemm_blocks, 256, 0, s1>>>(x, W1, dis, hb, NN);   // s1
    cudaEventRecord(e_g1, s1);

    // ---- scan + fill on default stream, overlapping gemm1
    k_scan_block<<<NB_SCAN, SCAN_BLK>>>(deg, rowptr, partials);
    k_scan_partials<<<1, 256>>>(partials);
    k_scan_add<<<nblkN, TB>>>(rowptr, partials, nextptr);
    k_fill<<<ew_grid, TB>>>(src, dst, nextptr, csr);

    // join gemm1, then layer-1 gather
    cudaStreamWaitEvent(0, e_g1, 0);
    k_gather128s<<<gather_blocks, TB>>>(hb, dis, deg, rowptr, csr, b1, h1);

    // ---- layer 2
    k_gemm_tc<64><<<gemm_blocks, 256>>>(h1, W2, dis, hb, NN);
    k_gather64s<<<gather_blocks, TB>>>(hb, dis, deg, rowptr, csr, b2, h2);

    // ---- pooling (Wf1 folded) + head
    cudaStreamWaitEvent(0, e_pool, 0);   // join s2
    k_pool64<<<(NN + 255) / 256, 256>>>(h2, batch, gsum);
    k_final2<<<1, 256>>>(gsum, gcnt, Wf1, bf1, Wf2, bf2, out);
}

// round 13
// speedup vs baseline: 1.0928x; 1.0230x over previous
#include <cuda_runtime.h>
#include <cuda_bf16.h>
#include <cstdint>

// Problem constants (fixed by the dataset)
#define NN 100000
#define EE 3200000
#define NG 64
#define F_IN 128
#define H1 128
#define H2 64
#define DENSE 128
#define LABELS 2

#define SCAN_BLK 512
#define NB_SCAN ((NN + SCAN_BLK - 1) / SCAN_BLK)   // 196

// ---------------- scratch (__device__ globals; no runtime allocation) -------
__device__ float g_dis[NN];
__device__ int   g_deg[NN];
__device__ int   g_rowptr[NN];
__device__ int   g_nextptr[NN];
__device__ int   g_partials[256];
__device__ int   g_csr[EE];                        // src per CSR slot
__device__ __nv_bfloat16 g_hb[(size_t)NN * 128];   // gemm outputs, pre-scaled by dis
__device__ __nv_bfloat16 g_h1[(size_t)NN * 128];   // relu(layer1), bf16
__device__ __nv_bfloat16 g_h2[(size_t)NN * 64];    // relu(layer2), bf16
__device__ float g_gsum[NG * 64];
__device__ float g_gcnt[NG];

// ---------------- CSR build --------------------------------------------------
__global__ void k_zero_deg(int* deg) {
    int i = blockIdx.x * blockDim.x + threadIdx.x;
    if (i < NN) deg[i] = 0;
}

__global__ void k_deg_count(const int* __restrict__ dst, int* __restrict__ deg) {
    int i = blockIdx.x * blockDim.x + threadIdx.x;
    int stride = gridDim.x * blockDim.x;
    const int4* d4 = (const int4*)dst;
    for (; i < EE / 4; i += stride) {
        int4 v = __ldg(&d4[i]);
        atomicAdd(&deg[v.x], 1);
        atomicAdd(&deg[v.y], 1);
        atomicAdd(&deg[v.z], 1);
        atomicAdd(&deg[v.w], 1);
    }
}

__global__ void k_dis(const int* __restrict__ deg, float* __restrict__ dis) {
    int i = blockIdx.x * blockDim.x + threadIdx.x;
    if (i < NN) dis[i] = rsqrtf(1.0f + (float)deg[i]);
}

__global__ void k_scan_block(const int* __restrict__ deg, int* __restrict__ rowptr,
                             int* __restrict__ partials) {
    __shared__ int s[SCAN_BLK];
    int tid = threadIdx.x;
    int i = blockIdx.x * SCAN_BLK + tid;
    int v = (i < NN) ? deg[i] : 0;
    s[tid] = v;
    __syncthreads();
#pragma unroll
    for (int off = 1; off < SCAN_BLK; off <<= 1) {
        int t = (tid >= off) ? s[tid - off] : 0;
        __syncthreads();
        s[tid] += t;
        __syncthreads();
    }
    if (i < NN) rowptr[i] = s[tid] - v;           // block-local exclusive
    if (tid == SCAN_BLK - 1) partials[blockIdx.x] = s[tid];
}

// fused: scan the 196 partials (redundantly per block) + finalize rowptr/nextptr
__global__ void k_scan_finish(int* __restrict__ rowptr, const int* __restrict__ partials,
                              int* __restrict__ nextptr) {
    __shared__ int s[256];
    int tid = threadIdx.x;
    int v = (tid < NB_SCAN) ? partials[tid] : 0;
    s[tid] = v;
    __syncthreads();
#pragma unroll
    for (int off = 1; off < 256; off <<= 1) {
        int t = (tid >= off) ? s[tid - off] : 0;
        __syncthreads();
        s[tid] += t;
        __syncthreads();
    }
    int ex = s[tid] - v;                           // exclusive
    __syncthreads();
    s[tid] = ex;
    __syncthreads();
    int i = blockIdx.x * 256 + tid;
    if (i < NN) {
        int r = rowptr[i] + s[i / SCAN_BLK];
        rowptr[i] = r;
        nextptr[i] = r;
    }
}

__global__ void k_fill(const int* __restrict__ src, const int* __restrict__ dst,
                       int* __restrict__ nextptr, int* __restrict__ csr) {
    int i = blockIdx.x * blockDim.x + threadIdx.x;
    int stride = gridDim.x * blockDim.x;
    for (; i < EE; i += stride) {
        int d = dst[i];
        int s = src[i];
        int pos = atomicAdd(&nextptr[d], 1);
        csr[pos] = s;
    }
}

// ---------------- tf32 helpers ----------------------------------------------
__device__ __forceinline__ uint32_t f2tf32(float f) {
    uint32_t r;
    asm("cvt.rna.tf32.f32 %0, %1;" : "=r"(r) : "f"(f));
    return r;
}

__device__ __forceinline__ void tf32_store4(float* p, float4 v) {
    uint32_t hx = f2tf32(v.x), hy = f2tf32(v.y), hz = f2tf32(v.z), hw = f2tf32(v.w);
    *(float4*)p = make_float4(__uint_as_float(hx), __uint_as_float(hy),
                              __uint_as_float(hz), __uint_as_float(hw));
}

__device__ __forceinline__ void mma_tf32(float d[4], const uint32_t a[4],
                                         uint32_t b0, uint32_t b1) {
    asm volatile(
        "mma.sync.aligned.m16n8k8.row.col.f32.tf32.tf32.f32 "
        "{%0,%1,%2,%3},{%4,%5,%6,%7},{%8,%9},{%0,%1,%2,%3};"
        : "+f"(d[0]), "+f"(d[1]), "+f"(d[2]), "+f"(d[3])
        : "r"(a[0]), "r"(a[1]), "r"(a[2]), "r"(a[3]), "r"(b0), "r"(b1));
}

// ---------------- tf32 GEMM (fp32 A): Cb = bf16((A @ B) * dis[m]) -----------
template<int BN>
__global__ void __launch_bounds__(256)
k_gemm_tc(const float* __restrict__ A, const float* __restrict__ B,
          const float* __restrict__ dis, __nv_bfloat16* __restrict__ Cb, int M) {
    constexpr int BM = 128, BK = 16, KTOT = 128;
    constexpr int AP = 20;
    constexpr int BP = BN + 8;
    constexpr int NT = (BN / 2) / 8;
    __shared__ float sA[BM * AP];
    __shared__ float sB[BK * BP];

    int tid = threadIdx.x;
    int row0 = blockIdx.x * BM;
    int lane = tid & 31, warp = tid >> 5;
    int wr = warp >> 1, wc = warp & 1;
    int g = lane >> 2, tig = lane & 3;

    float acc[2][NT][4];
#pragma unroll
    for (int m = 0; m < 2; m++)
#pragma unroll
        for (int n = 0; n < NT; n++)
#pragma unroll
            for (int i = 0; i < 4; i++) acc[m][n][i] = 0.f;

    for (int kk = 0; kk < KTOT; kk += BK) {
#pragma unroll
        for (int i = 0; i < 2; i++) {
            int j = tid + 256 * i;
            int r = j >> 2;
            int c4 = (j & 3) * 4;
            float4 v = make_float4(0.f, 0.f, 0.f, 0.f);
            if (row0 + r < M)
                v = *(const float4*)(A + (size_t)(row0 + r) * KTOT + kk + c4);
            tf32_store4(sA + r * AP + c4, v);
        }
#pragma unroll
        for (int i = 0; i < BN / 64; i++) {
            int j = tid + 256 * i;
            int r = j / (BN / 4);
            int c4 = (j % (BN / 4)) * 4;
            float4 v = *(const float4*)(B + (size_t)(kk + r) * BN + c4);
            tf32_store4(sB + r * BP + c4, v);
        }
        __syncthreads();

#pragma unroll
        for (int ks = 0; ks < 2; ks++) {
            int k0 = ks * 8;
            uint32_t a[2][4];
#pragma unroll
            for (int mt = 0; mt < 2; mt++) {
                int rb = wr * 32 + mt * 16;
                a[mt][0] = __float_as_uint(sA[(rb + g) * AP + k0 + tig]);
                a[mt][1] = __float_as_uint(sA[(rb + g + 8) * AP + k0 + tig]);
                a[mt][2] = __float_as_uint(sA[(rb + g) * AP + k0 + tig + 4]);
                a[mt][3] = __float_as_uint(sA[(rb + g + 8) * AP + k0 + tig + 4]);
            }
#pragma unroll
            for (int nt = 0; nt < NT; nt++) {
                int nc = wc * (BN / 2) + nt * 8 + g;
                uint32_t b0 = __float_as_uint(sB[(k0 + tig) * BP + nc]);
                uint32_t b1 = __float_as_uint(sB[(k0 + tig + 4) * BP + nc]);
#pragma unroll
                for (int mt = 0; mt < 2; mt++)
                    mma_tf32(acc[mt][nt], a[mt], b0, b1);
            }
        }
        __syncthreads();
    }

#pragma unroll
    for (int mt = 0; mt < 2; mt++) {
        int r1 = row0 + wr * 32 + mt * 16 + g;
        int r2 = r1 + 8;
        float d1 = (r1 < M) ? __ldg(&dis[r1]) : 0.f;
        float d2 = (r2 < M) ? __ldg(&dis[r2]) : 0.f;
#pragma unroll
        for (int nt = 0; nt < NT; nt++) {
            int cc = wc * (BN / 2) + nt * 8 + 2 * tig;
            if (r1 < M)
                *(__nv_bfloat162*)(Cb + (size_t)r1 * BN + cc) =
                    __float22bfloat162_rn(make_float2(acc[mt][nt][0] * d1,
                                                      acc[mt][nt][1] * d1));
            if (r2 < M)
                *(__nv_bfloat162*)(Cb + (size_t)r2 * BN + cc) =
                    __float22bfloat162_rn(make_float2(acc[mt][nt][2] * d2,
                                                      acc[mt][nt][3] * d2));
        }
    }
}

// ---------------- tf32 GEMM (bf16 A, BN=64): Cb = bf16((A @ B) * dis[m]) ----
__global__ void __launch_bounds__(256)
k_gemm_tc_h(const __nv_bfloat16* __restrict__ A, const float* __restrict__ B,
            const float* __restrict__ dis, __nv_bfloat16* __restrict__ Cb, int M) {
    constexpr int BM = 128, BK = 16, KTOT = 128, BN = 64;
    constexpr int AP = 20;
    constexpr int BP = BN + 8;
    constexpr int NT = (BN / 2) / 8;   // 4
    __shared__ float sA[BM * AP];
    __shared__ float sB[BK * BP];

    int tid = threadIdx.x;
    int row0 = blockIdx.x * BM;
    int lane = tid & 31, warp = tid >> 5;
    int wr = warp >> 1, wc = warp & 1;
    int g = lane >> 2, tig = lane & 3;

    float acc[2][NT][4];
#pragma unroll
    for (int m = 0; m < 2; m++)
#pragma unroll
        for (int n = 0; n < NT; n++)
#pragma unroll
            for (int i = 0; i < 4; i++) acc[m][n][i] = 0.f;

    for (int kk = 0; kk < KTOT; kk += BK) {
        // A tile [BM x BK] bf16 = 4096 B = 256 x uint4 (8 bf16 each)
        {
            int r = tid >> 1;             // 0..127
            int half = tid & 1;           // 8-col half
            uint4 v = make_uint4(0, 0, 0, 0);
            if (row0 + r < M)
                v = *(const uint4*)(A + (size_t)(row0 + r) * KTOT + kk + half * 8);
            const __nv_bfloat162* p = (const __nv_bfloat162*)&v;
            float* o = sA + r * AP + half * 8;
#pragma unroll
            for (int q = 0; q < 4; q++) {
                float2 f = __bfloat1622float2(p[q]);
                o[q * 2] = f.x;
                o[q * 2 + 1] = f.y;       // bf16->f32 is tf32-exact
            }
        }
        // B tile [BK x BN] fp32 = 256 x float4
        {
            int r = tid / (BN / 4);
            int c4 = (tid % (BN / 4)) * 4;
            float4 v = *(const float4*)(B + (size_t)(kk + r) * BN + c4);
            tf32_store4(sB + r * BP + c4, v);
        }
        __syncthreads();

#pragma unroll
        for (int ks = 0; ks < 2; ks++) {
            int k0 = ks * 8;
            uint32_t a[2][4];
#pragma unroll
            for (int mt = 0; mt < 2; mt++) {
                int rb = wr * 32 + mt * 16;
                a[mt][0] = __float_as_uint(sA[(rb + g) * AP + k0 + tig]);
                a[mt][1] = __float_as_uint(sA[(rb + g + 8) * AP + k0 + tig]);
                a[mt][2] = __float_as_uint(sA[(rb + g) * AP + k0 + tig + 4]);
                a[mt][3] = __float_as_uint(sA[(rb + g + 8) * AP + k0 + tig + 4]);
            }
#pragma unroll
            for (int nt = 0; nt < NT; nt++) {
                int nc = wc * (BN / 2) + nt * 8 + g;
                uint32_t b0 = __float_as_uint(sB[(k0 + tig) * BP + nc]);
                uint32_t b1 = __float_as_uint(sB[(k0 + tig + 4) * BP + nc]);
#pragma unroll
                for (int mt = 0; mt < 2; mt++)
                    mma_tf32(acc[mt][nt], a[mt], b0, b1);
            }
        }
        __syncthreads();
    }

#pragma unroll
    for (int mt = 0; mt < 2; mt++) {
        int r1 = row0 + wr * 32 + mt * 16 + g;
        int r2 = r1 + 8;
        float d1 = (r1 < M) ? __ldg(&dis[r1]) : 0.f;
        float d2 = (r2 < M) ? __ldg(&dis[r2]) : 0.f;
#pragma unroll
        for (int nt = 0; nt < NT; nt++) {
            int cc = wc * (BN / 2) + nt * 8 + 2 * tig;
            if (r1 < M)
                *(__nv_bfloat162*)(Cb + (size_t)r1 * BN + cc) =
                    __float22bfloat162_rn(make_float2(acc[mt][nt][0] * d1,
                                                      acc[mt][nt][1] * d1));
            if (r2 < M)
                *(__nv_bfloat162*)(Cb + (size_t)r2 * BN + cc) =
                    __float22bfloat162_rn(make_float2(acc[mt][nt][2] * d2,
                                                      acc[mt][nt][3] * d2));
        }
    }
}

// ---------------- fused gather helpers ---------------------------------------
__device__ __forceinline__ void accum8(float* a, uint4 v) {
    float2 f;
    f = __bfloat1622float2(*reinterpret_cast<__nv_bfloat162*>(&v.x));
    a[0] += f.x; a[1] += f.y;
    f = __bfloat1622float2(*reinterpret_cast<__nv_bfloat162*>(&v.y));
    a[2] += f.x; a[3] += f.y;
    f = __bfloat1622float2(*reinterpret_cast<__nv_bfloat162*>(&v.z));
    a[4] += f.x; a[5] += f.y;
    f = __bfloat1622float2(*reinterpret_cast<__nv_bfloat162*>(&v.w));
    a[6] += f.x; a[7] += f.y;
}

__device__ __forceinline__ void accum4(float* a, uint2 v) {
    float2 f;
    f = __bfloat1622float2(*reinterpret_cast<__nv_bfloat162*>(&v.x));
    a[0] += f.x; a[1] += f.y;
    f = __bfloat1622float2(*reinterpret_cast<__nv_bfloat162*>(&v.y));
    a[2] += f.x; a[3] += f.y;
}

// K=128: half-warp per edge row (16 lanes x uint4 = 256 B), 8 edges/iter.
// out (h1) is bf16.
__global__ void __launch_bounds__(256)
k_gather128s(const __nv_bfloat16* __restrict__ hb, const float* __restrict__ dis,
             const int* __restrict__ deg, const int* __restrict__ rowptr,
             const int* __restrict__ csr, const float* __restrict__ bias,
             __nv_bfloat16* __restrict__ out) {
    int warp = (blockIdx.x * blockDim.x + threadIdx.x) >> 5;
    int lane = threadIdx.x & 31;
    int h = lane >> 4;
    int l = lane & 15;
    int nwarps = (gridDim.x * blockDim.x) >> 5;
    for (int node = warp; node < NN; node += nwarps) {
        int beg = rowptr[node];
        int cnt = deg[node];
        float acc[8] = {0.f, 0.f, 0.f, 0.f, 0.f, 0.f, 0.f, 0.f};
        int off = beg + h;
        int e = 0;
        for (; e + 7 < cnt; e += 8) {
            int s0 = __ldg(csr + off + e);
            int s1 = __ldg(csr + off + e + 2);
            int s2 = __ldg(csr + off + e + 4);
            int s3 = __ldg(csr + off + e + 6);
            uint4 v0 = *(const uint4*)(hb + (size_t)s0 * 128 + l * 8);
            uint4 v1 = *(const uint4*)(hb + (size_t)s1 * 128 + l * 8);
            uint4 v2 = *(const uint4*)(hb + (size_t)s2 * 128 + l * 8);
            uint4 v3 = *(const uint4*)(hb + (size_t)s3 * 128 + l * 8);
            accum8(acc, v0); accum8(acc, v1); accum8(acc, v2); accum8(acc, v3);
        }
        for (; e < cnt; e += 2) {
            int idx = e + h;
            if (idx < cnt) {
                int s = __ldg(csr + beg + idx);
                uint4 v = *(const uint4*)(hb + (size_t)s * 128 + l * 8);
                accum8(acc, v);
            }
        }
        if (h == 0) {
            uint4 v = *(const uint4*)(hb + (size_t)node * 128 + l * 8);
            accum8(acc, v);
        }
#pragma unroll
        for (int i = 0; i < 8; i++)
            acc[i] += __shfl_xor_sync(0xffffffffu, acc[i], 16);
        if (h == 0) {
            float dn = dis[node];
            float4 b0 = *(const float4*)(bias + l * 8);
            float4 b1 = *(const float4*)(bias + l * 8 + 4);
            float r0 = fmaxf(acc[0] * dn + b0.x, 0.f);
            float r1 = fmaxf(acc[1] * dn + b0.y, 0.f);
            float r2 = fmaxf(acc[2] * dn + b0.z, 0.f);
            float r3 = fmaxf(acc[3] * dn + b0.w, 0.f);
            float r4 = fmaxf(acc[4] * dn + b1.x, 0.f);
            float r5 = fmaxf(acc[5] * dn + b1.y, 0.f);
            float r6 = fmaxf(acc[6] * dn + b1.z, 0.f);
            float r7 = fmaxf(acc[7] * dn + b1.w, 0.f);
            uint4 o;
            *reinterpret_cast<__nv_bfloat162*>(&o.x) =
                __float22bfloat162_rn(make_float2(r0, r1));
            *reinterpret_cast<__nv_bfloat162*>(&o.y) =
                __float22bfloat162_rn(make_float2(r2, r3));
            *reinterpret_cast<__nv_bfloat162*>(&o.z) =
                __float22bfloat162_rn(make_float2(r4, r5));
            *reinterpret_cast<__nv_bfloat162*>(&o.w) =
                __float22bfloat162_rn(make_float2(r6, r7));
            *(uint4*)(out + (size_t)node * 128 + l * 8) = o;
        }
    }
}

// K=64: half-warp per edge row (16 lanes x uint2 = 128 B), 8 edges/iter.
// out (h2) is bf16.
__global__ void __launch_bounds__(256)
k_gather64s(const __nv_bfloat16* __restrict__ hb, const float* __restrict__ dis,
            const int* __restrict__ deg, const int* __restrict__ rowptr,
            const int* __restrict__ csr, const float* __restrict__ bias,
            __nv_bfloat16* __restrict__ out) {
    int warp = (blockIdx.x * blockDim.x + threadIdx.x) >> 5;
    int lane = threadIdx.x & 31;
    int h = lane >> 4;
    int l = lane & 15;
    int nwarps = (gridDim.x * blockDim.x) >> 5;
    for (int node = warp; node < NN; node += nwarps) {
        int beg = rowptr[node];
        int cnt = deg[node];
        float acc[4] = {0.f, 0.f, 0.f, 0.f};
        int off = beg + h;
        int e = 0;
        for (; e + 7 < cnt; e += 8) {
            int s0 = __ldg(csr + off + e);
            int s1 = __ldg(csr + off + e + 2);
            int s2 = __ldg(csr + off + e + 4);
            int s3 = __ldg(csr + off + e + 6);
            uint2 v0 = *(const uint2*)(hb + (size_t)s0 * 64 + l * 4);
            uint2 v1 = *(const uint2*)(hb + (size_t)s1 * 64 + l * 4);
            uint2 v2 = *(const uint2*)(hb + (size_t)s2 * 64 + l * 4);
            uint2 v3 = *(const uint2*)(hb + (size_t)s3 * 64 + l * 4);
            accum4(acc, v0); accum4(acc, v1); accum4(acc, v2); accum4(acc, v3);
        }
        for (; e < cnt; e += 2) {
            int idx = e + h;
            if (idx < cnt) {
                int s = __ldg(csr + beg + idx);
                uint2 v = *(const uint2*)(hb + (size_t)s * 64 + l * 4);
                accum4(acc, v);
            }
        }
        if (h == 0) {
            uint2 v = *(const uint2*)(hb + (size_t)node * 64 + l * 4);
            accum4(acc, v);
        }
#pragma unroll
        for (int i = 0; i < 4; i++)
            acc[i] += __shfl_xor_sync(0xffffffffu, acc[i], 16);
        if (h == 0) {
            float dn = dis[node];
            float4 bv = *(const float4*)(bias + l * 4);
            float r0 = fmaxf(acc[0] * dn + bv.x, 0.f);
            float r1 = fmaxf(acc[1] * dn + bv.y, 0.f);
            float r2 = fmaxf(acc[2] * dn + bv.z, 0.f);
            float r3 = fmaxf(acc[3] * dn + bv.w, 0.f);
            uint2 o;
            *reinterpret_cast<__nv_bfloat162*>(&o.x) =
                __float22bfloat162_rn(make_float2(r0, r1));
            *reinterpret_cast<__nv_bfloat162*>(&o.y) =
                __float22bfloat162_rn(make_float2(r2, r3));
            *(uint2*)(out + (size_t)node * 64 + l * 4) = o;
        }
    }
}

// ---------------- pooling (64-wide, bf16 in) ---------------------------------
__global__ void k_zero_pool(float* gsum, float* gcnt) {
    int i = blockIdx.x * blockDim.x + threadIdx.x;
    if (i < NG * 64) gsum[i] = 0.f;
    if (i < NG) gcnt[i] = 0.f;
}

__global__ void k_count(const int* __restrict__ batch, float* __restrict__ gcnt) {
    int i = blockIdx.x * blockDim.x + threadIdx.x;
    unsigned act = __ballot_sync(0xffffffffu, i < NN);
    if (i < NN) {
        int b = batch[i];
        unsigned m = __match_any_sync(act, b);
        int leader = __ffs(m) - 1;
        if ((threadIdx.x & 31) == leader)
            atomicAdd(&gcnt[b], (float)__popc(m));
    }
}

__global__ void k_pool64(const __nv_bfloat16* __restrict__ h2,
                         const int* __restrict__ batch, float* __restrict__ gsum) {
    constexpr int RB = 256;
    __shared__ float sm[4][64];
    __shared__ int s_gmin, s_ngr;
    int base = blockIdx.x * RB;
    int nrows = NN - base; if (nrows > RB) nrows = RB;
    int tid = threadIdx.x;
    if (tid == 0) {
        int gmin = batch[base];
        int gmax = batch[base + nrows - 1];
        s_gmin = gmin; s_ngr = gmax - gmin + 1;
    }
    for (int i = tid; i < 4 * 64; i += 256) ((float*)sm)[i] = 0.f;
    __syncthreads();
    int gmin = s_gmin, ngr = s_ngr;
    int col = tid & 63, strip = tid >> 6;
    if (ngr <= 4) {
        int curg = -1; float acc = 0.f;
        for (int r = strip; r < nrows; r += 4) {
            int node = base + r;
            int g = batch[node];
            float v = __bfloat162float(h2[(size_t)node * 64 + col]);
            if (g != curg) {
                if (curg >= 0) atomicAdd(&sm[curg - gmin][col], acc);
                curg = g; acc = v;
            } else acc += v;
        }
        if (curg >= 0) atomicAdd(&sm[curg - gmin][col], acc);
        __syncthreads();
        if (tid < 64)
            for (int s = 0; s < ngr; s++)
                atomicAdd(&gsum[(size_t)(gmin + s) * 64 + col], sm[s][col]);
    } else {
        for (int r = strip; r < nrows; r += 4) {
            int node = base + r;
            atomicAdd(&gsum[(size_t)batch[node] * 64 + col],
                      __bfloat162float(h2[(size_t)node * 64 + col]));
        }
    }
}

// ---------------- final: ge = (gsum/cnt)@Wf1+bf1 ; ic = ge@Wf2+bf2 ----------
__global__ void k_final2(const float* __restrict__ gsum, const float* __restrict__ gcnt,
                         const float* __restrict__ Wf1, const float* __restrict__ bf1,
                         const float* __restrict__ Wf2, const float* __restrict__ bf2,
                         float* __restrict__ out) {
    __shared__ float ge[NG * DENSE];
    int tid = threadIdx.x;                     // 256
    for (int idx = tid; idx < NG * DENSE; idx += 256) {
        int gg = idx >> 7, j = idx & 127;
        float inv = 1.0f / fmaxf(gcnt[gg], 1.0f);
        const float* pg = gsum + gg * 64;
        float a = 0.f;
#pragma unroll 8
        for (int c = 0; c < 64; c++)
            a += pg[c] * Wf1[c * DENSE + j];
        float v = a * inv + bf1[j];
        ge[idx] = v;
        out[idx] = v;
    }
    __syncthreads();
    if (tid < NG * LABELS) {
        int gg = tid >> 1, l = tid & 1;
        float s = bf2[l];
#pragma unroll 8
        for (int c = 0; c < DENSE; c++)
            s += ge[gg * DENSE + c] * Wf2[c * LABELS + l];
        out[NG * DENSE + 1 + tid] = s;
    }
    if (tid == 0) out[NG * DENSE] = 0.f;
}

// ---------------- launch ----------------------------------------------------
extern "C" void kernel_launch(void* const* d_in, const int* in_sizes, int n_in,
                              void* d_out, int out_size) {
    const float* x   = (const float*)d_in[0];
    const float* W1  = (const float*)d_in[1];
    const float* b1  = (const float*)d_in[2];
    const float* W2  = (const float*)d_in[3];
    const float* b2  = (const float*)d_in[4];
    const float* Wf1 = (const float*)d_in[5];
    const float* bf1 = (const float*)d_in[6];
    const float* Wf2 = (const float*)d_in[7];
    const float* bf2 = (const float*)d_in[8];
    const int* ei    = (const int*)d_in[9];
    const int* batch = (const int*)d_in[10];
    const int* src = ei;
    const int* dst = ei + EE;
    float* out = (float*)d_out;

    float *dis, *gsum, *gcnt;
    __nv_bfloat16 *hb, *h1, *h2;
    int *deg, *rowptr, *nextptr, *partials, *csr;
    cudaGetSymbolAddress((void**)&dis,  g_dis);
    cudaGetSymbolAddress((void**)&deg,  g_deg);
    cudaGetSymbolAddress((void**)&rowptr, g_rowptr);
    cudaGetSymbolAddress((void**)&nextptr, g_nextptr);
    cudaGetSymbolAddress((void**)&partials, g_partials);
    cudaGetSymbolAddress((void**)&csr,  g_csr);
    cudaGetSymbolAddress((void**)&hb,   g_hb);
    cudaGetSymbolAddress((void**)&h1,   g_h1);
    cudaGetSymbolAddress((void**)&h2,   g_h2);
    cudaGetSymbolAddress((void**)&gsum, g_gsum);
    cudaGetSymbolAddress((void**)&gcnt, g_gcnt);

    // side streams + events (created once, on the uncaptured correctness call)
    static cudaStream_t s1 = nullptr, s2 = nullptr;
    static cudaEvent_t e_root = nullptr, e_dis = nullptr,
                       e_g1 = nullptr, e_pool = nullptr;
    if (!s1) {
        cudaStreamCreateWithFlags(&s1, cudaStreamNonBlocking);
        cudaStreamCreateWithFlags(&s2, cudaStreamNonBlocking);
        cudaEventCreateWithFlags(&e_root, cudaEventDisableTiming);
        cudaEventCreateWithFlags(&e_dis,  cudaEventDisableTiming);
        cudaEventCreateWithFlags(&e_g1,   cudaEventDisableTiming);
        cudaEventCreateWithFlags(&e_pool, cudaEventDisableTiming);
    }

    const int TB = 256;
    const int nblkN = (NN + TB - 1) / TB;
    const int ew_grid = 148 * 16;
    const int gemm_blocks = (NN + 127) / 128;
    const int gather_blocks = (NN * 32 + TB - 1) / TB;

    // fork point for s2 (pool setup depends only on inputs)
    k_zero_deg<<<nblkN, TB>>>(deg);
    cudaEventRecord(e_root, 0);
    cudaStreamWaitEvent(s2, e_root, 0);
    k_zero_pool<<<(NG * 64 + TB - 1) / TB, TB, 0, s2>>>(gsum, gcnt);
    k_count<<<nblkN, TB, 0, s2>>>(batch, gcnt);
    cudaEventRecord(e_pool, s2);

    // ---- degree + dis, then gemm1 forks onto s1 (dis is its only dependency)
    k_deg_count<<<ew_grid, TB>>>(dst, deg);
    k_dis<<<nblkN, TB>>>(deg, dis);
    cudaEventRecord(e_dis, 0);
    cudaStreamWaitEvent(s1, e_dis, 0);
    k_gemm_tc<128><<<gemm_blocks, 256, 0, s1>>>(x, W1, dis, hb, NN);   // s1
    cudaEventRecord(e_g1, s1);

    // ---- scan + fill on default stream, overlapping gemm1
    k_scan_block<<<NB_SCAN, SCAN_BLK>>>(deg, rowptr, partials);
    k_scan_finish<<<nblkN, TB>>>(rowptr, partials, nextptr);
    k_fill<<<ew_grid, TB>>>(src, dst, nextptr, csr);

    // join gemm1, then layer-1 gather (h1 bf16)
    cudaStreamWaitEvent(0, e_g1, 0);
    k_gather128s<<<gather_blocks, TB>>>(hb, dis, deg, rowptr, csr, b1, h1);

    // ---- layer 2: bf16-A gemm, then gather (h2 bf16)
    k_gemm_tc_h<<<gemm_blocks, 256>>>(h1, W2, dis, hb, NN);
    k_gather64s<<<gather_blocks, TB>>>(hb, dis, deg, rowptr, csr, b2, h2);

    // ---- pooling (Wf1 folded) + head
    cudaStreamWaitEvent(0, e_pool, 0);   // join s2
    k_pool64<<<(NN + 255) / 256, 256>>>(h2, batch, gsum);
    k_final2<<<1, 256>>>(gsum, gcnt, Wf1, bf1, Wf2, bf2, out);
}

// round 14
// speedup vs baseline: 1.1130x; 1.0185x over previous
#include <cuda_runtime.h>
#include <cuda_bf16.h>
#include <cstdint>

// Problem constants (fixed by the dataset)
#define NN 100000
#define EE 3200000
#define NG 64
#define F_IN 128
#define H1 128
#define H2 64
#define DENSE 128
#define LABELS 2

#define SCAN_BLK 512
#define NB_SCAN ((NN + SCAN_BLK - 1) / SCAN_BLK)   // 196

// ---------------- scratch (__device__ globals; no runtime allocation) -------
__device__ float g_dis[NN];
__device__ int   g_deg[NN];
__device__ int   g_rowptr[NN];
__device__ int   g_nextptr[NN];
__device__ int   g_partials[256];
__device__ int   g_csr[EE];                        // src per CSR slot
__device__ __nv_bfloat16 g_hb[(size_t)NN * 128];   // gemm outputs, pre-scaled by dis
__device__ __nv_bfloat16 g_h1[(size_t)NN * 128];   // relu(layer1), bf16
__device__ __nv_bfloat16 g_h2[(size_t)NN * 64];    // relu(layer2), bf16
__device__ float g_gsum[NG * 64];
__device__ float g_gcnt[NG];

// ---------------- CSR build --------------------------------------------------
__global__ void k_zero_deg(int* deg) {
    int i = blockIdx.x * blockDim.x + threadIdx.x;
    if (i < NN) deg[i] = 0;
}

__global__ void k_deg_count(const int* __restrict__ dst, int* __restrict__ deg) {
    int i = blockIdx.x * blockDim.x + threadIdx.x;
    int stride = gridDim.x * blockDim.x;
    const int4* d4 = (const int4*)dst;
    for (; i < EE / 4; i += stride) {
        int4 v = __ldg(&d4[i]);
        atomicAdd(&deg[v.x], 1);
        atomicAdd(&deg[v.y], 1);
        atomicAdd(&deg[v.z], 1);
        atomicAdd(&deg[v.w], 1);
    }
}

// block-local scan of deg -> rowptr + per-block totals; also emits dis
__global__ void k_scan_block(const int* __restrict__ deg, int* __restrict__ rowptr,
                             int* __restrict__ partials, float* __restrict__ dis) {
    __shared__ int s[SCAN_BLK];
    int tid = threadIdx.x;
    int i = blockIdx.x * SCAN_BLK + tid;
    int v = (i < NN) ? deg[i] : 0;
    s[tid] = v;
    __syncthreads();
#pragma unroll
    for (int off = 1; off < SCAN_BLK; off <<= 1) {
        int t = (tid >= off) ? s[tid - off] : 0;
        __syncthreads();
        s[tid] += t;
        __syncthreads();
    }
    if (i < NN) {
        rowptr[i] = s[tid] - v;           // block-local exclusive
        dis[i] = rsqrtf(1.0f + (float)v);
    }
    if (tid == SCAN_BLK - 1) partials[blockIdx.x] = s[tid];
}

// fused: scan the 196 partials (redundantly per block) + finalize rowptr/nextptr
__global__ void k_scan_finish(int* __restrict__ rowptr, const int* __restrict__ partials,
                              int* __restrict__ nextptr) {
    __shared__ int s[256];
    int tid = threadIdx.x;
    int v = (tid < NB_SCAN) ? partials[tid] : 0;
    s[tid] = v;
    __syncthreads();
#pragma unroll
    for (int off = 1; off < 256; off <<= 1) {
        int t = (tid >= off) ? s[tid - off] : 0;
        __syncthreads();
        s[tid] += t;
        __syncthreads();
    }
    int ex = s[tid] - v;                           // exclusive
    __syncthreads();
    s[tid] = ex;
    __syncthreads();
    int i = blockIdx.x * 256 + tid;
    if (i < NN) {
        int r = rowptr[i] + s[i / SCAN_BLK];
        rowptr[i] = r;
        nextptr[i] = r;
    }
}

__global__ void k_fill(const int* __restrict__ src, const int* __restrict__ dst,
                       int* __restrict__ nextptr, int* __restrict__ csr) {
    int i = blockIdx.x * blockDim.x + threadIdx.x;
    int stride = gridDim.x * blockDim.x;
    for (; i < EE; i += stride) {
        int d = dst[i];
        int s = src[i];
        int pos = atomicAdd(&nextptr[d], 1);
        csr[pos] = s;
    }
}

// ---------------- tf32 helpers ----------------------------------------------
__device__ __forceinline__ uint32_t f2tf32(float f) {
    uint32_t r;
    asm("cvt.rna.tf32.f32 %0, %1;" : "=r"(r) : "f"(f));
    return r;
}

__device__ __forceinline__ void tf32_store4(float* p, float4 v) {
    uint32_t hx = f2tf32(v.x), hy = f2tf32(v.y), hz = f2tf32(v.z), hw = f2tf32(v.w);
    *(float4*)p = make_float4(__uint_as_float(hx), __uint_as_float(hy),
                              __uint_as_float(hz), __uint_as_float(hw));
}

__device__ __forceinline__ void mma_tf32(float d[4], const uint32_t a[4],
                                         uint32_t b0, uint32_t b1) {
    asm volatile(
        "mma.sync.aligned.m16n8k8.row.col.f32.tf32.tf32.f32 "
        "{%0,%1,%2,%3},{%4,%5,%6,%7},{%8,%9},{%0,%1,%2,%3};"
        : "+f"(d[0]), "+f"(d[1]), "+f"(d[2]), "+f"(d[3])
        : "r"(a[0]), "r"(a[1]), "r"(a[2]), "r"(a[3]), "r"(b0), "r"(b1));
}

// ---------------- tf32 GEMM (fp32 A): Cb = bf16((A @ B) * dis[m]) -----------
template<int BN>
__global__ void __launch_bounds__(256)
k_gemm_tc(const float* __restrict__ A, const float* __restrict__ B,
          const float* __restrict__ dis, __nv_bfloat16* __restrict__ Cb, int M) {
    constexpr int BM = 128, BK = 16, KTOT = 128;
    constexpr int AP = 20;
    constexpr int BP = BN + 8;
    constexpr int NT = (BN / 2) / 8;
    __shared__ float sA[BM * AP];
    __shared__ float sB[BK * BP];

    int tid = threadIdx.x;
    int row0 = blockIdx.x * BM;
    int lane = tid & 31, warp = tid >> 5;
    int wr = warp >> 1, wc = warp & 1;
    int g = lane >> 2, tig = lane & 3;

    float acc[2][NT][4];
#pragma unroll
    for (int m = 0; m < 2; m++)
#pragma unroll
        for (int n = 0; n < NT; n++)
#pragma unroll
            for (int i = 0; i < 4; i++) acc[m][n][i] = 0.f;

    for (int kk = 0; kk < KTOT; kk += BK) {
#pragma unroll
        for (int i = 0; i < 2; i++) {
            int j = tid + 256 * i;
            int r = j >> 2;
            int c4 = (j & 3) * 4;
            float4 v = make_float4(0.f, 0.f, 0.f, 0.f);
            if (row0 + r < M)
                v = *(const float4*)(A + (size_t)(row0 + r) * KTOT + kk + c4);
            tf32_store4(sA + r * AP + c4, v);
        }
#pragma unroll
        for (int i = 0; i < BN / 64; i++) {
            int j = tid + 256 * i;
            int r = j / (BN / 4);
            int c4 = (j % (BN / 4)) * 4;
            float4 v = *(const float4*)(B + (size_t)(kk + r) * BN + c4);
            tf32_store4(sB + r * BP + c4, v);
        }
        __syncthreads();

#pragma unroll
        for (int ks = 0; ks < 2; ks++) {
            int k0 = ks * 8;
            uint32_t a[2][4];
#pragma unroll
            for (int mt = 0; mt < 2; mt++) {
                int rb = wr * 32 + mt * 16;
                a[mt][0] = __float_as_uint(sA[(rb + g) * AP + k0 + tig]);
                a[mt][1] = __float_as_uint(sA[(rb + g + 8) * AP + k0 + tig]);
                a[mt][2] = __float_as_uint(sA[(rb + g) * AP + k0 + tig + 4]);
                a[mt][3] = __float_as_uint(sA[(rb + g + 8) * AP + k0 + tig + 4]);
            }
#pragma unroll
            for (int nt = 0; nt < NT; nt++) {
                int nc = wc * (BN / 2) + nt * 8 + g;
                uint32_t b0 = __float_as_uint(sB[(k0 + tig) * BP + nc]);
                uint32_t b1 = __float_as_uint(sB[(k0 + tig + 4) * BP + nc]);
#pragma unroll
                for (int mt = 0; mt < 2; mt++)
                    mma_tf32(acc[mt][nt], a[mt], b0, b1);
            }
        }
        __syncthreads();
    }

#pragma unroll
    for (int mt = 0; mt < 2; mt++) {
        int r1 = row0 + wr * 32 + mt * 16 + g;
        int r2 = r1 + 8;
        float d1 = (r1 < M) ? __ldg(&dis[r1]) : 0.f;
        float d2 = (r2 < M) ? __ldg(&dis[r2]) : 0.f;
#pragma unroll
        for (int nt = 0; nt < NT; nt++) {
            int cc = wc * (BN / 2) + nt * 8 + 2 * tig;
            if (r1 < M)
                *(__nv_bfloat162*)(Cb + (size_t)r1 * BN + cc) =
                    __float22bfloat162_rn(make_float2(acc[mt][nt][0] * d1,
                                                      acc[mt][nt][1] * d1));
            if (r2 < M)
                *(__nv_bfloat162*)(Cb + (size_t)r2 * BN + cc) =
                    __float22bfloat162_rn(make_float2(acc[mt][nt][2] * d2,
                                                      acc[mt][nt][3] * d2));
        }
    }
}

// ---------------- tf32 GEMM (bf16 A, BN=64): Cb = bf16((A @ B) * dis[m]) ----
__global__ void __launch_bounds__(256)
k_gemm_tc_h(const __nv_bfloat16* __restrict__ A, const float* __restrict__ B,
            const float* __restrict__ dis, __nv_bfloat16* __restrict__ Cb, int M) {
    constexpr int BM = 128, BK = 16, KTOT = 128, BN = 64;
    constexpr int AP = 20;
    constexpr int BP = BN + 8;
    constexpr int NT = (BN / 2) / 8;   // 4
    __shared__ float sA[BM * AP];
    __shared__ float sB[BK * BP];

    int tid = threadIdx.x;
    int row0 = blockIdx.x * BM;
    int lane = tid & 31, warp = tid >> 5;
    int wr = warp >> 1, wc = warp & 1;
    int g = lane >> 2, tig = lane & 3;

    float acc[2][NT][4];
#pragma unroll
    for (int m = 0; m < 2; m++)
#pragma unroll
        for (int n = 0; n < NT; n++)
#pragma unroll
            for (int i = 0; i < 4; i++) acc[m][n][i] = 0.f;

    for (int kk = 0; kk < KTOT; kk += BK) {
        {
            int r = tid >> 1;
            int half = tid & 1;
            uint4 v = make_uint4(0, 0, 0, 0);
            if (row0 + r < M)
                v = *(const uint4*)(A + (size_t)(row0 + r) * KTOT + kk + half * 8);
            const __nv_bfloat162* p = (const __nv_bfloat162*)&v;
            float* o = sA + r * AP + half * 8;
#pragma unroll
            for (int q = 0; q < 4; q++) {
                float2 f = __bfloat1622float2(p[q]);
                o[q * 2] = f.x;
                o[q * 2 + 1] = f.y;       // bf16->f32 is tf32-exact
            }
        }
        {
            int r = tid / (BN / 4);
            int c4 = (tid % (BN / 4)) * 4;
            float4 v = *(const float4*)(B + (size_t)(kk + r) * BN + c4);
            tf32_store4(sB + r * BP + c4, v);
        }
        __syncthreads();

#pragma unroll
        for (int ks = 0; ks < 2; ks++) {
            int k0 = ks * 8;
            uint32_t a[2][4];
#pragma unroll
            for (int mt = 0; mt < 2; mt++) {
                int rb = wr * 32 + mt * 16;
                a[mt][0] = __float_as_uint(sA[(rb + g) * AP + k0 + tig]);
                a[mt][1] = __float_as_uint(sA[(rb + g + 8) * AP + k0 + tig]);
                a[mt][2] = __float_as_uint(sA[(rb + g) * AP + k0 + tig + 4]);
                a[mt][3] = __float_as_uint(sA[(rb + g + 8) * AP + k0 + tig + 4]);
            }
#pragma unroll
            for (int nt = 0; nt < NT; nt++) {
                int nc = wc * (BN / 2) + nt * 8 + g;
                uint32_t b0 = __float_as_uint(sB[(k0 + tig) * BP + nc]);
                uint32_t b1 = __float_as_uint(sB[(k0 + tig + 4) * BP + nc]);
#pragma unroll
                for (int mt = 0; mt < 2; mt++)
                    mma_tf32(acc[mt][nt], a[mt], b0, b1);
            }
        }
        __syncthreads();
    }

#pragma unroll
    for (int mt = 0; mt < 2; mt++) {
        int r1 = row0 + wr * 32 + mt * 16 + g;
        int r2 = r1 + 8;
        float d1 = (r1 < M) ? __ldg(&dis[r1]) : 0.f;
        float d2 = (r2 < M) ? __ldg(&dis[r2]) : 0.f;
#pragma unroll
        for (int nt = 0; nt < NT; nt++) {
            int cc = wc * (BN / 2) + nt * 8 + 2 * tig;
            if (r1 < M)
                *(__nv_bfloat162*)(Cb + (size_t)r1 * BN + cc) =
                    __float22bfloat162_rn(make_float2(acc[mt][nt][0] * d1,
                                                      acc[mt][nt][1] * d1));
            if (r2 < M)
                *(__nv_bfloat162*)(Cb + (size_t)r2 * BN + cc) =
                    __float22bfloat162_rn(make_float2(acc[mt][nt][2] * d2,
                                                      acc[mt][nt][3] * d2));
        }
    }
}

// ---------------- fused gather helpers ---------------------------------------
__device__ __forceinline__ void accum8(float* a, uint4 v) {
    float2 f;
    f = __bfloat1622float2(*reinterpret_cast<__nv_bfloat162*>(&v.x));
    a[0] += f.x; a[1] += f.y;
    f = __bfloat1622float2(*reinterpret_cast<__nv_bfloat162*>(&v.y));
    a[2] += f.x; a[3] += f.y;
    f = __bfloat1622float2(*reinterpret_cast<__nv_bfloat162*>(&v.z));
    a[4] += f.x; a[5] += f.y;
    f = __bfloat1622float2(*reinterpret_cast<__nv_bfloat162*>(&v.w));
    a[6] += f.x; a[7] += f.y;
}

__device__ __forceinline__ void accum4(float* a, uint2 v) {
    float2 f;
    f = __bfloat1622float2(*reinterpret_cast<__nv_bfloat162*>(&v.x));
    a[0] += f.x; a[1] += f.y;
    f = __bfloat1622float2(*reinterpret_cast<__nv_bfloat162*>(&v.y));
    a[2] += f.x; a[3] += f.y;
}

// K=128: half-warp per edge row (16 lanes x uint4 = 256 B), 8 edges/iter.
__global__ void __launch_bounds__(256)
k_gather128s(const __nv_bfloat16* __restrict__ hb, const float* __restrict__ dis,
             const int* __restrict__ deg, const int* __restrict__ rowptr,
             const int* __restrict__ csr, const float* __restrict__ bias,
             __nv_bfloat16* __restrict__ out) {
    int warp = (blockIdx.x * blockDim.x + threadIdx.x) >> 5;
    int lane = threadIdx.x & 31;
    int h = lane >> 4;
    int l = lane & 15;
    int nwarps = (gridDim.x * blockDim.x) >> 5;
    for (int node = warp; node < NN; node += nwarps) {
        int beg = rowptr[node];
        int cnt = deg[node];
        float acc[8] = {0.f, 0.f, 0.f, 0.f, 0.f, 0.f, 0.f, 0.f};
        int off = beg + h;
        int e = 0;
        for (; e + 7 < cnt; e += 8) {
            int s0 = __ldg(csr + off + e);
            int s1 = __ldg(csr + off + e + 2);
            int s2 = __ldg(csr + off + e + 4);
            int s3 = __ldg(csr + off + e + 6);
            uint4 v0 = *(const uint4*)(hb + (size_t)s0 * 128 + l * 8);
            uint4 v1 = *(const uint4*)(hb + (size_t)s1 * 128 + l * 8);
            uint4 v2 = *(const uint4*)(hb + (size_t)s2 * 128 + l * 8);
            uint4 v3 = *(const uint4*)(hb + (size_t)s3 * 128 + l * 8);
            accum8(acc, v0); accum8(acc, v1); accum8(acc, v2); accum8(acc, v3);
        }
        for (; e < cnt; e += 2) {
            int idx = e + h;
            if (idx < cnt) {
                int s = __ldg(csr + beg + idx);
                uint4 v = *(const uint4*)(hb + (size_t)s * 128 + l * 8);
                accum8(acc, v);
            }
        }
        if (h == 0) {
            uint4 v = *(const uint4*)(hb + (size_t)node * 128 + l * 8);
            accum8(acc, v);
        }
#pragma unroll
        for (int i = 0; i < 8; i++)
            acc[i] += __shfl_xor_sync(0xffffffffu, acc[i], 16);
        if (h == 0) {
            float dn = dis[node];
            float4 b0 = *(const float4*)(bias + l * 8);
            float4 b1 = *(const float4*)(bias + l * 8 + 4);
            float r0 = fmaxf(acc[0] * dn + b0.x, 0.f);
            float r1 = fmaxf(acc[1] * dn + b0.y, 0.f);
            float r2 = fmaxf(acc[2] * dn + b0.z, 0.f);
            float r3 = fmaxf(acc[3] * dn + b0.w, 0.f);
            float r4 = fmaxf(acc[4] * dn + b1.x, 0.f);
            float r5 = fmaxf(acc[5] * dn + b1.y, 0.f);
            float r6 = fmaxf(acc[6] * dn + b1.z, 0.f);
            float r7 = fmaxf(acc[7] * dn + b1.w, 0.f);
            uint4 o;
            *reinterpret_cast<__nv_bfloat162*>(&o.x) =
                __float22bfloat162_rn(make_float2(r0, r1));
            *reinterpret_cast<__nv_bfloat162*>(&o.y) =
                __float22bfloat162_rn(make_float2(r2, r3));
            *reinterpret_cast<__nv_bfloat162*>(&o.z) =
                __float22bfloat162_rn(make_float2(r4, r5));
            *reinterpret_cast<__nv_bfloat162*>(&o.w) =
                __float22bfloat162_rn(make_float2(r6, r7));
            *(uint4*)(out + (size_t)node * 128 + l * 8) = o;
        }
    }
}

// K=64: half-warp per edge row (16 lanes x uint2 = 128 B), 8 edges/iter.
__global__ void __launch_bounds__(256)
k_gather64s(const __nv_bfloat16* __restrict__ hb, const float* __restrict__ dis,
            const int* __restrict__ deg, const int* __restrict__ rowptr,
            const int* __restrict__ csr, const float* __restrict__ bias,
            __nv_bfloat16* __restrict__ out) {
    int warp = (blockIdx.x * blockDim.x + threadIdx.x) >> 5;
    int lane = threadIdx.x & 31;
    int h = lane >> 4;
    int l = lane & 15;
    int nwarps = (gridDim.x * blockDim.x) >> 5;
    for (int node = warp; node < NN; node += nwarps) {
        int beg = rowptr[node];
        int cnt = deg[node];
        float acc[4] = {0.f, 0.f, 0.f, 0.f};
        int off = beg + h;
        int e = 0;
        for (; e + 7 < cnt; e += 8) {
            int s0 = __ldg(csr + off + e);
            int s1 = __ldg(csr + off + e + 2);
            int s2 = __ldg(csr + off + e + 4);
            int s3 = __ldg(csr + off + e + 6);
            uint2 v0 = *(const uint2*)(hb + (size_t)s0 * 64 + l * 4);
            uint2 v1 = *(const uint2*)(hb + (size_t)s1 * 64 + l * 4);
            uint2 v2 = *(const uint2*)(hb + (size_t)s2 * 64 + l * 4);
            uint2 v3 = *(const uint2*)(hb + (size_t)s3 * 64 + l * 4);
            accum4(acc, v0); accum4(acc, v1); accum4(acc, v2); accum4(acc, v3);
        }
        for (; e < cnt; e += 2) {
            int idx = e + h;
            if (idx < cnt) {
                int s = __ldg(csr + beg + idx);
                uint2 v = *(const uint2*)(hb + (size_t)s * 64 + l * 4);
                accum4(acc, v);
            }
        }
        if (h == 0) {
            uint2 v = *(const uint2*)(hb + (size_t)node * 64 + l * 4);
            accum4(acc, v);
        }
#pragma unroll
        for (int i = 0; i < 4; i++)
            acc[i] += __shfl_xor_sync(0xffffffffu, acc[i], 16);
        if (h == 0) {
            float dn = dis[node];
            float4 bv = *(const float4*)(bias + l * 4);
            float r0 = fmaxf(acc[0] * dn + bv.x, 0.f);
            float r1 = fmaxf(acc[1] * dn + bv.y, 0.f);
            float r2 = fmaxf(acc[2] * dn + bv.z, 0.f);
            float r3 = fmaxf(acc[3] * dn + bv.w, 0.f);
            uint2 o;
            *reinterpret_cast<__nv_bfloat162*>(&o.x) =
                __float22bfloat162_rn(make_float2(r0, r1));
            *reinterpret_cast<__nv_bfloat162*>(&o.y) =
                __float22bfloat162_rn(make_float2(r2, r3));
            *(uint2*)(out + (size_t)node * 64 + l * 4) = o;
        }
    }
}

// ---------------- counts via binary search (batch sorted, no atomics) --------
__global__ void k_count_bs(const int* __restrict__ batch, float* __restrict__ gcnt) {
    int g = threadIdx.x;                  // 64 threads
    if (g >= NG) return;
    int lo = 0, hi = NN;
    while (lo < hi) { int m = (lo + hi) >> 1; if (batch[m] < g) lo = m + 1; else hi = m; }
    int start = lo;
    lo = 0; hi = NN;
    while (lo < hi) { int m = (lo + hi) >> 1; if (batch[m] < g + 1) lo = m + 1; else hi = m; }
    gcnt[g] = (float)(lo - start);
}

// ---------------- pooling (64-wide, bf16 in, bf162 loads) --------------------
__global__ void k_pool64(const __nv_bfloat16* __restrict__ h2,
                         const int* __restrict__ batch, float* __restrict__ gsum) {
    constexpr int RB = 256;
    __shared__ float sm[4][64];
    __shared__ int s_gmin, s_ngr;
    int base = blockIdx.x * RB;
    int nrows = NN - base; if (nrows > RB) nrows = RB;
    int tid = threadIdx.x;
    if (tid == 0) {
        int gmin = batch[base];
        int gmax = batch[base + nrows - 1];
        s_gmin = gmin; s_ngr = gmax - gmin + 1;
    }
    for (int i = tid; i < 4 * 64; i += 256) ((float*)sm)[i] = 0.f;
    __syncthreads();
    int gmin = s_gmin, ngr = s_ngr;
    int c2 = (tid & 31) * 2;          // column pair
    int strip = tid >> 5;             // 8 row strips
    if (ngr <= 4) {
        int curg = -1; float a0 = 0.f, a1 = 0.f;
        for (int r = strip; r < nrows; r += 8) {
            int node = base + r;
            int g = batch[node];
            uint32_t p = *(const uint32_t*)(h2 + (size_t)node * 64 + c2);
            float2 f = __bfloat1622float2(*reinterpret_cast<__nv_bfloat162*>(&p));
            if (g != curg) {
                if (curg >= 0) {
                    atomicAdd(&sm[curg - gmin][c2], a0);
                    atomicAdd(&sm[curg - gmin][c2 + 1], a1);
                }
                curg = g; a0 = f.x; a1 = f.y;
            } else { a0 += f.x; a1 += f.y; }
        }
        if (curg >= 0) {
            atomicAdd(&sm[curg - gmin][c2], a0);
            atomicAdd(&sm[curg - gmin][c2 + 1], a1);
        }
        __syncthreads();
        if (tid < 64)
            for (int s = 0; s < ngr; s++) {
                float v = sm[s][tid];
                if (v != 0.f) atomicAdd(&gsum[(size_t)(gmin + s) * 64 + tid], v);
            }
    } else {
        for (int r = strip; r < nrows; r += 8) {
            int node = base + r;
            uint32_t p = *(const uint32_t*)(h2 + (size_t)node * 64 + c2);
            float2 f = __bfloat1622float2(*reinterpret_cast<__nv_bfloat162*>(&p));
            int g = batch[node];
            atomicAdd(&gsum[(size_t)g * 64 + c2], f.x);
            atomicAdd(&gsum[(size_t)g * 64 + c2 + 1], f.y);
        }
    }
}

// ---------------- final: ge = (gsum/cnt)@Wf1+bf1 ; ic = ge@Wf2+bf2 ----------
__global__ void k_final2(const float* __restrict__ gsum, const float* __restrict__ gcnt,
                         const float* __restrict__ Wf1, const float* __restrict__ bf1,
                         const float* __restrict__ Wf2, const float* __restrict__ bf2,
                         float* __restrict__ out) {
    __shared__ float ge[NG * DENSE];
    int tid = threadIdx.x;                     // 256
    for (int idx = tid; idx < NG * DENSE; idx += 256) {
        int gg = idx >> 7, j = idx & 127;
        float inv = 1.0f / fmaxf(gcnt[gg], 1.0f);
        const float* pg = gsum + gg * 64;
        float a = 0.f;
#pragma unroll 8
        for (int c = 0; c < 64; c++)
            a += pg[c] * Wf1[c * DENSE + j];
        float v = a * inv + bf1[j];
        ge[idx] = v;
        out[idx] = v;
    }
    __syncthreads();
    if (tid < NG * LABELS) {
        int gg = tid >> 1, l = tid & 1;
        float s = bf2[l];
#pragma unroll 8
        for (int c = 0; c < DENSE; c++)
            s += ge[gg * DENSE + c] * Wf2[c * LABELS + l];
        out[NG * DENSE + 1 + tid] = s;
    }
    if (tid == 0) out[NG * DENSE] = 0.f;
}

// ---------------- launch ----------------------------------------------------
extern "C" void kernel_launch(void* const* d_in, const int* in_sizes, int n_in,
                              void* d_out, int out_size) {
    const float* x   = (const float*)d_in[0];
    const float* W1  = (const float*)d_in[1];
    const float* b1  = (const float*)d_in[2];
    const float* W2  = (const float*)d_in[3];
    const float* b2  = (const float*)d_in[4];
    const float* Wf1 = (const float*)d_in[5];
    const float* bf1 = (const float*)d_in[6];
    const float* Wf2 = (const float*)d_in[7];
    const float* bf2 = (const float*)d_in[8];
    const int* ei    = (const int*)d_in[9];
    const int* batch = (const int*)d_in[10];
    const int* src = ei;
    const int* dst = ei + EE;
    float* out = (float*)d_out;

    float *dis, *gsum, *gcnt;
    __nv_bfloat16 *hb, *h1, *h2;
    int *deg, *rowptr, *nextptr, *partials, *csr;
    cudaGetSymbolAddress((void**)&dis,  g_dis);
    cudaGetSymbolAddress((void**)&deg,  g_deg);
    cudaGetSymbolAddress((void**)&rowptr, g_rowptr);
    cudaGetSymbolAddress((void**)&nextptr, g_nextptr);
    cudaGetSymbolAddress((void**)&partials, g_partials);
    cudaGetSymbolAddress((void**)&csr,  g_csr);
    cudaGetSymbolAddress((void**)&hb,   g_hb);
    cudaGetSymbolAddress((void**)&h1,   g_h1);
    cudaGetSymbolAddress((void**)&h2,   g_h2);
    cudaGetSymbolAddress((void**)&gsum, g_gsum);
    cudaGetSymbolAddress((void**)&gcnt, g_gcnt);

    // side streams + events (created once, on the uncaptured correctness call)
    static cudaStream_t s1 = nullptr, s2 = nullptr;
    static cudaEvent_t e_root = nullptr, e_dis = nullptr,
                       e_g1 = nullptr, e_pool = nullptr;
    if (!s1) {
        cudaStreamCreateWithFlags(&s1, cudaStreamNonBlocking);
        cudaStreamCreateWithFlags(&s2, cudaStreamNonBlocking);
        cudaEventCreateWithFlags(&e_root, cudaEventDisableTiming);
        cudaEventCreateWithFlags(&e_dis,  cudaEventDisableTiming);
        cudaEventCreateWithFlags(&e_g1,   cudaEventDisableTiming);
        cudaEventCreateWithFlags(&e_pool, cudaEventDisableTiming);
    }

    const int TB = 256;
    const int nblkN = (NN + TB - 1) / TB;
    const int ew_grid = 148 * 16;
    const int gemm_blocks = (NN + 127) / 128;
    const int gather_blocks = (NN * 32 + TB - 1) / TB;

    // fork point for s2 (pool setup depends only on inputs)
    k_zero_deg<<<nblkN, TB>>>(deg);
    cudaEventRecord(e_root, 0);
    cudaStreamWaitEvent(s2, e_root, 0);
    cudaMemsetAsync(gsum, 0, NG * 64 * sizeof(float), s2);
    k_count_bs<<<1, 64, 0, s2>>>(batch, gcnt);
    cudaEventRecord(e_pool, s2);

    // ---- degree + scan (scan_block also emits dis); gemm1 forks after it
    k_deg_count<<<ew_grid, TB>>>(dst, deg);
    k_scan_block<<<NB_SCAN, SCAN_BLK>>>(deg, rowptr, partials, dis);
    cudaEventRecord(e_dis, 0);
    cudaStreamWaitEvent(s1, e_dis, 0);
    k_gemm_tc<128><<<gemm_blocks, 256, 0, s1>>>(x, W1, dis, hb, NN);   // s1
    cudaEventRecord(e_g1, s1);

    // ---- finish scan + fill on default stream, overlapping gemm1
    k_scan_finish<<<nblkN, TB>>>(rowptr, partials, nextptr);
    k_fill<<<ew_grid, TB>>>(src, dst, nextptr, csr);

    // join gemm1, then layer-1 gather (h1 bf16)
    cudaStreamWaitEvent(0, e_g1, 0);
    k_gather128s<<<gather_blocks, TB>>>(hb, dis, deg, rowptr, csr, b1, h1);

    // ---- layer 2: bf16-A gemm, then gather (h2 bf16)
    k_gemm_tc_h<<<gemm_blocks, 256>>>(h1, W2, dis, hb, NN);
    k_gather64s<<<gather_blocks, TB>>>(hb, dis, deg, rowptr, csr, b2, h2);

    // ---- pooling (Wf1 folded) + head
    cudaStreamWaitEvent(0, e_pool, 0);   // join s2
    k_pool64<<<(NN + 255) / 256, 256>>>(h2, batch, gsum);
    k_final2<<<1, 256>>>(gsum, gcnt, Wf1, bf1, Wf2, bf2, out);
}

// round 15
// speedup vs baseline: 1.1587x; 1.0411x over previous
#include <cuda_runtime.h>
#include <cuda_bf16.h>
#include <cstdint>

// Problem constants (fixed by the dataset)
#define NN 100000
#define EE 3200000
#define NG 64
#define F_IN 128
#define H1 128
#define H2 64
#define DENSE 128
#define LABELS 2

#define SCAN_BLK 512
#define NB_SCAN ((NN + SCAN_BLK - 1) / SCAN_BLK)   // 196

// PDL entry sync: wait for upstream grid's memory before touching its outputs
__device__ __forceinline__ void gds() {
#if defined(__CUDA_ARCH__) && (__CUDA_ARCH__ >= 900)
    cudaGridDependencySynchronize();
#endif
}

// ---------------- scratch (__device__ globals; no runtime allocation) -------
__device__ float g_dis[NN];
__device__ int   g_deg[NN];
__device__ int   g_rowptr[NN];
__device__ int   g_nextptr[NN];
__device__ int   g_partials[256];
__device__ int   g_csr[EE];                        // src per CSR slot
__device__ __nv_bfloat16 g_hb[(size_t)NN * 128];   // gemm outputs, pre-scaled by dis
__device__ __nv_bfloat16 g_h1[(size_t)NN * 128];   // relu(layer1), bf16
__device__ __nv_bfloat16 g_h2[(size_t)NN * 64];    // relu(layer2), bf16
__device__ float g_gsum[NG * 64];
__device__ float g_gcnt[NG];

// ---------------- CSR build --------------------------------------------------
__global__ void k_zero_deg(int* deg) {
    int i = blockIdx.x * blockDim.x + threadIdx.x;
    if (i < NN) deg[i] = 0;
}

__global__ void k_deg_count(const int* __restrict__ dst, int* __restrict__ deg) {
    gds();
    int i = blockIdx.x * blockDim.x + threadIdx.x;
    int stride = gridDim.x * blockDim.x;
    const int4* d4 = (const int4*)dst;
    for (; i < EE / 4; i += stride) {
        int4 v = __ldg(&d4[i]);
        atomicAdd(&deg[v.x], 1);
        atomicAdd(&deg[v.y], 1);
        atomicAdd(&deg[v.z], 1);
        atomicAdd(&deg[v.w], 1);
    }
}

// block-local scan of deg -> rowptr + per-block totals; also emits dis
__global__ void k_scan_block(const int* __restrict__ deg, int* __restrict__ rowptr,
                             int* __restrict__ partials, float* __restrict__ dis) {
    gds();
    __shared__ int s[SCAN_BLK];
    int tid = threadIdx.x;
    int i = blockIdx.x * SCAN_BLK + tid;
    int v = (i < NN) ? deg[i] : 0;
    s[tid] = v;
    __syncthreads();
#pragma unroll
    for (int off = 1; off < SCAN_BLK; off <<= 1) {
        int t = (tid >= off) ? s[tid - off] : 0;
        __syncthreads();
        s[tid] += t;
        __syncthreads();
    }
    if (i < NN) {
        rowptr[i] = s[tid] - v;           // block-local exclusive
        dis[i] = rsqrtf(1.0f + (float)v);
    }
    if (tid == SCAN_BLK - 1) partials[blockIdx.x] = s[tid];
}

// fused: scan the 196 partials (redundantly per block) + finalize rowptr/nextptr
__global__ void k_scan_finish(int* __restrict__ rowptr, const int* __restrict__ partials,
                              int* __restrict__ nextptr) {
    gds();
    __shared__ int s[256];
    int tid = threadIdx.x;
    int v = (tid < NB_SCAN) ? partials[tid] : 0;
    s[tid] = v;
    __syncthreads();
#pragma unroll
    for (int off = 1; off < 256; off <<= 1) {
        int t = (tid >= off) ? s[tid - off] : 0;
        __syncthreads();
        s[tid] += t;
        __syncthreads();
    }
    int ex = s[tid] - v;                           // exclusive
    __syncthreads();
    s[tid] = ex;
    __syncthreads();
    int i = blockIdx.x * 256 + tid;
    if (i < NN) {
        int r = rowptr[i] + s[i / SCAN_BLK];
        rowptr[i] = r;
        nextptr[i] = r;
    }
}

__global__ void k_fill(const int* __restrict__ src, const int* __restrict__ dst,
                       int* __restrict__ nextptr, int* __restrict__ csr) {
    gds();
    int i = blockIdx.x * blockDim.x + threadIdx.x;
    int stride = gridDim.x * blockDim.x;
    for (; i < EE; i += stride) {
        int d = dst[i];
        int s = src[i];
        int pos = atomicAdd(&nextptr[d], 1);
        csr[pos] = s;
    }
}

// ---------------- tf32 helpers ----------------------------------------------
__device__ __forceinline__ uint32_t f2tf32(float f) {
    uint32_t r;
    asm("cvt.rna.tf32.f32 %0, %1;" : "=r"(r) : "f"(f));
    return r;
}

__device__ __forceinline__ void tf32_store4(float* p, float4 v) {
    uint32_t hx = f2tf32(v.x), hy = f2tf32(v.y), hz = f2tf32(v.z), hw = f2tf32(v.w);
    *(float4*)p = make_float4(__uint_as_float(hx), __uint_as_float(hy),
                              __uint_as_float(hz), __uint_as_float(hw));
}

__device__ __forceinline__ void mma_tf32(float d[4], const uint32_t a[4],
                                         uint32_t b0, uint32_t b1) {
    asm volatile(
        "mma.sync.aligned.m16n8k8.row.col.f32.tf32.tf32.f32 "
        "{%0,%1,%2,%3},{%4,%5,%6,%7},{%8,%9},{%0,%1,%2,%3};"
        : "+f"(d[0]), "+f"(d[1]), "+f"(d[2]), "+f"(d[3])
        : "r"(a[0]), "r"(a[1]), "r"(a[2]), "r"(a[3]), "r"(b0), "r"(b1));
}

// ---------------- tf32 GEMM (fp32 A): Cb = bf16((A @ B) * dis[m]) -----------
template<int BN>
__global__ void __launch_bounds__(256)
k_gemm_tc(const float* __restrict__ A, const float* __restrict__ B,
          const float* __restrict__ dis, __nv_bfloat16* __restrict__ Cb, int M) {
    constexpr int BM = 128, BK = 16, KTOT = 128;
    constexpr int AP = 20;
    constexpr int BP = BN + 8;
    constexpr int NT = (BN / 2) / 8;
    __shared__ float sA[BM * AP];
    __shared__ float sB[BK * BP];

    int tid = threadIdx.x;
    int row0 = blockIdx.x * BM;
    int lane = tid & 31, warp = tid >> 5;
    int wr = warp >> 1, wc = warp & 1;
    int g = lane >> 2, tig = lane & 3;

    float acc[2][NT][4];
#pragma unroll
    for (int m = 0; m < 2; m++)
#pragma unroll
        for (int n = 0; n < NT; n++)
#pragma unroll
            for (int i = 0; i < 4; i++) acc[m][n][i] = 0.f;

    for (int kk = 0; kk < KTOT; kk += BK) {
#pragma unroll
        for (int i = 0; i < 2; i++) {
            int j = tid + 256 * i;
            int r = j >> 2;
            int c4 = (j & 3) * 4;
            float4 v = make_float4(0.f, 0.f, 0.f, 0.f);
            if (row0 + r < M)
                v = *(const float4*)(A + (size_t)(row0 + r) * KTOT + kk + c4);
            tf32_store4(sA + r * AP + c4, v);
        }
#pragma unroll
        for (int i = 0; i < BN / 64; i++) {
            int j = tid + 256 * i;
            int r = j / (BN / 4);
            int c4 = (j % (BN / 4)) * 4;
            float4 v = *(const float4*)(B + (size_t)(kk + r) * BN + c4);
            tf32_store4(sB + r * BP + c4, v);
        }
        __syncthreads();

#pragma unroll
        for (int ks = 0; ks < 2; ks++) {
            int k0 = ks * 8;
            uint32_t a[2][4];
#pragma unroll
            for (int mt = 0; mt < 2; mt++) {
                int rb = wr * 32 + mt * 16;
                a[mt][0] = __float_as_uint(sA[(rb + g) * AP + k0 + tig]);
                a[mt][1] = __float_as_uint(sA[(rb + g + 8) * AP + k0 + tig]);
                a[mt][2] = __float_as_uint(sA[(rb + g) * AP + k0 + tig + 4]);
                a[mt][3] = __float_as_uint(sA[(rb + g + 8) * AP + k0 + tig + 4]);
            }
#pragma unroll
            for (int nt = 0; nt < NT; nt++) {
                int nc = wc * (BN / 2) + nt * 8 + g;
                uint32_t b0 = __float_as_uint(sB[(k0 + tig) * BP + nc]);
                uint32_t b1 = __float_as_uint(sB[(k0 + tig + 4) * BP + nc]);
#pragma unroll
                for (int mt = 0; mt < 2; mt++)
                    mma_tf32(acc[mt][nt], a[mt], b0, b1);
            }
        }
        __syncthreads();
    }

#pragma unroll
    for (int mt = 0; mt < 2; mt++) {
        int r1 = row0 + wr * 32 + mt * 16 + g;
        int r2 = r1 + 8;
        float d1 = (r1 < M) ? __ldg(&dis[r1]) : 0.f;
        float d2 = (r2 < M) ? __ldg(&dis[r2]) : 0.f;
#pragma unroll
        for (int nt = 0; nt < NT; nt++) {
            int cc = wc * (BN / 2) + nt * 8 + 2 * tig;
            if (r1 < M)
                *(__nv_bfloat162*)(Cb + (size_t)r1 * BN + cc) =
                    __float22bfloat162_rn(make_float2(acc[mt][nt][0] * d1,
                                                      acc[mt][nt][1] * d1));
            if (r2 < M)
                *(__nv_bfloat162*)(Cb + (size_t)r2 * BN + cc) =
                    __float22bfloat162_rn(make_float2(acc[mt][nt][2] * d2,
                                                      acc[mt][nt][3] * d2));
        }
    }
}

// ---------------- tf32 GEMM (bf16 A, BN=64): Cb = bf16((A @ B) * dis[m]) ----
__global__ void __launch_bounds__(256)
k_gemm_tc_h(const __nv_bfloat16* __restrict__ A, const float* __restrict__ B,
            const float* __restrict__ dis, __nv_bfloat16* __restrict__ Cb, int M) {
    gds();
    constexpr int BM = 128, BK = 16, KTOT = 128, BN = 64;
    constexpr int AP = 20;
    constexpr int BP = BN + 8;
    constexpr int NT = (BN / 2) / 8;   // 4
    __shared__ float sA[BM * AP];
    __shared__ float sB[BK * BP];

    int tid = threadIdx.x;
    int row0 = blockIdx.x * BM;
    int lane = tid & 31, warp = tid >> 5;
    int wr = warp >> 1, wc = warp & 1;
    int g = lane >> 2, tig = lane & 3;

    float acc[2][NT][4];
#pragma unroll
    for (int m = 0; m < 2; m++)
#pragma unroll
        for (int n = 0; n < NT; n++)
#pragma unroll
            for (int i = 0; i < 4; i++) acc[m][n][i] = 0.f;

    for (int kk = 0; kk < KTOT; kk += BK) {
        {
            int r = tid >> 1;
            int half = tid & 1;
            uint4 v = make_uint4(0, 0, 0, 0);
            if (row0 + r < M)
                v = *(const uint4*)(A + (size_t)(row0 + r) * KTOT + kk + half * 8);
            const __nv_bfloat162* p = (const __nv_bfloat162*)&v;
            float* o = sA + r * AP + half * 8;
#pragma unroll
            for (int q = 0; q < 4; q++) {
                float2 f = __bfloat1622float2(p[q]);
                o[q * 2] = f.x;
                o[q * 2 + 1] = f.y;       // bf16->f32 is tf32-exact
            }
        }
        {
            int r = tid / (BN / 4);
            int c4 = (tid % (BN / 4)) * 4;
            float4 v = *(const float4*)(B + (size_t)(kk + r) * BN + c4);
            tf32_store4(sB + r * BP + c4, v);
        }
        __syncthreads();

#pragma unroll
        for (int ks = 0; ks < 2; ks++) {
            int k0 = ks * 8;
            uint32_t a[2][4];
#pragma unroll
            for (int mt = 0; mt < 2; mt++) {
                int rb = wr * 32 + mt * 16;
                a[mt][0] = __float_as_uint(sA[(rb + g) * AP + k0 + tig]);
                a[mt][1] = __float_as_uint(sA[(rb + g + 8) * AP + k0 + tig]);
                a[mt][2] = __float_as_uint(sA[(rb + g) * AP + k0 + tig + 4]);
                a[mt][3] = __float_as_uint(sA[(rb + g + 8) * AP + k0 + tig + 4]);
            }
#pragma unroll
            for (int nt = 0; nt < NT; nt++) {
                int nc = wc * (BN / 2) + nt * 8 + g;
                uint32_t b0 = __float_as_uint(sB[(k0 + tig) * BP + nc]);
                uint32_t b1 = __float_as_uint(sB[(k0 + tig + 4) * BP + nc]);
#pragma unroll
                for (int mt = 0; mt < 2; mt++)
                    mma_tf32(acc[mt][nt], a[mt], b0, b1);
            }
        }
        __syncthreads();
    }

#pragma unroll
    for (int mt = 0; mt < 2; mt++) {
        int r1 = row0 + wr * 32 + mt * 16 + g;
        int r2 = r1 + 8;
        float d1 = (r1 < M) ? __ldg(&dis[r1]) : 0.f;
        float d2 = (r2 < M) ? __ldg(&dis[r2]) : 0.f;
#pragma unroll
        for (int nt = 0; nt < NT; nt++) {
            int cc = wc * (BN / 2) + nt * 8 + 2 * tig;
            if (r1 < M)
                *(__nv_bfloat162*)(Cb + (size_t)r1 * BN + cc) =
                    __float22bfloat162_rn(make_float2(acc[mt][nt][0] * d1,
                                                      acc[mt][nt][1] * d1));
            if (r2 < M)
                *(__nv_bfloat162*)(Cb + (size_t)r2 * BN + cc) =
                    __float22bfloat162_rn(make_float2(acc[mt][nt][2] * d2,
                                                      acc[mt][nt][3] * d2));
        }
    }
}

// ---------------- fused gather helpers ---------------------------------------
__device__ __forceinline__ void accum8(float* a, uint4 v) {
    float2 f;
    f = __bfloat1622float2(*reinterpret_cast<__nv_bfloat162*>(&v.x));
    a[0] += f.x; a[1] += f.y;
    f = __bfloat1622float2(*reinterpret_cast<__nv_bfloat162*>(&v.y));
    a[2] += f.x; a[3] += f.y;
    f = __bfloat1622float2(*reinterpret_cast<__nv_bfloat162*>(&v.z));
    a[4] += f.x; a[5] += f.y;
    f = __bfloat1622float2(*reinterpret_cast<__nv_bfloat162*>(&v.w));
    a[6] += f.x; a[7] += f.y;
}

__device__ __forceinline__ void accum4(float* a, uint2 v) {
    float2 f;
    f = __bfloat1622float2(*reinterpret_cast<__nv_bfloat162*>(&v.x));
    a[0] += f.x; a[1] += f.y;
    f = __bfloat1622float2(*reinterpret_cast<__nv_bfloat162*>(&v.y));
    a[2] += f.x; a[3] += f.y;
}

// K=128: half-warp per edge row (16 lanes x uint4 = 256 B), 8 edges/iter.
__global__ void __launch_bounds__(256)
k_gather128s(const __nv_bfloat16* __restrict__ hb, const float* __restrict__ dis,
             const int* __restrict__ deg, const int* __restrict__ rowptr,
             const int* __restrict__ csr, const float* __restrict__ bias,
             __nv_bfloat16* __restrict__ out) {
    gds();
    int warp = (blockIdx.x * blockDim.x + threadIdx.x) >> 5;
    int lane = threadIdx.x & 31;
    int h = lane >> 4;
    int l = lane & 15;
    int nwarps = (gridDim.x * blockDim.x) >> 5;
    for (int node = warp; node < NN; node += nwarps) {
        int beg = rowptr[node];
        int cnt = deg[node];
        float acc[8] = {0.f, 0.f, 0.f, 0.f, 0.f, 0.f, 0.f, 0.f};
        int off = beg + h;
        int e = 0;
        for (; e + 7 < cnt; e += 8) {
            int s0 = __ldg(csr + off + e);
            int s1 = __ldg(csr + off + e + 2);
            int s2 = __ldg(csr + off + e + 4);
            int s3 = __ldg(csr + off + e + 6);
            uint4 v0 = *(const uint4*)(hb + (size_t)s0 * 128 + l * 8);
            uint4 v1 = *(const uint4*)(hb + (size_t)s1 * 128 + l * 8);
            uint4 v2 = *(const uint4*)(hb + (size_t)s2 * 128 + l * 8);
            uint4 v3 = *(const uint4*)(hb + (size_t)s3 * 128 + l * 8);
            accum8(acc, v0); accum8(acc, v1); accum8(acc, v2); accum8(acc, v3);
        }
        for (; e < cnt; e += 2) {
            int idx = e + h;
            if (idx < cnt) {
                int s = __ldg(csr + beg + idx);
                uint4 v = *(const uint4*)(hb + (size_t)s * 128 + l * 8);
                accum8(acc, v);
            }
        }
        if (h == 0) {
            uint4 v = *(const uint4*)(hb + (size_t)node * 128 + l * 8);
            accum8(acc, v);
        }
#pragma unroll
        for (int i = 0; i < 8; i++)
            acc[i] += __shfl_xor_sync(0xffffffffu, acc[i], 16);
        if (h == 0) {
            float dn = dis[node];
            float4 b0 = *(const float4*)(bias + l * 8);
            float4 b1 = *(const float4*)(bias + l * 8 + 4);
            float r0 = fmaxf(acc[0] * dn + b0.x, 0.f);
            float r1 = fmaxf(acc[1] * dn + b0.y, 0.f);
            float r2 = fmaxf(acc[2] * dn + b0.z, 0.f);
            float r3 = fmaxf(acc[3] * dn + b0.w, 0.f);
            float r4 = fmaxf(acc[4] * dn + b1.x, 0.f);
            float r5 = fmaxf(acc[5] * dn + b1.y, 0.f);
            float r6 = fmaxf(acc[6] * dn + b1.z, 0.f);
            float r7 = fmaxf(acc[7] * dn + b1.w, 0.f);
            uint4 o;
            *reinterpret_cast<__nv_bfloat162*>(&o.x) =
                __float22bfloat162_rn(make_float2(r0, r1));
            *reinterpret_cast<__nv_bfloat162*>(&o.y) =
                __float22bfloat162_rn(make_float2(r2, r3));
            *reinterpret_cast<__nv_bfloat162*>(&o.z) =
                __float22bfloat162_rn(make_float2(r4, r5));
            *reinterpret_cast<__nv_bfloat162*>(&o.w) =
                __float22bfloat162_rn(make_float2(r6, r7));
            *(uint4*)(out + (size_t)node * 128 + l * 8) = o;
        }
    }
}

// K=64: half-warp per edge row (16 lanes x uint2 = 128 B), 8 edges/iter.
__global__ void __launch_bounds__(256)
k_gather64s(const __nv_bfloat16* __restrict__ hb, const float* __restrict__ dis,
            const int* __restrict__ deg, const int* __restrict__ rowptr,
            const int* __restrict__ csr, const float* __restrict__ bias,
            __nv_bfloat16* __restrict__ out) {
    gds();
    int warp = (blockIdx.x * blockDim.x + threadIdx.x) >> 5;
    int lane = threadIdx.x & 31;
    int h = lane >> 4;
    int l = lane & 15;
    int nwarps = (gridDim.x * blockDim.x) >> 5;
    for (int node = warp; node < NN; node += nwarps) {
        int beg = rowptr[node];
        int cnt = deg[node];
        float acc[4] = {0.f, 0.f, 0.f, 0.f};
        int off = beg + h;
        int e = 0;
        for (; e + 7 < cnt; e += 8) {
            int s0 = __ldg(csr + off + e);
            int s1 = __ldg(csr + off + e + 2);
            int s2 = __ldg(csr + off + e + 4);
            int s3 = __ldg(csr + off + e + 6);
            uint2 v0 = *(const uint2*)(hb + (size_t)s0 * 64 + l * 4);
            uint2 v1 = *(const uint2*)(hb + (size_t)s1 * 64 + l * 4);
            uint2 v2 = *(const uint2*)(hb + (size_t)s2 * 64 + l * 4);
            uint2 v3 = *(const uint2*)(hb + (size_t)s3 * 64 + l * 4);
            accum4(acc, v0); accum4(acc, v1); accum4(acc, v2); accum4(acc, v3);
        }
        for (; e < cnt; e += 2) {
            int idx = e + h;
            if (idx < cnt) {
                int s = __ldg(csr + beg + idx);
                uint2 v = *(const uint2*)(hb + (size_t)s * 64 + l * 4);
                accum4(acc, v);
            }
        }
        if (h == 0) {
            uint2 v = *(const uint2*)(hb + (size_t)node * 64 + l * 4);
            accum4(acc, v);
        }
#pragma unroll
        for (int i = 0; i < 4; i++)
            acc[i] += __shfl_xor_sync(0xffffffffu, acc[i], 16);
        if (h == 0) {
            float dn = dis[node];
            float4 bv = *(const float4*)(bias + l * 4);
            float r0 = fmaxf(acc[0] * dn + bv.x, 0.f);
            float r1 = fmaxf(acc[1] * dn + bv.y, 0.f);
            float r2 = fmaxf(acc[2] * dn + bv.z, 0.f);
            float r3 = fmaxf(acc[3] * dn + bv.w, 0.f);
            uint2 o;
            *reinterpret_cast<__nv_bfloat162*>(&o.x) =
                __float22bfloat162_rn(make_float2(r0, r1));
            *reinterpret_cast<__nv_bfloat162*>(&o.y) =
                __float22bfloat162_rn(make_float2(r2, r3));
            *(uint2*)(out + (size_t)node * 64 + l * 4) = o;
        }
    }
}

// ---------------- counts via binary search (batch sorted, no atomics) --------
__global__ void k_count_bs(const int* __restrict__ batch, float* __restrict__ gcnt) {
    int g = threadIdx.x;                  // 64 threads
    if (g >= NG) return;
    int lo = 0, hi = NN;
    while (lo < hi) { int m = (lo + hi) >> 1; if (batch[m] < g) lo = m + 1; else hi = m; }
    int start = lo;
    lo = 0; hi = NN;
    while (lo < hi) { int m = (lo + hi) >> 1; if (batch[m] < g + 1) lo = m + 1; else hi = m; }
    gcnt[g] = (float)(lo - start);
}

// ---------------- pooling (64-wide, bf16 in, bf162 loads) --------------------
__global__ void k_pool64(const __nv_bfloat16* __restrict__ h2,
                         const int* __restrict__ batch, float* __restrict__ gsum) {
    gds();
    constexpr int RB = 256;
    __shared__ float sm[4][64];
    __shared__ int s_gmin, s_ngr;
    int base = blockIdx.x * RB;
    int nrows = NN - base; if (nrows > RB) nrows = RB;
    int tid = threadIdx.x;
    if (tid == 0) {
        int gmin = batch[base];
        int gmax = batch[base + nrows - 1];
        s_gmin = gmin; s_ngr = gmax - gmin + 1;
    }
    for (int i = tid; i < 4 * 64; i += 256) ((float*)sm)[i] = 0.f;
    __syncthreads();
    int gmin = s_gmin, ngr = s_ngr;
    int c2 = (tid & 31) * 2;          // column pair
    int strip = tid >> 5;             // 8 row strips
    if (ngr <= 4) {
        int curg = -1; float a0 = 0.f, a1 = 0.f;
        for (int r = strip; r < nrows; r += 8) {
            int node = base + r;
            int g = batch[node];
            uint32_t p = *(const uint32_t*)(h2 + (size_t)node * 64 + c2);
            float2 f = __bfloat1622float2(*reinterpret_cast<__nv_bfloat162*>(&p));
            if (g != curg) {
                if (curg >= 0) {
                    atomicAdd(&sm[curg - gmin][c2], a0);
                    atomicAdd(&sm[curg - gmin][c2 + 1], a1);
                }
                curg = g; a0 = f.x; a1 = f.y;
            } else { a0 += f.x; a1 += f.y; }
        }
        if (curg >= 0) {
            atomicAdd(&sm[curg - gmin][c2], a0);
            atomicAdd(&sm[curg - gmin][c2 + 1], a1);
        }
        __syncthreads();
        if (tid < 64)
            for (int s = 0; s < ngr; s++) {
                float v = sm[s][tid];
                if (v != 0.f) atomicAdd(&gsum[(size_t)(gmin + s) * 64 + tid], v);
            }
    } else {
        for (int r = strip; r < nrows; r += 8) {
            int node = base + r;
            uint32_t p = *(const uint32_t*)(h2 + (size_t)node * 64 + c2);
            float2 f = __bfloat1622float2(*reinterpret_cast<__nv_bfloat162*>(&p));
            int g = batch[node];
            atomicAdd(&gsum[(size_t)g * 64 + c2], f.x);
            atomicAdd(&gsum[(size_t)g * 64 + c2 + 1], f.y);
        }
    }
}

// ---------------- final: ge = (gsum/cnt)@Wf1+bf1 ; ic = ge@Wf2+bf2 ----------
__global__ void k_final2(const float* __restrict__ gsum, const float* __restrict__ gcnt,
                         const float* __restrict__ Wf1, const float* __restrict__ bf1,
                         const float* __restrict__ Wf2, const float* __restrict__ bf2,
                         float* __restrict__ out) {
    gds();
    __shared__ float ge[NG * DENSE];
    int tid = threadIdx.x;                     // 256
    for (int idx = tid; idx < NG * DENSE; idx += 256) {
        int gg = idx >> 7, j = idx & 127;
        float inv = 1.0f / fmaxf(gcnt[gg], 1.0f);
        const float* pg = gsum + gg * 64;
        float a = 0.f;
#pragma unroll 8
        for (int c = 0; c < 64; c++)
            a += pg[c] * Wf1[c * DENSE + j];
        float v = a * inv + bf1[j];
        ge[idx] = v;
        out[idx] = v;
    }
    __syncthreads();
    if (tid < NG * LABELS) {
        int gg = tid >> 1, l = tid & 1;
        float s = bf2[l];
#pragma unroll 8
        for (int c = 0; c < DENSE; c++)
            s += ge[gg * DENSE + c] * Wf2[c * LABELS + l];
        out[NG * DENSE + 1 + tid] = s;
    }
    if (tid == 0) out[NG * DENSE] = 0.f;
}

// ---------------- PDL launch helper ------------------------------------------
template<typename F, typename... Args>
static inline void launch_pdl(F* kernel, dim3 grid, dim3 block, cudaStream_t st,
                              Args... args) {
    cudaLaunchConfig_t cfg = {};
    cfg.gridDim = grid;
    cfg.blockDim = block;
    cfg.dynamicSmemBytes = 0;
    cfg.stream = st;
    cudaLaunchAttribute attr[1];
    attr[0].id = cudaLaunchAttributeProgrammaticStreamSerialization;
    attr[0].val.programmaticStreamSerializationAllowed = 1;
    cfg.attrs = attr;
    cfg.numAttrs = 1;
    cudaLaunchKernelEx(&cfg, kernel, args...);
}

// ---------------- launch ----------------------------------------------------
extern "C" void kernel_launch(void* const* d_in, const int* in_sizes, int n_in,
                              void* d_out, int out_size) {
    const float* x   = (const float*)d_in[0];
    const float* W1  = (const float*)d_in[1];
    const float* b1  = (const float*)d_in[2];
    const float* W2  = (const float*)d_in[3];
    const float* b2  = (const float*)d_in[4];
    const float* Wf1 = (const float*)d_in[5];
    const float* bf1 = (const float*)d_in[6];
    const float* Wf2 = (const float*)d_in[7];
    const float* bf2 = (const float*)d_in[8];
    const int* ei    = (const int*)d_in[9];
    const int* batch = (const int*)d_in[10];
    const int* src = ei;
    const int* dst = ei + EE;
    float* out = (float*)d_out;

    float *dis, *gsum, *gcnt;
    __nv_bfloat16 *hb, *h1, *h2;
    int *deg, *rowptr, *nextptr, *partials, *csr;
    cudaGetSymbolAddress((void**)&dis,  g_dis);
    cudaGetSymbolAddress((void**)&deg,  g_deg);
    cudaGetSymbolAddress((void**)&rowptr, g_rowptr);
    cudaGetSymbolAddress((void**)&nextptr, g_nextptr);
    cudaGetSymbolAddress((void**)&partials, g_partials);
    cudaGetSymbolAddress((void**)&csr,  g_csr);
    cudaGetSymbolAddress((void**)&hb,   g_hb);
    cudaGetSymbolAddress((void**)&h1,   g_h1);
    cudaGetSymbolAddress((void**)&h2,   g_h2);
    cudaGetSymbolAddress((void**)&gsum, g_gsum);
    cudaGetSymbolAddress((void**)&gcnt, g_gcnt);

    // side streams + events (created once, on the uncaptured correctness call)
    static cudaStream_t s1 = nullptr, s2 = nullptr;
    static cudaEvent_t e_root = nullptr, e_dis = nullptr,
                       e_g1 = nullptr, e_pool = nullptr;
    if (!s1) {
        cudaStreamCreateWithFlags(&s1, cudaStreamNonBlocking);
        cudaStreamCreateWithFlags(&s2, cudaStreamNonBlocking);
        cudaEventCreateWithFlags(&e_root, cudaEventDisableTiming);
        cudaEventCreateWithFlags(&e_dis,  cudaEventDisableTiming);
        cudaEventCreateWithFlags(&e_g1,   cudaEventDisableTiming);
        cudaEventCreateWithFlags(&e_pool, cudaEventDisableTiming);
    }

    const int TB = 256;
    const int nblkN = (NN + TB - 1) / TB;
    const int ew_grid = 148 * 16;
    const int gemm_blocks = (NN + 127) / 128;
    const int gather_blocks = (NN * 32 + TB - 1) / TB;

    // fork point for s2 (pool setup depends only on inputs)
    k_zero_deg<<<nblkN, TB>>>(deg);
    cudaEventRecord(e_root, 0);
    cudaStreamWaitEvent(s2, e_root, 0);
    cudaMemsetAsync(gsum, 0, NG * 64 * sizeof(float), s2);
    k_count_bs<<<1, 64, 0, s2>>>(batch, gcnt);
    cudaEventRecord(e_pool, s2);

    // ---- degree + scan (scan_block also emits dis); gemm1 forks after it
    launch_pdl(k_deg_count, dim3(ew_grid), dim3(TB), (cudaStream_t)0, dst, deg);
    launch_pdl(k_scan_block, dim3(NB_SCAN), dim3(SCAN_BLK), (cudaStream_t)0,
               deg, rowptr, partials, dis);
    cudaEventRecord(e_dis, 0);
    cudaStreamWaitEvent(s1, e_dis, 0);
    k_gemm_tc<128><<<gemm_blocks, 256, 0, s1>>>(x, W1, dis, hb, NN);   // s1
    cudaEventRecord(e_g1, s1);

    // ---- finish scan + fill on default stream, overlapping gemm1
    launch_pdl(k_scan_finish, dim3(nblkN), dim3(TB), (cudaStream_t)0,
               rowptr, (const int*)partials, nextptr);
    launch_pdl(k_fill, dim3(ew_grid), dim3(TB), (cudaStream_t)0,
               src, dst, nextptr, csr);

    // join gemm1, then layer-1 gather (h1 bf16)
    cudaStreamWaitEvent(0, e_g1, 0);
    launch_pdl(k_gather128s, dim3(gather_blocks), dim3(TB), (cudaStream_t)0,
               (const __nv_bfloat16*)hb, (const float*)dis, (const int*)deg,
               (const int*)rowptr, (const int*)csr, b1, h1);

    // ---- layer 2: bf16-A gemm, then gather (h2 bf16)
    launch_pdl(k_gemm_tc_h, dim3(gemm_blocks), dim3(256), (cudaStream_t)0,
               (const __nv_bfloat16*)h1, W2, (const float*)dis, hb, (int)NN);
    launch_pdl(k_gather64s, dim3(gather_blocks), dim3(TB), (cudaStream_t)0,
               (const __nv_bfloat16*)hb, (const float*)dis, (const int*)deg,
               (const int*)rowptr, (const int*)csr, b2, h2);

    // ---- pooling (Wf1 folded) + head
    cudaStreamWaitEvent(0, e_pool, 0);   // join s2
    launch_pdl(k_pool64, dim3((NN + 255) / 256), dim3(256), (cudaStream_t)0,
               (const __nv_bfloat16*)h2, batch, gsum);
    launch_pdl(k_final2, dim3(1), dim3(256), (cudaStream_t)0,
               (const float*)gsum, (const float*)gcnt, Wf1, bf1, Wf2, bf2, out);
}

// round 16
// speedup vs baseline: 1.2417x; 1.0716x over previous
#include <cuda_runtime.h>
#include <cuda_bf16.h>
#include <cstdint>

// Problem constants (fixed by the dataset)
#define NN 100000
#define EE 3200000
#define NG 64
#define F_IN 128
#define H1 128
#define H2 64
#define DENSE 128
#define LABELS 2

#define SCAN_BLK 512
#define NB_SCAN ((NN + SCAN_BLK - 1) / SCAN_BLK)   // 196

// PDL entry sync: wait for upstream grid's memory before touching its outputs
__device__ __forceinline__ void gds() {
#if defined(__CUDA_ARCH__) && (__CUDA_ARCH__ >= 900)
    cudaGridDependencySynchronize();
#endif
}

// ---------------- scratch (__device__ globals; no runtime allocation) -------
__device__ float g_dis[NN];
__device__ int   g_deg[NN];
__device__ int   g_rowptr[NN];
__device__ int   g_nextptr[NN];
__device__ int   g_partials[256];
__device__ int   g_csr[EE];                        // src per CSR slot
__device__ __nv_bfloat16 g_hb[(size_t)NN * 128];   // gemm outputs, pre-scaled by dis
__device__ __nv_bfloat16 g_h1[(size_t)NN * 128];   // relu(layer1), bf16
__device__ __nv_bfloat16 g_h2[(size_t)NN * 64];    // relu(layer2), bf16
__device__ float g_gsum[NG * 64];
__device__ float g_gcnt[NG];
__device__ unsigned g_done;                        // pool ticket (reset each call)

// ---------------- CSR build --------------------------------------------------
__global__ void k_deg_count(const int* __restrict__ dst, int* __restrict__ deg) {
    gds();
    int i = blockIdx.x * blockDim.x + threadIdx.x;
    int stride = gridDim.x * blockDim.x;
    const int4* d4 = (const int4*)dst;
    for (; i < EE / 4; i += stride) {
        int4 v = __ldg(&d4[i]);
        atomicAdd(&deg[v.x], 1);
        atomicAdd(&deg[v.y], 1);
        atomicAdd(&deg[v.z], 1);
        atomicAdd(&deg[v.w], 1);
    }
}

// block-local scan of deg -> rowptr + per-block totals; also emits dis
__global__ void k_scan_block(const int* __restrict__ deg, int* __restrict__ rowptr,
                             int* __restrict__ partials, float* __restrict__ dis) {
    gds();
    __shared__ int s[SCAN_BLK];
    int tid = threadIdx.x;
    int i = blockIdx.x * SCAN_BLK + tid;
    int v = (i < NN) ? deg[i] : 0;
    s[tid] = v;
    __syncthreads();
#pragma unroll
    for (int off = 1; off < SCAN_BLK; off <<= 1) {
        int t = (tid >= off) ? s[tid - off] : 0;
        __syncthreads();
        s[tid] += t;
        __syncthreads();
    }
    if (i < NN) {
        rowptr[i] = s[tid] - v;           // block-local exclusive
        dis[i] = rsqrtf(1.0f + (float)v);
    }
    if (tid == SCAN_BLK - 1) partials[blockIdx.x] = s[tid];
}

// fused: scan the 196 partials (redundantly per block) + finalize rowptr/nextptr
__global__ void k_scan_finish(int* __restrict__ rowptr, const int* __restrict__ partials,
                              int* __restrict__ nextptr) {
    gds();
    __shared__ int s[256];
    int tid = threadIdx.x;
    int v = (tid < NB_SCAN) ? partials[tid] : 0;
    s[tid] = v;
    __syncthreads();
#pragma unroll
    for (int off = 1; off < 256; off <<= 1) {
        int t = (tid >= off) ? s[tid - off] : 0;
        __syncthreads();
        s[tid] += t;
        __syncthreads();
    }
    int ex = s[tid] - v;                           // exclusive
    __syncthreads();
    s[tid] = ex;
    __syncthreads();
    int i = blockIdx.x * 256 + tid;
    if (i < NN) {
        int r = rowptr[i] + s[i / SCAN_BLK];
        rowptr[i] = r;
        nextptr[i] = r;
    }
}

__global__ void k_fill(const int* __restrict__ src, const int* __restrict__ dst,
                       int* __restrict__ nextptr, int* __restrict__ csr) {
    gds();
    int i = blockIdx.x * blockDim.x + threadIdx.x;
    int stride = gridDim.x * blockDim.x;
    for (; i < EE; i += stride) {
        int d = dst[i];
        int s = src[i];
        int pos = atomicAdd(&nextptr[d], 1);
        csr[pos] = s;
    }
}

// ---------------- tf32 helpers ----------------------------------------------
__device__ __forceinline__ uint32_t f2tf32(float f) {
    uint32_t r;
    asm("cvt.rna.tf32.f32 %0, %1;" : "=r"(r) : "f"(f));
    return r;
}

__device__ __forceinline__ void tf32_store4(float* p, float4 v) {
    uint32_t hx = f2tf32(v.x), hy = f2tf32(v.y), hz = f2tf32(v.z), hw = f2tf32(v.w);
    *(float4*)p = make_float4(__uint_as_float(hx), __uint_as_float(hy),
                              __uint_as_float(hz), __uint_as_float(hw));
}

__device__ __forceinline__ void mma_tf32(float d[4], const uint32_t a[4],
                                         uint32_t b0, uint32_t b1) {
    asm volatile(
        "mma.sync.aligned.m16n8k8.row.col.f32.tf32.tf32.f32 "
        "{%0,%1,%2,%3},{%4,%5,%6,%7},{%8,%9},{%0,%1,%2,%3};"
        : "+f"(d[0]), "+f"(d[1]), "+f"(d[2]), "+f"(d[3])
        : "r"(a[0]), "r"(a[1]), "r"(a[2]), "r"(a[3]), "r"(b0), "r"(b1));
}

// ---------------- tf32 GEMM (fp32 A): Cb = bf16((A @ B) * dis[m]) -----------
template<int BN>
__global__ void __launch_bounds__(256)
k_gemm_tc(const float* __restrict__ A, const float* __restrict__ B,
          const float* __restrict__ dis, __nv_bfloat16* __restrict__ Cb, int M) {
    constexpr int BM = 128, BK = 16, KTOT = 128;
    constexpr int AP = 20;
    constexpr int BP = BN + 8;
    constexpr int NT = (BN / 2) / 8;
    __shared__ float sA[BM * AP];
    __shared__ float sB[BK * BP];

    int tid = threadIdx.x;
    int row0 = blockIdx.x * BM;
    int lane = tid & 31, warp = tid >> 5;
    int wr = warp >> 1, wc = warp & 1;
    int g = lane >> 2, tig = lane & 3;

    float acc[2][NT][4];
#pragma unroll
    for (int m = 0; m < 2; m++)
#pragma unroll
        for (int n = 0; n < NT; n++)
#pragma unroll
            for (int i = 0; i < 4; i++) acc[m][n][i] = 0.f;

    for (int kk = 0; kk < KTOT; kk += BK) {
#pragma unroll
        for (int i = 0; i < 2; i++) {
            int j = tid + 256 * i;
            int r = j >> 2;
            int c4 = (j & 3) * 4;
            float4 v = make_float4(0.f, 0.f, 0.f, 0.f);
            if (row0 + r < M)
                v = *(const float4*)(A + (size_t)(row0 + r) * KTOT + kk + c4);
            tf32_store4(sA + r * AP + c4, v);
        }
#pragma unroll
        for (int i = 0; i < BN / 64; i++) {
            int j = tid + 256 * i;
            int r = j / (BN / 4);
            int c4 = (j % (BN / 4)) * 4;
            float4 v = *(const float4*)(B + (size_t)(kk + r) * BN + c4);
            tf32_store4(sB + r * BP + c4, v);
        }
        __syncthreads();

#pragma unroll
        for (int ks = 0; ks < 2; ks++) {
            int k0 = ks * 8;
            uint32_t a[2][4];
#pragma unroll
            for (int mt = 0; mt < 2; mt++) {
                int rb = wr * 32 + mt * 16;
                a[mt][0] = __float_as_uint(sA[(rb + g) * AP + k0 + tig]);
                a[mt][1] = __float_as_uint(sA[(rb + g + 8) * AP + k0 + tig]);
                a[mt][2] = __float_as_uint(sA[(rb + g) * AP + k0 + tig + 4]);
                a[mt][3] = __float_as_uint(sA[(rb + g + 8) * AP + k0 + tig + 4]);
            }
#pragma unroll
            for (int nt = 0; nt < NT; nt++) {
                int nc = wc * (BN / 2) + nt * 8 + g;
                uint32_t b0 = __float_as_uint(sB[(k0 + tig) * BP + nc]);
                uint32_t b1 = __float_as_uint(sB[(k0 + tig + 4) * BP + nc]);
#pragma unroll
                for (int mt = 0; mt < 2; mt++)
                    mma_tf32(acc[mt][nt], a[mt], b0, b1);
            }
        }
        __syncthreads();
    }

#pragma unroll
    for (int mt = 0; mt < 2; mt++) {
        int r1 = row0 + wr * 32 + mt * 16 + g;
        int r2 = r1 + 8;
        float d1 = (r1 < M) ? __ldg(&dis[r1]) : 0.f;
        float d2 = (r2 < M) ? __ldg(&dis[r2]) : 0.f;
#pragma unroll
        for (int nt = 0; nt < NT; nt++) {
            int cc = wc * (BN / 2) + nt * 8 + 2 * tig;
            if (r1 < M)
                *(__nv_bfloat162*)(Cb + (size_t)r1 * BN + cc) =
                    __float22bfloat162_rn(make_float2(acc[mt][nt][0] * d1,
                                                      acc[mt][nt][1] * d1));
            if (r2 < M)
                *(__nv_bfloat162*)(Cb + (size_t)r2 * BN + cc) =
                    __float22bfloat162_rn(make_float2(acc[mt][nt][2] * d2,
                                                      acc[mt][nt][3] * d2));
        }
    }
}

// ---------------- tf32 GEMM (bf16 A, BN=64): Cb = bf16((A @ B) * dis[m]) ----
__global__ void __launch_bounds__(256)
k_gemm_tc_h(const __nv_bfloat16* __restrict__ A, const float* __restrict__ B,
            const float* __restrict__ dis, __nv_bfloat16* __restrict__ Cb, int M) {
    gds();
    constexpr int BM = 128, BK = 16, KTOT = 128, BN = 64;
    constexpr int AP = 20;
    constexpr int BP = BN + 8;
    constexpr int NT = (BN / 2) / 8;   // 4
    __shared__ float sA[BM * AP];
    __shared__ float sB[BK * BP];

    int tid = threadIdx.x;
    int row0 = blockIdx.x * BM;
    int lane = tid & 31, warp = tid >> 5;
    int wr = warp >> 1, wc = warp & 1;
    int g = lane >> 2, tig = lane & 3;

    float acc[2][NT][4];
#pragma unroll
    for (int m = 0; m < 2; m++)
#pragma unroll
        for (int n = 0; n < NT; n++)
#pragma unroll
            for (int i = 0; i < 4; i++) acc[m][n][i] = 0.f;

    for (int kk = 0; kk < KTOT; kk += BK) {
        {
            int r = tid >> 1;
            int half = tid & 1;
            uint4 v = make_uint4(0, 0, 0, 0);
            if (row0 + r < M)
                v = *(const uint4*)(A + (size_t)(row0 + r) * KTOT + kk + half * 8);
            const __nv_bfloat162* p = (const __nv_bfloat162*)&v;
            float* o = sA + r * AP + half * 8;
#pragma unroll
            for (int q = 0; q < 4; q++) {
                float2 f = __bfloat1622float2(p[q]);
                o[q * 2] = f.x;
                o[q * 2 + 1] = f.y;       // bf16->f32 is tf32-exact
            }
        }
        {
            int r = tid / (BN / 4);
            int c4 = (tid % (BN / 4)) * 4;
            float4 v = *(const float4*)(B + (size_t)(kk + r) * BN + c4);
            tf32_store4(sB + r * BP + c4, v);
        }
        __syncthreads();

#pragma unroll
        for (int ks = 0; ks < 2; ks++) {
            int k0 = ks * 8;
            uint32_t a[2][4];
#pragma unroll
            for (int mt = 0; mt < 2; mt++) {
                int rb = wr * 32 + mt * 16;
                a[mt][0] = __float_as_uint(sA[(rb + g) * AP + k0 + tig]);
                a[mt][1] = __float_as_uint(sA[(rb + g + 8) * AP + k0 + tig]);
                a[mt][2] = __float_as_uint(sA[(rb + g) * AP + k0 + tig + 4]);
                a[mt][3] = __float_as_uint(sA[(rb + g + 8) * AP + k0 + tig + 4]);
            }
#pragma unroll
            for (int nt = 0; nt < NT; nt++) {
                int nc = wc * (BN / 2) + nt * 8 + g;
                uint32_t b0 = __float_as_uint(sB[(k0 + tig) * BP + nc]);
                uint32_t b1 = __float_as_uint(sB[(k0 + tig + 4) * BP + nc]);
#pragma unroll
                for (int mt = 0; mt < 2; mt++)
                    mma_tf32(acc[mt][nt], a[mt], b0, b1);
            }
        }
        __syncthreads();
    }

#pragma unroll
    for (int mt = 0; mt < 2; mt++) {
        int r1 = row0 + wr * 32 + mt * 16 + g;
        int r2 = r1 + 8;
        float d1 = (r1 < M) ? __ldg(&dis[r1]) : 0.f;
        float d2 = (r2 < M) ? __ldg(&dis[r2]) : 0.f;
#pragma unroll
        for (int nt = 0; nt < NT; nt++) {
            int cc = wc * (BN / 2) + nt * 8 + 2 * tig;
            if (r1 < M)
                *(__nv_bfloat162*)(Cb + (size_t)r1 * BN + cc) =
                    __float22bfloat162_rn(make_float2(acc[mt][nt][0] * d1,
                                                      acc[mt][nt][1] * d1));
            if (r2 < M)
                *(__nv_bfloat162*)(Cb + (size_t)r2 * BN + cc) =
                    __float22bfloat162_rn(make_float2(acc[mt][nt][2] * d2,
                                                      acc[mt][nt][3] * d2));
        }
    }
}

// ---------------- fused gather helpers ---------------------------------------
__device__ __forceinline__ void accum8(float* a, uint4 v) {
    float2 f;
    f = __bfloat1622float2(*reinterpret_cast<__nv_bfloat162*>(&v.x));
    a[0] += f.x; a[1] += f.y;
    f = __bfloat1622float2(*reinterpret_cast<__nv_bfloat162*>(&v.y));
    a[2] += f.x; a[3] += f.y;
    f = __bfloat1622float2(*reinterpret_cast<__nv_bfloat162*>(&v.z));
    a[4] += f.x; a[5] += f.y;
    f = __bfloat1622float2(*reinterpret_cast<__nv_bfloat162*>(&v.w));
    a[6] += f.x; a[7] += f.y;
}

__device__ __forceinline__ void accum4(float* a, uint2 v) {
    float2 f;
    f = __bfloat1622float2(*reinterpret_cast<__nv_bfloat162*>(&v.x));
    a[0] += f.x; a[1] += f.y;
    f = __bfloat1622float2(*reinterpret_cast<__nv_bfloat162*>(&v.y));
    a[2] += f.x; a[3] += f.y;
}

// K=128: half-warp per edge row (16 lanes x uint4 = 256 B), 8 edges/iter.
__global__ void __launch_bounds__(256)
k_gather128s(const __nv_bfloat16* __restrict__ hb, const float* __restrict__ dis,
             const int* __restrict__ deg, const int* __restrict__ rowptr,
             const int* __restrict__ csr, const float* __restrict__ bias,
             __nv_bfloat16* __restrict__ out) {
    gds();
    int warp = (blockIdx.x * blockDim.x + threadIdx.x) >> 5;
    int lane = threadIdx.x & 31;
    int h = lane >> 4;
    int l = lane & 15;
    int nwarps = (gridDim.x * blockDim.x) >> 5;
    for (int node = warp; node < NN; node += nwarps) {
        int beg = rowptr[node];
        int cnt = deg[node];
        float acc[8] = {0.f, 0.f, 0.f, 0.f, 0.f, 0.f, 0.f, 0.f};
        int off = beg + h;
        int e = 0;
        for (; e + 7 < cnt; e += 8) {
            int s0 = __ldg(csr + off + e);
            int s1 = __ldg(csr + off + e + 2);
            int s2 = __ldg(csr + off + e + 4);
            int s3 = __ldg(csr + off + e + 6);
            uint4 v0 = *(const uint4*)(hb + (size_t)s0 * 128 + l * 8);
            uint4 v1 = *(const uint4*)(hb + (size_t)s1 * 128 + l * 8);
            uint4 v2 = *(const uint4*)(hb + (size_t)s2 * 128 + l * 8);
            uint4 v3 = *(const uint4*)(hb + (size_t)s3 * 128 + l * 8);
            accum8(acc, v0); accum8(acc, v1); accum8(acc, v2); accum8(acc, v3);
        }
        for (; e < cnt; e += 2) {
            int idx = e + h;
            if (idx < cnt) {
                int s = __ldg(csr + beg + idx);
                uint4 v = *(const uint4*)(hb + (size_t)s * 128 + l * 8);
                accum8(acc, v);
            }
        }
        if (h == 0) {
            uint4 v = *(const uint4*)(hb + (size_t)node * 128 + l * 8);
            accum8(acc, v);
        }
#pragma unroll
        for (int i = 0; i < 8; i++)
            acc[i] += __shfl_xor_sync(0xffffffffu, acc[i], 16);
        if (h == 0) {
            float dn = dis[node];
            float4 b0 = *(const float4*)(bias + l * 8);
            float4 b1 = *(const float4*)(bias + l * 8 + 4);
            float r0 = fmaxf(acc[0] * dn + b0.x, 0.f);
            float r1 = fmaxf(acc[1] * dn + b0.y, 0.f);
            float r2 = fmaxf(acc[2] * dn + b0.z, 0.f);
            float r3 = fmaxf(acc[3] * dn + b0.w, 0.f);
            float r4 = fmaxf(acc[4] * dn + b1.x, 0.f);
            float r5 = fmaxf(acc[5] * dn + b1.y, 0.f);
            float r6 = fmaxf(acc[6] * dn + b1.z, 0.f);
            float r7 = fmaxf(acc[7] * dn + b1.w, 0.f);
            uint4 o;
            *reinterpret_cast<__nv_bfloat162*>(&o.x) =
                __float22bfloat162_rn(make_float2(r0, r1));
            *reinterpret_cast<__nv_bfloat162*>(&o.y) =
                __float22bfloat162_rn(make_float2(r2, r3));
            *reinterpret_cast<__nv_bfloat162*>(&o.z) =
                __float22bfloat162_rn(make_float2(r4, r5));
            *reinterpret_cast<__nv_bfloat162*>(&o.w) =
                __float22bfloat162_rn(make_float2(r6, r7));
            *(uint4*)(out + (size_t)node * 128 + l * 8) = o;
        }
    }
}

// K=64: half-warp per edge row (16 lanes x uint2 = 128 B), 8 edges/iter.
__global__ void __launch_bounds__(256)
k_gather64s(const __nv_bfloat16* __restrict__ hb, const float* __restrict__ dis,
            const int* __restrict__ deg, const int* __restrict__ rowptr,
            const int* __restrict__ csr, const float* __restrict__ bias,
            __nv_bfloat16* __restrict__ out) {
    gds();
    int warp = (blockIdx.x * blockDim.x + threadIdx.x) >> 5;
    int lane = threadIdx.x & 31;
    int h = lane >> 4;
    int l = lane & 15;
    int nwarps = (gridDim.x * blockDim.x) >> 5;
    for (int node = warp; node < NN; node += nwarps) {
        int beg = rowptr[node];
        int cnt = deg[node];
        float acc[4] = {0.f, 0.f, 0.f, 0.f};
        int off = beg + h;
        int e = 0;
        for (; e + 7 < cnt; e += 8) {
            int s0 = __ldg(csr + off + e);
            int s1 = __ldg(csr + off + e + 2);
            int s2 = __ldg(csr + off + e + 4);
            int s3 = __ldg(csr + off + e + 6);
            uint2 v0 = *(const uint2*)(hb + (size_t)s0 * 64 + l * 4);
            uint2 v1 = *(const uint2*)(hb + (size_t)s1 * 64 + l * 4);
            uint2 v2 = *(const uint2*)(hb + (size_t)s2 * 64 + l * 4);
            uint2 v3 = *(const uint2*)(hb + (size_t)s3 * 64 + l * 4);
            accum4(acc, v0); accum4(acc, v1); accum4(acc, v2); accum4(acc, v3);
        }
        for (; e < cnt; e += 2) {
            int idx = e + h;
            if (idx < cnt) {
                int s = __ldg(csr + beg + idx);
                uint2 v = *(const uint2*)(hb + (size_t)s * 64 + l * 4);
                accum4(acc, v);
            }
        }
        if (h == 0) {
            uint2 v = *(const uint2*)(hb + (size_t)node * 64 + l * 4);
            accum4(acc, v);
        }
#pragma unroll
        for (int i = 0; i < 4; i++)
            acc[i] += __shfl_xor_sync(0xffffffffu, acc[i], 16);
        if (h == 0) {
            float dn = dis[node];
            float4 bv = *(const float4*)(bias + l * 4);
            float r0 = fmaxf(acc[0] * dn + bv.x, 0.f);
            float r1 = fmaxf(acc[1] * dn + bv.y, 0.f);
            float r2 = fmaxf(acc[2] * dn + bv.z, 0.f);
            float r3 = fmaxf(acc[3] * dn + bv.w, 0.f);
            uint2 o;
            *reinterpret_cast<__nv_bfloat162*>(&o.x) =
                __float22bfloat162_rn(make_float2(r0, r1));
            *reinterpret_cast<__nv_bfloat162*>(&o.y) =
                __float22bfloat162_rn(make_float2(r2, r3));
            *(uint2*)(out + (size_t)node * 64 + l * 4) = o;
        }
    }
}

// ---------------- counts via binary search (batch sorted, no atomics) --------
__global__ void k_count_bs(const int* __restrict__ batch, float* __restrict__ gcnt) {
    int g = threadIdx.x;                  // 64 threads
    if (g >= NG) return;
    int lo = 0, hi = NN;
    while (lo < hi) { int m = (lo + hi) >> 1; if (batch[m] < g) lo = m + 1; else hi = m; }
    int start = lo;
    lo = 0; hi = NN;
    while (lo < hi) { int m = (lo + hi) >> 1; if (batch[m] < g + 1) lo = m + 1; else hi = m; }
    gcnt[g] = (float)(lo - start);
}

// ---------------- pooling + fused head (last-block pattern) ------------------
// Pool gsum as before; the block that finishes last computes
//   ge = (gsum/cnt)@Wf1 + bf1 ; ic = ge@Wf2 + bf2 ; penalty = 0
__global__ void __launch_bounds__(256)
k_pool64f(const __nv_bfloat16* __restrict__ h2, const int* __restrict__ batch,
          float* __restrict__ gsum, const float* __restrict__ gcnt,
          const float* __restrict__ Wf1, const float* __restrict__ bf1,
          const float* __restrict__ Wf2, const float* __restrict__ bf2,
          float* __restrict__ out) {
    gds();
    constexpr int RB = 256;
    __shared__ float sm[4][64];
    __shared__ float ge[NG * DENSE];      // used only by the last block
    __shared__ int s_gmin, s_ngr;
    __shared__ bool s_last;
    int base = blockIdx.x * RB;
    int nrows = NN - base; if (nrows > RB) nrows = RB;
    int tid = threadIdx.x;
    if (tid == 0) {
        int gmin = batch[base];
        int gmax = batch[base + nrows - 1];
        s_gmin = gmin; s_ngr = gmax - gmin + 1;
    }
    for (int i = tid; i < 4 * 64; i += 256) ((float*)sm)[i] = 0.f;
    __syncthreads();
    int gmin = s_gmin, ngr = s_ngr;
    int c2 = (tid & 31) * 2;          // column pair
    int strip = tid >> 5;             // 8 row strips
    if (ngr <= 4) {
        int curg = -1; float a0 = 0.f, a1 = 0.f;
        for (int r = strip; r < nrows; r += 8) {
            int node = base + r;
            int g = batch[node];
            uint32_t p = *(const uint32_t*)(h2 + (size_t)node * 64 + c2);
            float2 f = __bfloat1622float2(*reinterpret_cast<__nv_bfloat162*>(&p));
            if (g != curg) {
                if (curg >= 0) {
                    atomicAdd(&sm[curg - gmin][c2], a0);
                    atomicAdd(&sm[curg - gmin][c2 + 1], a1);
                }
                curg = g; a0 = f.x; a1 = f.y;
            } else { a0 += f.x; a1 += f.y; }
        }
        if (curg >= 0) {
            atomicAdd(&sm[curg - gmin][c2], a0);
            atomicAdd(&sm[curg - gmin][c2 + 1], a1);
        }
        __syncthreads();
        if (tid < 64)
            for (int s = 0; s < ngr; s++) {
                float v = sm[s][tid];
                if (v != 0.f) atomicAdd(&gsum[(size_t)(gmin + s) * 64 + tid], v);
            }
    } else {
        for (int r = strip; r < nrows; r += 8) {
            int node = base + r;
            uint32_t p = *(const uint32_t*)(h2 + (size_t)node * 64 + c2);
            float2 f = __bfloat1622float2(*reinterpret_cast<__nv_bfloat162*>(&p));
            int g = batch[node];
            atomicAdd(&gsum[(size_t)g * 64 + c2], f.x);
            atomicAdd(&gsum[(size_t)g * 64 + c2 + 1], f.y);
        }
    }

    // ---- last-block head
    __threadfence();
    if (tid == 0) {
        unsigned t = atomicAdd(&g_done, 1u);
        s_last = (t == gridDim.x - 1);
    }
    __syncthreads();
    if (!s_last) return;
    if (tid == 0) g_done = 0;          // reset for next graph replay

    for (int idx = tid; idx < NG * DENSE; idx += 256) {
        int gg = idx >> 7, j = idx & 127;
        float inv = 1.0f / fmaxf(gcnt[gg], 1.0f);
        const float* pg = gsum + gg * 64;
        float a = 0.f;
#pragma unroll 8
        for (int c = 0; c < 64; c++)
            a += pg[c] * Wf1[c * DENSE + j];
        float v = a * inv + bf1[j];
        ge[idx] = v;
        out[idx] = v;
    }
    __syncthreads();
    if (tid < NG * LABELS) {
        int gg = tid >> 1, l = tid & 1;
        float s = bf2[l];
#pragma unroll 8
        for (int c = 0; c < DENSE; c++)
            s += ge[gg * DENSE + c] * Wf2[c * LABELS + l];
        out[NG * DENSE + 1 + tid] = s;
    }
    if (tid == 0) out[NG * DENSE] = 0.f;
}

// ---------------- PDL launch helper ------------------------------------------
template<typename F, typename... Args>
static inline void launch_pdl(F* kernel, dim3 grid, dim3 block, cudaStream_t st,
                              Args... args) {
    cudaLaunchConfig_t cfg = {};
    cfg.gridDim = grid;
    cfg.blockDim = block;
    cfg.dynamicSmemBytes = 0;
    cfg.stream = st;
    cudaLaunchAttribute attr[1];
    attr[0].id = cudaLaunchAttributeProgrammaticStreamSerialization;
    attr[0].val.programmaticStreamSerializationAllowed = 1;
    cfg.attrs = attr;
    cfg.numAttrs = 1;
    cudaLaunchKernelEx(&cfg, kernel, args...);
}

// ---------------- launch ----------------------------------------------------
extern "C" void kernel_launch(void* const* d_in, const int* in_sizes, int n_in,
                              void* d_out, int out_size) {
    const float* x   = (const float*)d_in[0];
    const float* W1  = (const float*)d_in[1];
    const float* b1  = (const float*)d_in[2];
    const float* W2  = (const float*)d_in[3];
    const float* b2  = (const float*)d_in[4];
    const float* Wf1 = (const float*)d_in[5];
    const float* bf1 = (const float*)d_in[6];
    const float* Wf2 = (const float*)d_in[7];
    const float* bf2 = (const float*)d_in[8];
    const int* ei    = (const int*)d_in[9];
    const int* batch = (const int*)d_in[10];
    const int* src = ei;
    const int* dst = ei + EE;
    float* out = (float*)d_out;

    float *dis, *gsum, *gcnt;
    __nv_bfloat16 *hb, *h1, *h2;
    int *deg, *rowptr, *nextptr, *partials, *csr;
    cudaGetSymbolAddress((void**)&dis,  g_dis);
    cudaGetSymbolAddress((void**)&deg,  g_deg);
    cudaGetSymbolAddress((void**)&rowptr, g_rowptr);
    cudaGetSymbolAddress((void**)&nextptr, g_nextptr);
    cudaGetSymbolAddress((void**)&partials, g_partials);
    cudaGetSymbolAddress((void**)&csr,  g_csr);
    cudaGetSymbolAddress((void**)&hb,   g_hb);
    cudaGetSymbolAddress((void**)&h1,   g_h1);
    cudaGetSymbolAddress((void**)&h2,   g_h2);
    cudaGetSymbolAddress((void**)&gsum, g_gsum);
    cudaGetSymbolAddress((void**)&gcnt, g_gcnt);

    // side streams + events (created once, on the uncaptured correctness call)
    static cudaStream_t s1 = nullptr, s2 = nullptr;
    static cudaEvent_t e_root = nullptr, e_dis = nullptr,
                       e_g1 = nullptr, e_pool = nullptr;
    if (!s1) {
        cudaStreamCreateWithFlags(&s1, cudaStreamNonBlocking);
        cudaStreamCreateWithFlags(&s2, cudaStreamNonBlocking);
        cudaEventCreateWithFlags(&e_root, cudaEventDisableTiming);
        cudaEventCreateWithFlags(&e_dis,  cudaEventDisableTiming);
        cudaEventCreateWithFlags(&e_g1,   cudaEventDisableTiming);
        cudaEventCreateWithFlags(&e_pool, cudaEventDisableTiming);
    }

    const int TB = 256;
    const int nblkN = (NN + TB - 1) / TB;
    const int ew_grid = 148 * 16;
    const int gemm_blocks = (NN + 127) / 128;
    const int gather_blocks = (NN * 32 + TB - 1) / TB;

    // deg zero via memset, then fork s2 for pool setup (input-only deps)
    cudaMemsetAsync(deg, 0, NN * sizeof(int), 0);
    cudaEventRecord(e_root, 0);
    cudaStreamWaitEvent(s2, e_root, 0);
    cudaMemsetAsync(gsum, 0, NG * 64 * sizeof(float), s2);
    k_count_bs<<<1, 64, 0, s2>>>(batch, gcnt);
    cudaEventRecord(e_pool, s2);

    // ---- degree + scan (scan_block also emits dis); gemm1 forks after it
    launch_pdl(k_deg_count, dim3(ew_grid), dim3(TB), (cudaStream_t)0, dst, deg);
    launch_pdl(k_scan_block, dim3(NB_SCAN), dim3(SCAN_BLK), (cudaStream_t)0,
               deg, rowptr, partials, dis);
    cudaEventRecord(e_dis, 0);
    cudaStreamWaitEvent(s1, e_dis, 0);
    k_gemm_tc<128><<<gemm_blocks, 256, 0, s1>>>(x, W1, dis, hb, NN);   // s1
    cudaEventRecord(e_g1, s1);

    // ---- finish scan + fill on default stream, overlapping gemm1
    launch_pdl(k_scan_finish, dim3(nblkN), dim3(TB), (cudaStream_t)0,
               rowptr, (const int*)partials, nextptr);
    launch_pdl(k_fill, dim3(ew_grid), dim3(TB), (cudaStream_t)0,
               src, dst, nextptr, csr);

    // join gemm1, then layer-1 gather (h1 bf16)
    cudaStreamWaitEvent(0, e_g1, 0);
    launch_pdl(k_gather128s, dim3(gather_blocks), dim3(TB), (cudaStream_t)0,
               (const __nv_bfloat16*)hb, (const float*)dis, (const int*)deg,
               (const int*)rowptr, (const int*)csr, b1, h1);

    // ---- layer 2: bf16-A gemm, then gather (h2 bf16)
    launch_pdl(k_gemm_tc_h, dim3(gemm_blocks), dim3(256), (cudaStream_t)0,
               (const __nv_bfloat16*)h1, W2, (const float*)dis, hb, (int)NN);
    launch_pdl(k_gather64s, dim3(gather_blocks), dim3(TB), (cudaStream_t)0,
               (const __nv_bfloat16*)hb, (const float*)dis, (const int*)deg,
               (const int*)rowptr, (const int*)csr, b2, h2);

    // ---- pooling + fused head (last block)
    cudaStreamWaitEvent(0, e_pool, 0);   // join s2
    launch_pdl(k_pool64f, dim3((NN + 255) / 256), dim3(256), (cudaStream_t)0,
               (const __nv_bfloat16*)h2, batch, gsum, (const float*)gcnt,
               Wf1, bf1, Wf2, bf2, out);
}

// round 17
// speedup vs baseline: 1.2498x; 1.0065x over previous
#include <cuda_runtime.h>
#include <cuda_bf16.h>
#include <cstdint>

// Problem constants (fixed by the dataset)
#define NN 100000
#define EE 3200000
#define NG 64
#define F_IN 128
#define H1 128
#define H2 64
#define DENSE 128
#define LABELS 2

#define SCAN_BLK 512
#define NB_SCAN ((NN + SCAN_BLK - 1) / SCAN_BLK)   // 196

// PDL entry sync: wait for upstream grid's memory before touching its outputs
__device__ __forceinline__ void gds() {
#if defined(__CUDA_ARCH__) && (__CUDA_ARCH__ >= 900)
    cudaGridDependencySynchronize();
#endif
}

// ---------------- scratch (__device__ globals; no runtime allocation) -------
__device__ float g_dis[NN];
__device__ int   g_deg[NN];
__device__ int   g_rowptr[NN];
__device__ int   g_nextptr[NN];
__device__ int   g_partials[256];
__device__ int   g_csr[EE];                        // src per CSR slot
__device__ __nv_bfloat16 g_hb[(size_t)NN * 128];   // gemm outputs, pre-scaled by dis
__device__ __nv_bfloat16 g_h1[(size_t)NN * 128];   // relu(layer1), bf16
__device__ __nv_bfloat16 g_h2[(size_t)NN * 64];    // relu(layer2), bf16
__device__ float g_gsum[NG * 64];
__device__ float g_gcnt[NG];
__device__ unsigned g_done;                        // pool ticket (reset each call)

// ---------------- CSR build --------------------------------------------------
__global__ void k_deg_count(const int* __restrict__ dst, int* __restrict__ deg) {
    gds();
    int i = blockIdx.x * blockDim.x + threadIdx.x;
    int stride = gridDim.x * blockDim.x;
    const int4* d4 = (const int4*)dst;
    for (; i < EE / 4; i += stride) {
        int4 v = __ldg(&d4[i]);
        atomicAdd(&deg[v.x], 1);
        atomicAdd(&deg[v.y], 1);
        atomicAdd(&deg[v.z], 1);
        atomicAdd(&deg[v.w], 1);
    }
}

// block-local scan of deg -> rowptr + per-block totals; also emits dis
__global__ void k_scan_block(const int* __restrict__ deg, int* __restrict__ rowptr,
                             int* __restrict__ partials, float* __restrict__ dis) {
    gds();
    __shared__ int s[SCAN_BLK];
    int tid = threadIdx.x;
    int i = blockIdx.x * SCAN_BLK + tid;
    int v = (i < NN) ? deg[i] : 0;
    s[tid] = v;
    __syncthreads();
#pragma unroll
    for (int off = 1; off < SCAN_BLK; off <<= 1) {
        int t = (tid >= off) ? s[tid - off] : 0;
        __syncthreads();
        s[tid] += t;
        __syncthreads();
    }
    if (i < NN) {
        rowptr[i] = s[tid] - v;           // block-local exclusive
        dis[i] = rsqrtf(1.0f + (float)v);
    }
    if (tid == SCAN_BLK - 1) partials[blockIdx.x] = s[tid];
}

// fused: scan the 196 partials (redundantly per block) + finalize rowptr/nextptr
__global__ void k_scan_finish(int* __restrict__ rowptr, const int* __restrict__ partials,
                              int* __restrict__ nextptr) {
    gds();
    __shared__ int s[256];
    int tid = threadIdx.x;
    int v = (tid < NB_SCAN) ? partials[tid] : 0;
    s[tid] = v;
    __syncthreads();
#pragma unroll
    for (int off = 1; off < 256; off <<= 1) {
        int t = (tid >= off) ? s[tid - off] : 0;
        __syncthreads();
        s[tid] += t;
        __syncthreads();
    }
    int ex = s[tid] - v;                           // exclusive
    __syncthreads();
    s[tid] = ex;
    __syncthreads();
    int i = blockIdx.x * 256 + tid;
    if (i < NN) {
        int r = rowptr[i] + s[i / SCAN_BLK];
        rowptr[i] = r;
        nextptr[i] = r;
    }
}

__global__ void k_fill(const int* __restrict__ src, const int* __restrict__ dst,
                       int* __restrict__ nextptr, int* __restrict__ csr) {
    gds();
    int i = blockIdx.x * blockDim.x + threadIdx.x;
    int stride = gridDim.x * blockDim.x;
    for (; i < EE; i += stride) {
        int d = dst[i];
        int s = src[i];
        int pos = atomicAdd(&nextptr[d], 1);
        csr[pos] = s;
    }
}

// ---------------- tf32 helpers ----------------------------------------------
__device__ __forceinline__ uint32_t f2tf32(float f) {
    uint32_t r;
    asm("cvt.rna.tf32.f32 %0, %1;" : "=r"(r) : "f"(f));
    return r;
}

__device__ __forceinline__ void tf32_store4(float* p, float4 v) {
    uint32_t hx = f2tf32(v.x), hy = f2tf32(v.y), hz = f2tf32(v.z), hw = f2tf32(v.w);
    *(float4*)p = make_float4(__uint_as_float(hx), __uint_as_float(hy),
                              __uint_as_float(hz), __uint_as_float(hw));
}

__device__ __forceinline__ void mma_tf32(float d[4], const uint32_t a[4],
                                         uint32_t b0, uint32_t b1) {
    asm volatile(
        "mma.sync.aligned.m16n8k8.row.col.f32.tf32.tf32.f32 "
        "{%0,%1,%2,%3},{%4,%5,%6,%7},{%8,%9},{%0,%1,%2,%3};"
        : "+f"(d[0]), "+f"(d[1]), "+f"(d[2]), "+f"(d[3])
        : "r"(a[0]), "r"(a[1]), "r"(a[2]), "r"(a[3]), "r"(b0), "r"(b1));
}

// ---------------- tf32 GEMM (fp32 A): Cb = bf16((A @ B) * dis[m]) -----------
template<int BN>
__global__ void __launch_bounds__(256)
k_gemm_tc(const float* __restrict__ A, const float* __restrict__ B,
          const float* __restrict__ dis, __nv_bfloat16* __restrict__ Cb, int M) {
    constexpr int BM = 128, BK = 16, KTOT = 128;
    constexpr int AP = 20;
    constexpr int BP = BN + 8;
    constexpr int NT = (BN / 2) / 8;
    __shared__ float sA[BM * AP];
    __shared__ float sB[BK * BP];

    int tid = threadIdx.x;
    int row0 = blockIdx.x * BM;
    int lane = tid & 31, warp = tid >> 5;
    int wr = warp >> 1, wc = warp & 1;
    int g = lane >> 2, tig = lane & 3;

    float acc[2][NT][4];
#pragma unroll
    for (int m = 0; m < 2; m++)
#pragma unroll
        for (int n = 0; n < NT; n++)
#pragma unroll
            for (int i = 0; i < 4; i++) acc[m][n][i] = 0.f;

    for (int kk = 0; kk < KTOT; kk += BK) {
#pragma unroll
        for (int i = 0; i < 2; i++) {
            int j = tid + 256 * i;
            int r = j >> 2;
            int c4 = (j & 3) * 4;
            float4 v = make_float4(0.f, 0.f, 0.f, 0.f);
            if (row0 + r < M)
                v = *(const float4*)(A + (size_t)(row0 + r) * KTOT + kk + c4);
            tf32_store4(sA + r * AP + c4, v);
        }
#pragma unroll
        for (int i = 0; i < BN / 64; i++) {
            int j = tid + 256 * i;
            int r = j / (BN / 4);
            int c4 = (j % (BN / 4)) * 4;
            float4 v = *(const float4*)(B + (size_t)(kk + r) * BN + c4);
            tf32_store4(sB + r * BP + c4, v);
        }
        __syncthreads();

#pragma unroll
        for (int ks = 0; ks < 2; ks++) {
            int k0 = ks * 8;
            uint32_t a[2][4];
#pragma unroll
            for (int mt = 0; mt < 2; mt++) {
                int rb = wr * 32 + mt * 16;
                a[mt][0] = __float_as_uint(sA[(rb + g) * AP + k0 + tig]);
                a[mt][1] = __float_as_uint(sA[(rb + g + 8) * AP + k0 + tig]);
                a[mt][2] = __float_as_uint(sA[(rb + g) * AP + k0 + tig + 4]);
                a[mt][3] = __float_as_uint(sA[(rb + g + 8) * AP + k0 + tig + 4]);
            }
#pragma unroll
            for (int nt = 0; nt < NT; nt++) {
                int nc = wc * (BN / 2) + nt * 8 + g;
                uint32_t b0 = __float_as_uint(sB[(k0 + tig) * BP + nc]);
                uint32_t b1 = __float_as_uint(sB[(k0 + tig + 4) * BP + nc]);
#pragma unroll
                for (int mt = 0; mt < 2; mt++)
                    mma_tf32(acc[mt][nt], a[mt], b0, b1);
            }
        }
        __syncthreads();
    }

#pragma unroll
    for (int mt = 0; mt < 2; mt++) {
        int r1 = row0 + wr * 32 + mt * 16 + g;
        int r2 = r1 + 8;
        float d1 = (r1 < M) ? __ldg(&dis[r1]) : 0.f;
        float d2 = (r2 < M) ? __ldg(&dis[r2]) : 0.f;
#pragma unroll
        for (int nt = 0; nt < NT; nt++) {
            int cc = wc * (BN / 2) + nt * 8 + 2 * tig;
            if (r1 < M)
                *(__nv_bfloat162*)(Cb + (size_t)r1 * BN + cc) =
                    __float22bfloat162_rn(make_float2(acc[mt][nt][0] * d1,
                                                      acc[mt][nt][1] * d1));
            if (r2 < M)
                *(__nv_bfloat162*)(Cb + (size_t)r2 * BN + cc) =
                    __float22bfloat162_rn(make_float2(acc[mt][nt][2] * d2,
                                                      acc[mt][nt][3] * d2));
        }
    }
}

// ---------------- tf32 GEMM (bf16 A, BN=64): Cb = bf16((A @ B) * dis[m]) ----
__global__ void __launch_bounds__(256)
k_gemm_tc_h(const __nv_bfloat16* __restrict__ A, const float* __restrict__ B,
            const float* __restrict__ dis, __nv_bfloat16* __restrict__ Cb, int M) {
    gds();
    constexpr int BM = 128, BK = 16, KTOT = 128, BN = 64;
    constexpr int AP = 20;
    constexpr int BP = BN + 8;
    constexpr int NT = (BN / 2) / 8;   // 4
    __shared__ float sA[BM * AP];
    __shared__ float sB[BK * BP];

    int tid = threadIdx.x;
    int row0 = blockIdx.x * BM;
    int lane = tid & 31, warp = tid >> 5;
    int wr = warp >> 1, wc = warp & 1;
    int g = lane >> 2, tig = lane & 3;

    float acc[2][NT][4];
#pragma unroll
    for (int m = 0; m < 2; m++)
#pragma unroll
        for (int n = 0; n < NT; n++)
#pragma unroll
            for (int i = 0; i < 4; i++) acc[m][n][i] = 0.f;

    for (int kk = 0; kk < KTOT; kk += BK) {
        {
            int r = tid >> 1;
            int half = tid & 1;
            uint4 v = make_uint4(0, 0, 0, 0);
            if (row0 + r < M)
                v = *(const uint4*)(A + (size_t)(row0 + r) * KTOT + kk + half * 8);
            const __nv_bfloat162* p = (const __nv_bfloat162*)&v;
            float* o = sA + r * AP + half * 8;
#pragma unroll
            for (int q = 0; q < 4; q++) {
                float2 f = __bfloat1622float2(p[q]);
                o[q * 2] = f.x;
                o[q * 2 + 1] = f.y;       // bf16->f32 is tf32-exact
            }
        }
        {
            int r = tid / (BN / 4);
            int c4 = (tid % (BN / 4)) * 4;
            float4 v = *(const float4*)(B + (size_t)(kk + r) * BN + c4);
            tf32_store4(sB + r * BP + c4, v);
        }
        __syncthreads();

#pragma unroll
        for (int ks = 0; ks < 2; ks++) {
            int k0 = ks * 8;
            uint32_t a[2][4];
#pragma unroll
            for (int mt = 0; mt < 2; mt++) {
                int rb = wr * 32 + mt * 16;
                a[mt][0] = __float_as_uint(sA[(rb + g) * AP + k0 + tig]);
                a[mt][1] = __float_as_uint(sA[(rb + g + 8) * AP + k0 + tig]);
                a[mt][2] = __float_as_uint(sA[(rb + g) * AP + k0 + tig + 4]);
                a[mt][3] = __float_as_uint(sA[(rb + g + 8) * AP + k0 + tig + 4]);
            }
#pragma unroll
            for (int nt = 0; nt < NT; nt++) {
                int nc = wc * (BN / 2) + nt * 8 + g;
                uint32_t b0 = __float_as_uint(sB[(k0 + tig) * BP + nc]);
                uint32_t b1 = __float_as_uint(sB[(k0 + tig + 4) * BP + nc]);
#pragma unroll
                for (int mt = 0; mt < 2; mt++)
                    mma_tf32(acc[mt][nt], a[mt], b0, b1);
            }
        }
        __syncthreads();
    }

#pragma unroll
    for (int mt = 0; mt < 2; mt++) {
        int r1 = row0 + wr * 32 + mt * 16 + g;
        int r2 = r1 + 8;
        float d1 = (r1 < M) ? __ldg(&dis[r1]) : 0.f;
        float d2 = (r2 < M) ? __ldg(&dis[r2]) : 0.f;
#pragma unroll
        for (int nt = 0; nt < NT; nt++) {
            int cc = wc * (BN / 2) + nt * 8 + 2 * tig;
            if (r1 < M)
                *(__nv_bfloat162*)(Cb + (size_t)r1 * BN + cc) =
                    __float22bfloat162_rn(make_float2(acc[mt][nt][0] * d1,
                                                      acc[mt][nt][1] * d1));
            if (r2 < M)
                *(__nv_bfloat162*)(Cb + (size_t)r2 * BN + cc) =
                    __float22bfloat162_rn(make_float2(acc[mt][nt][2] * d2,
                                                      acc[mt][nt][3] * d2));
        }
    }
}

// ---------------- packed f32x2 gather accumulation ---------------------------
// bf162 word w -> f32x2 pair (lo = w<<16, hi = w & 0xffff0000), one packed add.
__device__ __forceinline__ void accp(unsigned long long& acc, uint32_t w) {
    uint32_t lo = w << 16;
    uint32_t hi = w & 0xffff0000u;
    unsigned long long v;
    asm("mov.b64 %0, {%1, %2};" : "=l"(v) : "r"(lo), "r"(hi));
    asm("add.rn.f32x2 %0, %1, %2;" : "=l"(acc) : "l"(acc), "l"(v));
}

__device__ __forceinline__ void accp4(unsigned long long* a, uint4 v) {
    accp(a[0], v.x); accp(a[1], v.y); accp(a[2], v.z); accp(a[3], v.w);
}

__device__ __forceinline__ void accp2(unsigned long long* a, uint2 v) {
    accp(a[0], v.x); accp(a[1], v.y);
}

__device__ __forceinline__ float2 unpackp(unsigned long long acc) {
    float lo, hi;
    asm("mov.b64 {%0, %1}, %2;" : "=f"(lo), "=f"(hi) : "l"(acc));
    return make_float2(lo, hi);
}

// K=128: half-warp per edge row (16 lanes x uint4 = 256 B), 8 edges/iter.
__global__ void __launch_bounds__(256)
k_gather128s(const __nv_bfloat16* __restrict__ hb, const float* __restrict__ dis,
             const int* __restrict__ deg, const int* __restrict__ rowptr,
             const int* __restrict__ csr, const float* __restrict__ bias,
             __nv_bfloat16* __restrict__ out) {
    gds();
    int warp = (blockIdx.x * blockDim.x + threadIdx.x) >> 5;
    int lane = threadIdx.x & 31;
    int h = lane >> 4;
    int l = lane & 15;
    int nwarps = (gridDim.x * blockDim.x) >> 5;
    for (int node = warp; node < NN; node += nwarps) {
        int beg = rowptr[node];
        int cnt = deg[node];
        unsigned long long pa[4] = {0ull, 0ull, 0ull, 0ull};
        int off = beg + h;
        int e = 0;
        for (; e + 7 < cnt; e += 8) {
            int s0 = __ldg(csr + off + e);
            int s1 = __ldg(csr + off + e + 2);
            int s2 = __ldg(csr + off + e + 4);
            int s3 = __ldg(csr + off + e + 6);
            uint4 v0 = *(const uint4*)(hb + (size_t)s0 * 128 + l * 8);
            uint4 v1 = *(const uint4*)(hb + (size_t)s1 * 128 + l * 8);
            uint4 v2 = *(const uint4*)(hb + (size_t)s2 * 128 + l * 8);
            uint4 v3 = *(const uint4*)(hb + (size_t)s3 * 128 + l * 8);
            accp4(pa, v0); accp4(pa, v1); accp4(pa, v2); accp4(pa, v3);
        }
        for (; e < cnt; e += 2) {
            int idx = e + h;
            if (idx < cnt) {
                int s = __ldg(csr + beg + idx);
                uint4 v = *(const uint4*)(hb + (size_t)s * 128 + l * 8);
                accp4(pa, v);
            }
        }
        if (h == 0) {
            uint4 v = *(const uint4*)(hb + (size_t)node * 128 + l * 8);
            accp4(pa, v);
        }
        float acc[8];
#pragma unroll
        for (int i = 0; i < 4; i++) {
            float2 f = unpackp(pa[i]);
            acc[2 * i] = f.x; acc[2 * i + 1] = f.y;
        }
#pragma unroll
        for (int i = 0; i < 8; i++)
            acc[i] += __shfl_xor_sync(0xffffffffu, acc[i], 16);
        if (h == 0) {
            float dn = dis[node];
            float4 b0 = *(const float4*)(bias + l * 8);
            float4 b1 = *(const float4*)(bias + l * 8 + 4);
            float r0 = fmaxf(acc[0] * dn + b0.x, 0.f);
            float r1 = fmaxf(acc[1] * dn + b0.y, 0.f);
            float r2 = fmaxf(acc[2] * dn + b0.z, 0.f);
            float r3 = fmaxf(acc[3] * dn + b0.w, 0.f);
            float r4 = fmaxf(acc[4] * dn + b1.x, 0.f);
            float r5 = fmaxf(acc[5] * dn + b1.y, 0.f);
            float r6 = fmaxf(acc[6] * dn + b1.z, 0.f);
            float r7 = fmaxf(acc[7] * dn + b1.w, 0.f);
            uint4 o;
            *reinterpret_cast<__nv_bfloat162*>(&o.x) =
                __float22bfloat162_rn(make_float2(r0, r1));
            *reinterpret_cast<__nv_bfloat162*>(&o.y) =
                __float22bfloat162_rn(make_float2(r2, r3));
            *reinterpret_cast<__nv_bfloat162*>(&o.z) =
                __float22bfloat162_rn(make_float2(r4, r5));
            *reinterpret_cast<__nv_bfloat162*>(&o.w) =
                __float22bfloat162_rn(make_float2(r6, r7));
            *(uint4*)(out + (size_t)node * 128 + l * 8) = o;
        }
    }
}

// K=64: half-warp per edge row (16 lanes x uint2 = 128 B), 8 edges/iter.
__global__ void __launch_bounds__(256)
k_gather64s(const __nv_bfloat16* __restrict__ hb, const float* __restrict__ dis,
            const int* __restrict__ deg, const int* __restrict__ rowptr,
            const int* __restrict__ csr, const float* __restrict__ bias,
            __nv_bfloat16* __restrict__ out) {
    gds();
    int warp = (blockIdx.x * blockDim.x + threadIdx.x) >> 5;
    int lane = threadIdx.x & 31;
    int h = lane >> 4;
    int l = lane & 15;
    int nwarps = (gridDim.x * blockDim.x) >> 5;
    for (int node = warp; node < NN; node += nwarps) {
        int beg = rowptr[node];
        int cnt = deg[node];
        unsigned long long pa[2] = {0ull, 0ull};
        int off = beg + h;
        int e = 0;
        for (; e + 7 < cnt; e += 8) {
            int s0 = __ldg(csr + off + e);
            int s1 = __ldg(csr + off + e + 2);
            int s2 = __ldg(csr + off + e + 4);
            int s3 = __ldg(csr + off + e + 6);
            uint2 v0 = *(const uint2*)(hb + (size_t)s0 * 64 + l * 4);
            uint2 v1 = *(const uint2*)(hb + (size_t)s1 * 64 + l * 4);
            uint2 v2 = *(const uint2*)(hb + (size_t)s2 * 64 + l * 4);
            uint2 v3 = *(const uint2*)(hb + (size_t)s3 * 64 + l * 4);
            accp2(pa, v0); accp2(pa, v1); accp2(pa, v2); accp2(pa, v3);
        }
        for (; e < cnt; e += 2) {
            int idx = e + h;
            if (idx < cnt) {
                int s = __ldg(csr + beg + idx);
                uint2 v = *(const uint2*)(hb + (size_t)s * 64 + l * 4);
                accp2(pa, v);
            }
        }
        if (h == 0) {
            uint2 v = *(const uint2*)(hb + (size_t)node * 64 + l * 4);
            accp2(pa, v);
        }
        float acc[4];
        {
            float2 f0 = unpackp(pa[0]);
            float2 f1 = unpackp(pa[1]);
            acc[0] = f0.x; acc[1] = f0.y; acc[2] = f1.x; acc[3] = f1.y;
        }
#pragma unroll
        for (int i = 0; i < 4; i++)
            acc[i] += __shfl_xor_sync(0xffffffffu, acc[i], 16);
        if (h == 0) {
            float dn = dis[node];
            float4 bv = *(const float4*)(bias + l * 4);
            float r0 = fmaxf(acc[0] * dn + bv.x, 0.f);
            float r1 = fmaxf(acc[1] * dn + bv.y, 0.f);
            float r2 = fmaxf(acc[2] * dn + bv.z, 0.f);
            float r3 = fmaxf(acc[3] * dn + bv.w, 0.f);
            uint2 o;
            *reinterpret_cast<__nv_bfloat162*>(&o.x) =
                __float22bfloat162_rn(make_float2(r0, r1));
            *reinterpret_cast<__nv_bfloat162*>(&o.y) =
                __float22bfloat162_rn(make_float2(r2, r3));
            *(uint2*)(out + (size_t)node * 64 + l * 4) = o;
        }
    }
}

// ---------------- counts via binary search (batch sorted, no atomics) --------
__global__ void k_count_bs(const int* __restrict__ batch, float* __restrict__ gcnt) {
    int g = threadIdx.x;                  // 64 threads
    if (g >= NG) return;
    int lo = 0, hi = NN;
    while (lo < hi) { int m = (lo + hi) >> 1; if (batch[m] < g) lo = m + 1; else hi = m; }
    int start = lo;
    lo = 0; hi = NN;
    while (lo < hi) { int m = (lo + hi) >> 1; if (batch[m] < g + 1) lo = m + 1; else hi = m; }
    gcnt[g] = (float)(lo - start);
}

// ---------------- pooling + fused head (last-block pattern) ------------------
__global__ void __launch_bounds__(256)
k_pool64f(const __nv_bfloat16* __restrict__ h2, const int* __restrict__ batch,
          float* __restrict__ gsum, const float* __restrict__ gcnt,
          const float* __restrict__ Wf1, const float* __restrict__ bf1,
          const float* __restrict__ Wf2, const float* __restrict__ bf2,
          float* __restrict__ out) {
    gds();
    constexpr int RB = 256;
    __shared__ float sm[4][64];
    __shared__ float ge[NG * DENSE];      // used only by the last block
    __shared__ int s_gmin, s_ngr;
    __shared__ bool s_last;
    int base = blockIdx.x * RB;
    int nrows = NN - base; if (nrows > RB) nrows = RB;
    int tid = threadIdx.x;
    if (tid == 0) {
        int gmin = batch[base];
        int gmax = batch[base + nrows - 1];
        s_gmin = gmin; s_ngr = gmax - gmin + 1;
    }
    for (int i = tid; i < 4 * 64; i += 256) ((float*)sm)[i] = 0.f;
    __syncthreads();
    int gmin = s_gmin, ngr = s_ngr;
    int c2 = (tid & 31) * 2;
    int strip = tid >> 5;
    if (ngr <= 4) {
        int curg = -1; float a0 = 0.f, a1 = 0.f;
        for (int r = strip; r < nrows; r += 8) {
            int node = base + r;
            int g = batch[node];
            uint32_t p = *(const uint32_t*)(h2 + (size_t)node * 64 + c2);
            float2 f = __bfloat1622float2(*reinterpret_cast<__nv_bfloat162*>(&p));
            if (g != curg) {
                if (curg >= 0) {
                    atomicAdd(&sm[curg - gmin][c2], a0);
                    atomicAdd(&sm[curg - gmin][c2 + 1], a1);
                }
                curg = g; a0 = f.x; a1 = f.y;
            } else { a0 += f.x; a1 += f.y; }
        }
        if (curg >= 0) {
            atomicAdd(&sm[curg - gmin][c2], a0);
            atomicAdd(&sm[curg - gmin][c2 + 1], a1);
        }
        __syncthreads();
        if (tid < 64)
            for (int s = 0; s < ngr; s++) {
                float v = sm[s][tid];
                if (v != 0.f) atomicAdd(&gsum[(size_t)(gmin + s) * 64 + tid], v);
            }
    } else {
        for (int r = strip; r < nrows; r += 8) {
            int node = base + r;
            uint32_t p = *(const uint32_t*)(h2 + (size_t)node * 64 + c2);
            float2 f = __bfloat1622float2(*reinterpret_cast<__nv_bfloat162*>(&p));
            int g = batch[node];
            atomicAdd(&gsum[(size_t)g * 64 + c2], f.x);
            atomicAdd(&gsum[(size_t)g * 64 + c2 + 1], f.y);
        }
    }

    // ---- last-block head
    __threadfence();
    if (tid == 0) {
        unsigned t = atomicAdd(&g_done, 1u);
        s_last = (t == gridDim.x - 1);
    }
    __syncthreads();
    if (!s_last) return;
    if (tid == 0) g_done = 0;          // reset for next graph replay

    for (int idx = tid; idx < NG * DENSE; idx += 256) {
        int gg = idx >> 7, j = idx & 127;
        float inv = 1.0f / fmaxf(gcnt[gg], 1.0f);
        const float* pg = gsum + gg * 64;
        float a = 0.f;
#pragma unroll 8
        for (int c = 0; c < 64; c++)
            a += pg[c] * Wf1[c * DENSE + j];
        float v = a * inv + bf1[j];
        ge[idx] = v;
        out[idx] = v;
    }
    __syncthreads();
    if (tid < NG * LABELS) {
        int gg = tid >> 1, l = tid & 1;
        float s = bf2[l];
#pragma unroll 8
        for (int c = 0; c < DENSE; c++)
            s += ge[gg * DENSE + c] * Wf2[c * LABELS + l];
        out[NG * DENSE + 1 + tid] = s;
    }
    if (tid == 0) out[NG * DENSE] = 0.f;
}

// ---------------- PDL launch helper ------------------------------------------
template<typename F, typename... Args>
static inline void launch_pdl(F* kernel, dim3 grid, dim3 block, cudaStream_t st,
                              Args... args) {
    cudaLaunchConfig_t cfg = {};
    cfg.gridDim = grid;
    cfg.blockDim = block;
    cfg.dynamicSmemBytes = 0;
    cfg.stream = st;
    cudaLaunchAttribute attr[1];
    attr[0].id = cudaLaunchAttributeProgrammaticStreamSerialization;
    attr[0].val.programmaticStreamSerializationAllowed = 1;
    cfg.attrs = attr;
    cfg.numAttrs = 1;
    cudaLaunchKernelEx(&cfg, kernel, args...);
}

// ---------------- launch ----------------------------------------------------
extern "C" void kernel_launch(void* const* d_in, const int* in_sizes, int n_in,
                              void* d_out, int out_size) {
    const float* x   = (const float*)d_in[0];
    const float* W1  = (const float*)d_in[1];
    const float* b1  = (const float*)d_in[2];
    const float* W2  = (const float*)d_in[3];
    const float* b2  = (const float*)d_in[4];
    const float* Wf1 = (const float*)d_in[5];
    const float* bf1 = (const float*)d_in[6];
    const float* Wf2 = (const float*)d_in[7];
    const float* bf2 = (const float*)d_in[8];
    const int* ei    = (const int*)d_in[9];
    const int* batch = (const int*)d_in[10];
    const int* src = ei;
    const int* dst = ei + EE;
    float* out = (float*)d_out;

    float *dis, *gsum, *gcnt;
    __nv_bfloat16 *hb, *h1, *h2;
    int *deg, *rowptr, *nextptr, *partials, *csr;
    cudaGetSymbolAddress((void**)&dis,  g_dis);
    cudaGetSymbolAddress((void**)&deg,  g_deg);
    cudaGetSymbolAddress((void**)&rowptr, g_rowptr);
    cudaGetSymbolAddress((void**)&nextptr, g_nextptr);
    cudaGetSymbolAddress((void**)&partials, g_partials);
    cudaGetSymbolAddress((void**)&csr,  g_csr);
    cudaGetSymbolAddress((void**)&hb,   g_hb);
    cudaGetSymbolAddress((void**)&h1,   g_h1);
    cudaGetSymbolAddress((void**)&h2,   g_h2);
    cudaGetSymbolAddress((void**)&gsum, g_gsum);
    cudaGetSymbolAddress((void**)&gcnt, g_gcnt);

    // side streams + events (created once, on the uncaptured correctness call)
    static cudaStream_t s1 = nullptr, s2 = nullptr;
    static cudaEvent_t e_root = nullptr, e_dis = nullptr,
                       e_g1 = nullptr, e_pool = nullptr;
    if (!s1) {
        cudaStreamCreateWithFlags(&s1, cudaStreamNonBlocking);
        cudaStreamCreateWithFlags(&s2, cudaStreamNonBlocking);
        cudaEventCreateWithFlags(&e_root, cudaEventDisableTiming);
        cudaEventCreateWithFlags(&e_dis,  cudaEventDisableTiming);
        cudaEventCreateWithFlags(&e_g1,   cudaEventDisableTiming);
        cudaEventCreateWithFlags(&e_pool, cudaEventDisableTiming);
    }

    const int TB = 256;
    const int nblkN = (NN + TB - 1) / TB;
    const int ew_grid = 148 * 16;
    const int gemm_blocks = (NN + 127) / 128;
    const int gather_blocks = (NN * 32 + TB - 1) / TB;

    // deg zero via memset, then fork s2 for pool setup (input-only deps)
    cudaMemsetAsync(deg, 0, NN * sizeof(int), 0);
    cudaEventRecord(e_root, 0);
    cudaStreamWaitEvent(s2, e_root, 0);
    cudaMemsetAsync(gsum, 0, NG * 64 * sizeof(float), s2);
    k_count_bs<<<1, 64, 0, s2>>>(batch, gcnt);
    cudaEventRecord(e_pool, s2);

    // ---- degree + scan (scan_block also emits dis); gemm1 forks after it
    launch_pdl(k_deg_count, dim3(ew_grid), dim3(TB), (cudaStream_t)0, dst, deg);
    launch_pdl(k_scan_block, dim3(NB_SCAN), dim3(SCAN_BLK), (cudaStream_t)0,
               deg, rowptr, partials, dis);
    cudaEventRecord(e_dis, 0);
    cudaStreamWaitEvent(s1, e_dis, 0);
    k_gemm_tc<128><<<gemm_blocks, 256, 0, s1>>>(x, W1, dis, hb, NN);   // s1
    cudaEventRecord(e_g1, s1);

    // ---- finish scan + fill on default stream, overlapping gemm1
    launch_pdl(k_scan_finish, dim3(nblkN), dim3(TB), (cudaStream_t)0,
               rowptr, (const int*)partials, nextptr);
    launch_pdl(k_fill, dim3(ew_grid), dim3(TB), (cudaStream_t)0,
               src, dst, nextptr, csr);

    // join gemm1, then layer-1 gather (h1 bf16)
    cudaStreamWaitEvent(0, e_g1, 0);
    launch_pdl(k_gather128s, dim3(gather_blocks), dim3(TB), (cudaStream_t)0,
               (const __nv_bfloat16*)hb, (const float*)dis, (const int*)deg,
               (const int*)rowptr, (const int*)csr, b1, h1);

    // ---- layer 2: bf16-A gemm, then gather (h2 bf16)
    launch_pdl(k_gemm_tc_h, dim3(gemm_blocks), dim3(256), (cudaStream_t)0,
               (const __nv_bfloat16*)h1, W2, (const float*)dis, hb, (int)NN);
    launch_pdl(k_gather64s, dim3(gather_blocks), dim3(TB), (cudaStream_t)0,
               (const __nv_bfloat16*)hb, (const float*)dis, (const int*)deg,
               (const int*)rowptr, (const int*)csr, b2, h2);

    // ---- pooling + fused head (last block)
    cudaStreamWaitEvent(0, e_pool, 0);   // join s2
    launch_pdl(k_pool64f, dim3((NN + 255) / 256), dim3(256), (cudaStream_t)0,
               (const __nv_bfloat16*)h2, batch, gsum, (const float*)gcnt,
               Wf1, bf1, Wf2, bf2, out);
}